// round 1
// baseline (speedup 1.0000x reference)
#include <cuda_runtime.h>
#include <math.h>

#define BDIM 1024
#define NB 4
#define NSEQ 1024
#define NHEADS 16
#define HDIM 64
#define ROWS (NB*NSEQ)   // 4096
#define MAXSEQ 1024

// ---------------- scratch (device globals; no allocation allowed) ----------------
__device__ float g_xn[(size_t)ROWS*BDIM];            // 16 MB
__device__ float g_qkv[(size_t)ROWS*3*BDIM];         // 48 MB
__device__ float g_scores[(size_t)NB*NHEADS*NSEQ*NSEQ]; // 256 MB
__device__ float g_ctx[(size_t)ROWS*BDIM];           // 16 MB
__device__ float g_y[(size_t)ROWS*BDIM];             // 16 MB
__device__ float g_mlp[(size_t)ROWS*4*BDIM];         // 64 MB

// ---------------- LayerNorm: one block per row of 1024 ----------------
__global__ __launch_bounds__(256) void ln_kernel(const float* __restrict__ x,
    const float* __restrict__ g, const float* __restrict__ b, float* __restrict__ out)
{
    __shared__ float red[256];
    const int row = blockIdx.x;
    const int t = threadIdx.x;
    const float4* xr = reinterpret_cast<const float4*>(x + (size_t)row * BDIM);
    float4 v = xr[t];
    float s = v.x + v.y + v.z + v.w;
    red[t] = s; __syncthreads();
    #pragma unroll
    for (int o = 128; o > 0; o >>= 1) { if (t < o) red[t] += red[t + o]; __syncthreads(); }
    const float mu = red[0] * (1.0f / BDIM);
    __syncthreads();
    float dx = v.x - mu, dy = v.y - mu, dz = v.z - mu, dw = v.w - mu;
    red[t] = dx*dx + dy*dy + dz*dz + dw*dw; __syncthreads();
    #pragma unroll
    for (int o = 128; o > 0; o >>= 1) { if (t < o) red[t] += red[t + o]; __syncthreads(); }
    const float var = red[0] * (1.0f / BDIM);
    const float rinv = rsqrtf(var + 1e-5f);
    float4 gg = reinterpret_cast<const float4*>(g)[t];
    float4 bb = reinterpret_cast<const float4*>(b)[t];
    float4 o4;
    o4.x = dx * rinv * gg.x + bb.x;
    o4.y = dy * rinv * gg.y + bb.y;
    o4.z = dz * rinv * gg.z + bb.z;
    o4.w = dw * rinv * gg.w + bb.w;
    reinterpret_cast<float4*>(out + (size_t)row * BDIM)[t] = o4;
}

// ---------------- Tiled SGEMM with fused epilogues ----------------
// C[M,N] = epi(A[M,K] @ B[K,N] + bias)
enum { EPI_BIAS = 0, EPI_GELU = 1, EPI_RESGATE = 2 };

template<int EPI>
__global__ __launch_bounds__(256) void sgemm_kernel(
    const float* __restrict__ A, const float* __restrict__ B,
    const float* __restrict__ bias, const float* __restrict__ res,
    const float* __restrict__ gate, float* __restrict__ C,
    int M, int N, int K)
{
    constexpr int BM = 128, BN = 128, BK = 8, TM = 8, TN = 8;
    __shared__ float As[BK * BM];   // transposed: As[k*BM + m]
    __shared__ float Bs[BK * BN];
    const int tid = threadIdx.x;
    const int cCol = blockIdx.x, cRow = blockIdx.y;
    const int threadCol = tid & 15;        // 0..15
    const int threadRow = tid >> 4;        // 0..15
    const int iRA = tid >> 1;              // 0..127
    const int iCA = (tid & 1) * 4;         // 0 or 4
    const int iRB = tid >> 5;              // 0..7
    const int iCB = (tid & 31) * 4;        // 0..124

    const float* Ap = A + (size_t)cRow * BM * K;
    const float* Bp = B + cCol * BN;

    float acc[TM][TN] = {};
    for (int k0 = 0; k0 < K; k0 += BK) {
        float4 a4 = *reinterpret_cast<const float4*>(Ap + (size_t)iRA * K + iCA);
        As[(iCA + 0) * BM + iRA] = a4.x;
        As[(iCA + 1) * BM + iRA] = a4.y;
        As[(iCA + 2) * BM + iRA] = a4.z;
        As[(iCA + 3) * BM + iRA] = a4.w;
        *reinterpret_cast<float4*>(&Bs[iRB * BN + iCB]) =
            *reinterpret_cast<const float4*>(Bp + (size_t)iRB * N + iCB);
        __syncthreads();
        Ap += BK;
        Bp += (size_t)BK * N;
        #pragma unroll
        for (int k = 0; k < BK; k++) {
            float regM[TM], regN[TN];
            #pragma unroll
            for (int i = 0; i < TM; i += 4)
                *reinterpret_cast<float4*>(&regM[i]) =
                    *reinterpret_cast<const float4*>(&As[k * BM + threadRow * TM + i]);
            #pragma unroll
            for (int j = 0; j < TN; j += 4)
                *reinterpret_cast<float4*>(&regN[j]) =
                    *reinterpret_cast<const float4*>(&Bs[k * BN + threadCol * TN + j]);
            #pragma unroll
            for (int i = 0; i < TM; i++)
                #pragma unroll
                for (int j = 0; j < TN; j++)
                    acc[i][j] = fmaf(regM[i], regN[j], acc[i][j]);
        }
        __syncthreads();
    }

    const int rowBase = cRow * BM + threadRow * TM;
    const int colBase = cCol * BN + threadCol * TN;
    const float gt = (EPI == EPI_RESGATE) ? gate[0] : 0.0f;
    #pragma unroll
    for (int i = 0; i < TM; i++) {
        const size_t rOff = (size_t)(rowBase + i) * N;
        #pragma unroll
        for (int j = 0; j < TN; j++) {
            const int col = colBase + j;
            float v = acc[i][j] + bias[col];
            if (EPI == EPI_GELU)
                v = 0.5f * v * (1.0f + erff(v * 0.70710678118654752f));
            if (EPI == EPI_RESGATE)
                v = res[rOff + col] + gt * v;
            C[rOff + col] = v;
        }
    }
}

// ---------------- Attention scores: S[b,h,i,j] = scale*q.k + relbias + mask ----------------
__global__ __launch_bounds__(256) void attn_score_kernel(
    const float* __restrict__ qkv, const int* __restrict__ mask,
    const float* __restrict__ rel, float* __restrict__ S)
{
    const int bh = blockIdx.z;
    const int b = bh >> 4, h = bh & 15;
    const int i0 = blockIdx.y * 64, j0 = blockIdx.x * 64;
    __shared__ float Qs[64][68];
    __shared__ float Ks[64][68];
    const int t = threadIdx.x;
    const int lr = t >> 4;           // 0..15
    const int lc = (t & 15) * 4;     // 0..60
    #pragma unroll
    for (int rr = 0; rr < 64; rr += 16) {
        const float* qp = qkv + ((size_t)(b * NSEQ + i0 + rr + lr)) * (3 * BDIM) + h * HDIM + lc;
        *reinterpret_cast<float4*>(&Qs[rr + lr][lc]) = *reinterpret_cast<const float4*>(qp);
        const float* kp = qkv + ((size_t)(b * NSEQ + j0 + rr + lr)) * (3 * BDIM) + BDIM + h * HDIM + lc;
        *reinterpret_cast<float4*>(&Ks[rr + lr][lc]) = *reinterpret_cast<const float4*>(kp);
    }
    __syncthreads();
    const int ty = t >> 4, tx = t & 15;
    float acc[4][4] = {};
    #pragma unroll
    for (int d = 0; d < 64; d++) {
        float a[4], bb[4];
        #pragma unroll
        for (int ii = 0; ii < 4; ii++) a[ii] = Qs[ty + 16 * ii][d];
        #pragma unroll
        for (int jj = 0; jj < 4; jj++) bb[jj] = Ks[tx + 16 * jj][d];
        #pragma unroll
        for (int ii = 0; ii < 4; ii++)
            #pragma unroll
            for (int jj = 0; jj < 4; jj++)
                acc[ii][jj] = fmaf(a[ii], bb[jj], acc[ii][jj]);
    }
    const float scale = 0.125f;  // HEAD_DIM^-0.5 = 1/8
    #pragma unroll
    for (int ii = 0; ii < 4; ii++) {
        const int i = i0 + ty + 16 * ii;
        const float mi = (float)mask[b * NSEQ + i];
        #pragma unroll
        for (int jj = 0; jj < 4; jj++) {
            const int j = j0 + tx + 16 * jj;
            const float mj = (float)mask[b * NSEQ + j];
            float v = acc[ii][jj] * scale + rel[(size_t)(i - j + (MAXSEQ - 1)) * NHEADS + h];
            if (mi * mj < 0.5f) v = -1e9f;
            S[((size_t)bh * NSEQ + i) * NSEQ + j] = v;
        }
    }
}

// ---------------- Row softmax over 1024 (one block per row) ----------------
__global__ __launch_bounds__(256) void softmax_kernel(float* __restrict__ S)
{
    __shared__ float red[256];
    const size_t row = blockIdx.x;
    float4* p = reinterpret_cast<float4*>(S + row * NSEQ);
    const int t = threadIdx.x;
    float4 v = p[t];
    float mx = fmaxf(fmaxf(v.x, v.y), fmaxf(v.z, v.w));
    red[t] = mx; __syncthreads();
    #pragma unroll
    for (int o = 128; o > 0; o >>= 1) { if (t < o) red[t] = fmaxf(red[t], red[t + o]); __syncthreads(); }
    mx = red[0];
    __syncthreads();
    float4 e;
    e.x = expf(v.x - mx); e.y = expf(v.y - mx);
    e.z = expf(v.z - mx); e.w = expf(v.w - mx);
    red[t] = e.x + e.y + e.z + e.w; __syncthreads();
    #pragma unroll
    for (int o = 128; o > 0; o >>= 1) { if (t < o) red[t] += red[t + o]; __syncthreads(); }
    const float inv = 1.0f / red[0];
    e.x *= inv; e.y *= inv; e.z *= inv; e.w *= inv;
    p[t] = e;
}

// ---------------- ctx[b,i,h,d] = sum_j P[b,h,i,j] * v[b,j,h,d] ----------------
__global__ __launch_bounds__(256) void attn_av_kernel(
    const float* __restrict__ S, const float* __restrict__ qkv, float* __restrict__ ctx)
{
    const int bh = blockIdx.z;
    const int b = bh >> 4, h = bh & 15;
    const int i0 = blockIdx.x * 64;
    __shared__ float Ps[64][36];
    __shared__ float Vs[32][64];
    const int t = threadIdx.x;
    const int ty = t >> 4, tx = t & 15;
    const int pr = t >> 3;          // 0..31
    const int pc = (t & 7) * 4;     // 0..28
    const int vr = t >> 4;          // 0..15
    const int vc = (t & 15) * 4;    // 0..60
    float acc[4][4] = {};
    for (int j0 = 0; j0 < NSEQ; j0 += 32) {
        #pragma unroll
        for (int rr = 0; rr < 64; rr += 32)
            *reinterpret_cast<float4*>(&Ps[rr + pr][pc]) =
                *reinterpret_cast<const float4*>(&S[((size_t)bh * NSEQ + i0 + rr + pr) * NSEQ + j0 + pc]);
        #pragma unroll
        for (int rr = 0; rr < 32; rr += 16)
            *reinterpret_cast<float4*>(&Vs[rr + vr][vc]) =
                *reinterpret_cast<const float4*>(qkv + ((size_t)(b * NSEQ + j0 + rr + vr)) * (3 * BDIM)
                                                 + 2 * BDIM + h * HDIM + vc);
        __syncthreads();
        #pragma unroll
        for (int kk = 0; kk < 32; kk++) {
            float a[4], vv[4];
            #pragma unroll
            for (int ii = 0; ii < 4; ii++) a[ii] = Ps[ty + 16 * ii][kk];
            #pragma unroll
            for (int jj = 0; jj < 4; jj++) vv[jj] = Vs[kk][tx + 16 * jj];
            #pragma unroll
            for (int ii = 0; ii < 4; ii++)
                #pragma unroll
                for (int jj = 0; jj < 4; jj++)
                    acc[ii][jj] = fmaf(a[ii], vv[jj], acc[ii][jj]);
        }
        __syncthreads();
    }
    #pragma unroll
    for (int ii = 0; ii < 4; ii++) {
        const int i = i0 + ty + 16 * ii;
        #pragma unroll
        for (int jj = 0; jj < 4; jj++)
            ctx[((size_t)(b * NSEQ + i)) * BDIM + h * HDIM + tx + 16 * jj] = acc[ii][jj];
    }
}

// ---------------- launch ----------------
extern "C" void kernel_launch(void* const* d_in, const int* in_sizes, int n_in,
                              void* d_out, int out_size)
{
    const float* x      = (const float*)d_in[0];
    const int*   mask   = (const int*)  d_in[1];
    const float* ln1_g  = (const float*)d_in[2];
    const float* ln1_b  = (const float*)d_in[3];
    const float* qkv_w  = (const float*)d_in[4];
    const float* qkv_b  = (const float*)d_in[5];
    const float* proj_w = (const float*)d_in[6];
    const float* proj_b = (const float*)d_in[7];
    const float* rel    = (const float*)d_in[8];
    const float* ln2_g  = (const float*)d_in[9];
    const float* ln2_b  = (const float*)d_in[10];
    const float* w1     = (const float*)d_in[11];
    const float* b1     = (const float*)d_in[12];
    const float* w2     = (const float*)d_in[13];
    const float* b2     = (const float*)d_in[14];
    const float* gate1  = (const float*)d_in[15];
    const float* gate2  = (const float*)d_in[16];
    float* out = (float*)d_out;

    float *xn, *qkv, *scores, *ctx, *y, *mlp;
    cudaGetSymbolAddress((void**)&xn,     g_xn);
    cudaGetSymbolAddress((void**)&qkv,    g_qkv);
    cudaGetSymbolAddress((void**)&scores, g_scores);
    cudaGetSymbolAddress((void**)&ctx,    g_ctx);
    cudaGetSymbolAddress((void**)&y,      g_y);
    cudaGetSymbolAddress((void**)&mlp,    g_mlp);

    // 1) LN1
    ln_kernel<<<ROWS, 256>>>(x, ln1_g, ln1_b, xn);
    // 2) qkv = xn @ qkv_w + qkv_b    (4096 x 3072 x 1024)
    sgemm_kernel<EPI_BIAS><<<dim3(3 * BDIM / 128, ROWS / 128), 256>>>(
        xn, qkv_w, qkv_b, nullptr, nullptr, qkv, ROWS, 3 * BDIM, BDIM);
    // 3) scores = scale*q@k^T + relbias (+mask)
    attn_score_kernel<<<dim3(NSEQ / 64, NSEQ / 64, NB * NHEADS), 256>>>(qkv, mask, rel, scores);
    // 4) softmax rows
    softmax_kernel<<<NB * NHEADS * NSEQ, 256>>>(scores);
    // 5) ctx = P @ v
    attn_av_kernel<<<dim3(NSEQ / 64, 1, NB * NHEADS), 256>>>(scores, qkv, ctx);
    // 6) y = x + gate1 * (ctx @ proj_w + proj_b)
    sgemm_kernel<EPI_RESGATE><<<dim3(BDIM / 128, ROWS / 128), 256>>>(
        ctx, proj_w, proj_b, x, gate1, y, ROWS, BDIM, BDIM);
    // 7) LN2
    ln_kernel<<<ROWS, 256>>>(y, ln2_g, ln2_b, xn);
    // 8) mlp = gelu(xn @ w1 + b1)
    sgemm_kernel<EPI_GELU><<<dim3(4 * BDIM / 128, ROWS / 128), 256>>>(
        xn, w1, b1, nullptr, nullptr, mlp, ROWS, 4 * BDIM, BDIM);
    // 9) out = y + gate2 * (mlp @ w2 + b2)
    sgemm_kernel<EPI_RESGATE><<<dim3(BDIM / 128, ROWS / 128), 256>>>(
        mlp, w2, b2, y, gate2, out, ROWS, BDIM, 4 * BDIM);
}

// round 2
// speedup vs baseline: 2.1832x; 2.1832x over previous
#include <cuda_runtime.h>
#include <math.h>
#include <stdint.h>

#define BDIM 1024
#define NB 4
#define NSEQ 1024
#define NHEADS 16
#define HDIM 64
#define ROWS (NB*NSEQ)   // 4096
#define MAXSEQ 1024

// ---------------- scratch (device globals; no allocation allowed) ----------------
__device__ float g_xn[(size_t)ROWS*BDIM];               // 16 MB
__device__ float g_qkv[(size_t)ROWS*3*BDIM];            // 48 MB
__device__ float g_scores[(size_t)NB*NHEADS*NSEQ*NSEQ]; // 256 MB
__device__ float g_ctx[(size_t)ROWS*BDIM];              // 16 MB
__device__ float g_y[(size_t)ROWS*BDIM];                // 16 MB
__device__ float g_mlp[(size_t)ROWS*4*BDIM];            // 64 MB

// ---------------- LayerNorm: one block per row of 1024 ----------------
__global__ __launch_bounds__(256) void ln_kernel(const float* __restrict__ x,
    const float* __restrict__ g, const float* __restrict__ b, float* __restrict__ out)
{
    __shared__ float red[256];
    const int row = blockIdx.x;
    const int t = threadIdx.x;
    const float4* xr = reinterpret_cast<const float4*>(x + (size_t)row * BDIM);
    float4 v = xr[t];
    float s = v.x + v.y + v.z + v.w;
    red[t] = s; __syncthreads();
    #pragma unroll
    for (int o = 128; o > 0; o >>= 1) { if (t < o) red[t] += red[t + o]; __syncthreads(); }
    const float mu = red[0] * (1.0f / BDIM);
    __syncthreads();
    float dx = v.x - mu, dy = v.y - mu, dz = v.z - mu, dw = v.w - mu;
    red[t] = dx*dx + dy*dy + dz*dz + dw*dw; __syncthreads();
    #pragma unroll
    for (int o = 128; o > 0; o >>= 1) { if (t < o) red[t] += red[t + o]; __syncthreads(); }
    const float var = red[0] * (1.0f / BDIM);
    const float rinv = rsqrtf(var + 1e-5f);
    float4 gg = reinterpret_cast<const float4*>(g)[t];
    float4 bb = reinterpret_cast<const float4*>(b)[t];
    float4 o4;
    o4.x = dx * rinv * gg.x + bb.x;
    o4.y = dy * rinv * gg.y + bb.y;
    o4.z = dz * rinv * gg.z + bb.z;
    o4.w = dw * rinv * gg.w + bb.w;
    reinterpret_cast<float4*>(out + (size_t)row * BDIM)[t] = o4;
}

// ---------------- TF32 tensor-core GEMM with fused epilogues ----------------
enum { EPI_BIAS = 0, EPI_GELU = 1, EPI_RESGATE = 2 };

__device__ __forceinline__ uint32_t f2tf(float x) {
    uint32_t r;
    asm("cvt.rna.tf32.f32 %0, %1;" : "=r"(r) : "f"(x));
    return r;
}

__device__ __forceinline__ void mma_tf32(float c[4], const uint32_t a[4], const uint32_t b[2]) {
    asm volatile(
        "mma.sync.aligned.m16n8k8.row.col.f32.tf32.tf32.f32 "
        "{%0,%1,%2,%3}, {%4,%5,%6,%7}, {%8,%9}, {%0,%1,%2,%3};"
        : "+f"(c[0]), "+f"(c[1]), "+f"(c[2]), "+f"(c[3])
        : "r"(a[0]), "r"(a[1]), "r"(a[2]), "r"(a[3]), "r"(b[0]), "r"(b[1]));
}

// C[M,N] = epi(A[M,K] @ B[K,N] + bias); M%128==0, N%128==0, K%16==0
template<int EPI>
__global__ __launch_bounds__(256, 2) void tf32gemm_kernel(
    const float* __restrict__ A, const float* __restrict__ B,
    const float* __restrict__ bias, const float* __restrict__ res,
    const float* __restrict__ gate, float* __restrict__ C,
    int M, int N, int K)
{
    constexpr int BM = 128, BN = 128, BK = 16;
    constexpr int AST = BK + 4;   // 20 floats/row  -> conflict-free A frag loads
    constexpr int BST = BN + 8;   // 136 floats/row -> conflict-free B frag loads
    __shared__ uint32_t As[2][BM * AST];
    __shared__ uint32_t Bs[2][BK * BST];

    const int tid  = threadIdx.x;
    const int lane = tid & 31;
    const int wid  = tid >> 5;
    const int g    = lane >> 2;      // 0..7
    const int t4   = lane & 3;       // 0..3
    const int mWarp = (wid >> 2) * 64;   // 0 or 64
    const int nWarp = (wid & 3) * 32;    // 0,32,64,96

    // global load mapping
    const int aRow = tid >> 2;             // 0..63  (+64 second)
    const int aCol = (tid & 3) * 4;        // 0,4,8,12
    const int bRow = tid >> 5;             // 0..7   (+8 second)
    const int bCol = (tid & 31) * 4;       // 0..124

    const float* Ap = A + (size_t)(blockIdx.y * BM + aRow) * K + aCol;
    const float* Bp = B + (size_t)bRow * N + blockIdx.x * BN + bCol;

    float acc[4][4][4] = {};

    const int nT = K / BK;
    float4 pa0, pa1, pb0, pb1;

    // prologue: load tile 0
    pa0 = *reinterpret_cast<const float4*>(Ap);
    pa1 = *reinterpret_cast<const float4*>(Ap + (size_t)64 * K);
    pb0 = *reinterpret_cast<const float4*>(Bp);
    pb1 = *reinterpret_cast<const float4*>(Bp + (size_t)8 * N);
    {
        uint32_t* as = &As[0][aRow * AST + aCol];
        as[0] = f2tf(pa0.x); as[1] = f2tf(pa0.y); as[2] = f2tf(pa0.z); as[3] = f2tf(pa0.w);
        uint32_t* as2 = &As[0][(aRow + 64) * AST + aCol];
        as2[0] = f2tf(pa1.x); as2[1] = f2tf(pa1.y); as2[2] = f2tf(pa1.z); as2[3] = f2tf(pa1.w);
        uint32_t* bs = &Bs[0][bRow * BST + bCol];
        bs[0] = f2tf(pb0.x); bs[1] = f2tf(pb0.y); bs[2] = f2tf(pb0.z); bs[3] = f2tf(pb0.w);
        uint32_t* bs2 = &Bs[0][(bRow + 8) * BST + bCol];
        bs2[0] = f2tf(pb1.x); bs2[1] = f2tf(pb1.y); bs2[2] = f2tf(pb1.z); bs2[3] = f2tf(pb1.w);
    }
    __syncthreads();

    for (int t = 0; t < nT; t++) {
        const int cur = t & 1;
        if (t + 1 < nT) {
            const float* ap = Ap + (size_t)(t + 1) * BK;
            const float* bp = Bp + (size_t)(t + 1) * BK * N;
            pa0 = *reinterpret_cast<const float4*>(ap);
            pa1 = *reinterpret_cast<const float4*>(ap + (size_t)64 * K);
            pb0 = *reinterpret_cast<const float4*>(bp);
            pb1 = *reinterpret_cast<const float4*>(bp + (size_t)8 * N);
        }

        #pragma unroll
        for (int ks = 0; ks < 2; ks++) {
            const int k0 = ks * 8;
            uint32_t bf[4][2];
            #pragma unroll
            for (int ni = 0; ni < 4; ni++) {
                const int nb = nWarp + ni * 8;
                bf[ni][0] = Bs[cur][(k0 + t4) * BST + nb + g];
                bf[ni][1] = Bs[cur][(k0 + t4 + 4) * BST + nb + g];
            }
            #pragma unroll
            for (int mi = 0; mi < 4; mi++) {
                const int mb = mWarp + mi * 16;
                uint32_t af[4];
                af[0] = As[cur][(mb + g) * AST + k0 + t4];
                af[1] = As[cur][(mb + g + 8) * AST + k0 + t4];
                af[2] = As[cur][(mb + g) * AST + k0 + t4 + 4];
                af[3] = As[cur][(mb + g + 8) * AST + k0 + t4 + 4];
                #pragma unroll
                for (int ni = 0; ni < 4; ni++)
                    mma_tf32(acc[mi][ni], af, bf[ni]);
            }
        }

        if (t + 1 < nT) {
            const int nxt = cur ^ 1;
            uint32_t* as = &As[nxt][aRow * AST + aCol];
            as[0] = f2tf(pa0.x); as[1] = f2tf(pa0.y); as[2] = f2tf(pa0.z); as[3] = f2tf(pa0.w);
            uint32_t* as2 = &As[nxt][(aRow + 64) * AST + aCol];
            as2[0] = f2tf(pa1.x); as2[1] = f2tf(pa1.y); as2[2] = f2tf(pa1.z); as2[3] = f2tf(pa1.w);
            uint32_t* bs = &Bs[nxt][bRow * BST + bCol];
            bs[0] = f2tf(pb0.x); bs[1] = f2tf(pb0.y); bs[2] = f2tf(pb0.z); bs[3] = f2tf(pb0.w);
            uint32_t* bs2 = &Bs[nxt][(bRow + 8) * BST + bCol];
            bs2[0] = f2tf(pb1.x); bs2[1] = f2tf(pb1.y); bs2[2] = f2tf(pb1.z); bs2[3] = f2tf(pb1.w);
        }
        __syncthreads();
    }

    // epilogue: C fragment (g, 2*t4) / (g+8, 2*t4) per 16x8 tile
    const float gt = (EPI == EPI_RESGATE) ? gate[0] : 0.0f;
    #pragma unroll
    for (int mi = 0; mi < 4; mi++) {
        const int row0 = blockIdx.y * BM + mWarp + mi * 16 + g;
        #pragma unroll
        for (int ni = 0; ni < 4; ni++) {
            const int col = blockIdx.x * BN + nWarp + ni * 8 + t4 * 2;
            const float b0 = bias[col], b1 = bias[col + 1];
            #pragma unroll
            for (int h = 0; h < 2; h++) {
                const int row = row0 + h * 8;
                float v0 = acc[mi][ni][2 * h + 0] + b0;
                float v1 = acc[mi][ni][2 * h + 1] + b1;
                if (EPI == EPI_GELU) {
                    v0 = 0.5f * v0 * (1.0f + erff(v0 * 0.70710678118654752f));
                    v1 = 0.5f * v1 * (1.0f + erff(v1 * 0.70710678118654752f));
                }
                if (EPI == EPI_RESGATE) {
                    const size_t off = (size_t)row * N + col;
                    v0 = res[off] + gt * v0;
                    v1 = res[off + 1] + gt * v1;
                }
                *reinterpret_cast<float2*>(C + (size_t)row * N + col) = make_float2(v0, v1);
            }
        }
    }
}

// ---------------- Attention scores: S[b,h,i,j] = scale*q.k + relbias + mask ----------------
__global__ __launch_bounds__(256) void attn_score_kernel(
    const float* __restrict__ qkv, const int* __restrict__ mask,
    const float* __restrict__ rel, float* __restrict__ S)
{
    const int bh = blockIdx.z;
    const int b = bh >> 4, h = bh & 15;
    const int i0 = blockIdx.y * 64, j0 = blockIdx.x * 64;
    __shared__ float Qs[64][68];
    __shared__ float Ks[64][68];
    const int t = threadIdx.x;
    const int lr = t >> 4;           // 0..15
    const int lc = (t & 15) * 4;     // 0..60
    #pragma unroll
    for (int rr = 0; rr < 64; rr += 16) {
        const float* qp = qkv + ((size_t)(b * NSEQ + i0 + rr + lr)) * (3 * BDIM) + h * HDIM + lc;
        *reinterpret_cast<float4*>(&Qs[rr + lr][lc]) = *reinterpret_cast<const float4*>(qp);
        const float* kp = qkv + ((size_t)(b * NSEQ + j0 + rr + lr)) * (3 * BDIM) + BDIM + h * HDIM + lc;
        *reinterpret_cast<float4*>(&Ks[rr + lr][lc]) = *reinterpret_cast<const float4*>(kp);
    }
    __syncthreads();
    const int ty = t >> 4, tx = t & 15;
    float acc[4][4] = {};
    #pragma unroll
    for (int d = 0; d < 64; d++) {
        float a[4], bb[4];
        #pragma unroll
        for (int ii = 0; ii < 4; ii++) a[ii] = Qs[ty + 16 * ii][d];
        #pragma unroll
        for (int jj = 0; jj < 4; jj++) bb[jj] = Ks[tx + 16 * jj][d];
        #pragma unroll
        for (int ii = 0; ii < 4; ii++)
            #pragma unroll
            for (int jj = 0; jj < 4; jj++)
                acc[ii][jj] = fmaf(a[ii], bb[jj], acc[ii][jj]);
    }
    const float scale = 0.125f;
    #pragma unroll
    for (int ii = 0; ii < 4; ii++) {
        const int i = i0 + ty + 16 * ii;
        const float mi = (float)mask[b * NSEQ + i];
        #pragma unroll
        for (int jj = 0; jj < 4; jj++) {
            const int j = j0 + tx + 16 * jj;
            const float mj = (float)mask[b * NSEQ + j];
            float v = acc[ii][jj] * scale + rel[(size_t)(i - j + (MAXSEQ - 1)) * NHEADS + h];
            if (mi * mj < 0.5f) v = -1e9f;
            S[((size_t)bh * NSEQ + i) * NSEQ + j] = v;
        }
    }
}

// ---------------- Row softmax over 1024 (one block per row) ----------------
__global__ __launch_bounds__(256) void softmax_kernel(float* __restrict__ S)
{
    __shared__ float red[256];
    const size_t row = blockIdx.x;
    float4* p = reinterpret_cast<float4*>(S + row * NSEQ);
    const int t = threadIdx.x;
    float4 v = p[t];
    float mx = fmaxf(fmaxf(v.x, v.y), fmaxf(v.z, v.w));
    red[t] = mx; __syncthreads();
    #pragma unroll
    for (int o = 128; o > 0; o >>= 1) { if (t < o) red[t] = fmaxf(red[t], red[t + o]); __syncthreads(); }
    mx = red[0];
    __syncthreads();
    float4 e;
    e.x = expf(v.x - mx); e.y = expf(v.y - mx);
    e.z = expf(v.z - mx); e.w = expf(v.w - mx);
    red[t] = e.x + e.y + e.z + e.w; __syncthreads();
    #pragma unroll
    for (int o = 128; o > 0; o >>= 1) { if (t < o) red[t] += red[t + o]; __syncthreads(); }
    const float inv = 1.0f / red[0];
    e.x *= inv; e.y *= inv; e.z *= inv; e.w *= inv;
    p[t] = e;
}

// ---------------- ctx[b,i,h,d] = sum_j P[b,h,i,j] * v[b,j,h,d] ----------------
__global__ __launch_bounds__(256) void attn_av_kernel(
    const float* __restrict__ S, const float* __restrict__ qkv, float* __restrict__ ctx)
{
    const int bh = blockIdx.z;
    const int b = bh >> 4, h = bh & 15;
    const int i0 = blockIdx.x * 64;
    __shared__ float Ps[64][36];
    __shared__ float Vs[32][64];
    const int t = threadIdx.x;
    const int ty = t >> 4, tx = t & 15;
    const int pr = t >> 3;          // 0..31
    const int pc = (t & 7) * 4;     // 0..28
    const int vr = t >> 4;          // 0..15
    const int vc = (t & 15) * 4;    // 0..60
    float acc[4][4] = {};
    for (int j0 = 0; j0 < NSEQ; j0 += 32) {
        #pragma unroll
        for (int rr = 0; rr < 64; rr += 32)
            *reinterpret_cast<float4*>(&Ps[rr + pr][pc]) =
                *reinterpret_cast<const float4*>(&S[((size_t)bh * NSEQ + i0 + rr + pr) * NSEQ + j0 + pc]);
        #pragma unroll
        for (int rr = 0; rr < 32; rr += 16)
            *reinterpret_cast<float4*>(&Vs[rr + vr][vc]) =
                *reinterpret_cast<const float4*>(qkv + ((size_t)(b * NSEQ + j0 + rr + vr)) * (3 * BDIM)
                                                 + 2 * BDIM + h * HDIM + vc);
        __syncthreads();
        #pragma unroll
        for (int kk = 0; kk < 32; kk++) {
            float a[4], vv[4];
            #pragma unroll
            for (int ii = 0; ii < 4; ii++) a[ii] = Ps[ty + 16 * ii][kk];
            #pragma unroll
            for (int jj = 0; jj < 4; jj++) vv[jj] = Vs[kk][tx + 16 * jj];
            #pragma unroll
            for (int ii = 0; ii < 4; ii++)
                #pragma unroll
                for (int jj = 0; jj < 4; jj++)
                    acc[ii][jj] = fmaf(a[ii], vv[jj], acc[ii][jj]);
        }
        __syncthreads();
    }
    #pragma unroll
    for (int ii = 0; ii < 4; ii++) {
        const int i = i0 + ty + 16 * ii;
        #pragma unroll
        for (int jj = 0; jj < 4; jj++)
            ctx[((size_t)(b * NSEQ + i)) * BDIM + h * HDIM + tx + 16 * jj] = acc[ii][jj];
    }
}

// ---------------- launch ----------------
extern "C" void kernel_launch(void* const* d_in, const int* in_sizes, int n_in,
                              void* d_out, int out_size)
{
    const float* x      = (const float*)d_in[0];
    const int*   mask   = (const int*)  d_in[1];
    const float* ln1_g  = (const float*)d_in[2];
    const float* ln1_b  = (const float*)d_in[3];
    const float* qkv_w  = (const float*)d_in[4];
    const float* qkv_b  = (const float*)d_in[5];
    const float* proj_w = (const float*)d_in[6];
    const float* proj_b = (const float*)d_in[7];
    const float* rel    = (const float*)d_in[8];
    const float* ln2_g  = (const float*)d_in[9];
    const float* ln2_b  = (const float*)d_in[10];
    const float* w1     = (const float*)d_in[11];
    const float* b1     = (const float*)d_in[12];
    const float* w2     = (const float*)d_in[13];
    const float* b2     = (const float*)d_in[14];
    const float* gate1  = (const float*)d_in[15];
    const float* gate2  = (const float*)d_in[16];
    float* out = (float*)d_out;

    float *xn, *qkv, *scores, *ctx, *y, *mlp;
    cudaGetSymbolAddress((void**)&xn,     g_xn);
    cudaGetSymbolAddress((void**)&qkv,    g_qkv);
    cudaGetSymbolAddress((void**)&scores, g_scores);
    cudaGetSymbolAddress((void**)&ctx,    g_ctx);
    cudaGetSymbolAddress((void**)&y,      g_y);
    cudaGetSymbolAddress((void**)&mlp,    g_mlp);

    // 1) LN1
    ln_kernel<<<ROWS, 256>>>(x, ln1_g, ln1_b, xn);
    // 2) qkv = xn @ qkv_w + qkv_b    (4096 x 3072 x 1024)
    tf32gemm_kernel<EPI_BIAS><<<dim3(3 * BDIM / 128, ROWS / 128), 256>>>(
        xn, qkv_w, qkv_b, nullptr, nullptr, qkv, ROWS, 3 * BDIM, BDIM);
    // 3) scores = scale*q@k^T + relbias (+mask)
    attn_score_kernel<<<dim3(NSEQ / 64, NSEQ / 64, NB * NHEADS), 256>>>(qkv, mask, rel, scores);
    // 4) softmax rows
    softmax_kernel<<<NB * NHEADS * NSEQ, 256>>>(scores);
    // 5) ctx = P @ v
    attn_av_kernel<<<dim3(NSEQ / 64, 1, NB * NHEADS), 256>>>(scores, qkv, ctx);
    // 6) y = x + gate1 * (ctx @ proj_w + proj_b)
    tf32gemm_kernel<EPI_RESGATE><<<dim3(BDIM / 128, ROWS / 128), 256>>>(
        ctx, proj_w, proj_b, x, gate1, y, ROWS, BDIM, BDIM);
    // 7) LN2
    ln_kernel<<<ROWS, 256>>>(y, ln2_g, ln2_b, xn);
    // 8) mlp = gelu(xn @ w1 + b1)
    tf32gemm_kernel<EPI_GELU><<<dim3(4 * BDIM / 128, ROWS / 128), 256>>>(
        xn, w1, b1, nullptr, nullptr, mlp, ROWS, 4 * BDIM, BDIM);
    // 9) out = y + gate2 * (mlp @ w2 + b2)
    tf32gemm_kernel<EPI_RESGATE><<<dim3(BDIM / 128, ROWS / 128), 256>>>(
        mlp, w2, b2, y, gate2, out, ROWS, BDIM, 4 * BDIM);
}

// round 3
// speedup vs baseline: 2.9529x; 1.3525x over previous
#include <cuda_runtime.h>
#include <math.h>
#include <stdint.h>

#define BDIM 1024
#define NB 4
#define NSEQ 1024
#define NHEADS 16
#define HDIM 64
#define ROWS (NB*NSEQ)   // 4096
#define MAXSEQ 1024

// ---------------- scratch (device globals; no allocation allowed) ----------------
__device__ float g_xn[(size_t)ROWS*BDIM];               // 16 MB
__device__ float g_qkv[(size_t)ROWS*3*BDIM];            // 48 MB
__device__ float g_ctx[(size_t)ROWS*BDIM];              // 16 MB
__device__ float g_y[(size_t)ROWS*BDIM];                // 16 MB
__device__ float g_mlp[(size_t)ROWS*4*BDIM];            // 64 MB

// ---------------- common mma helpers ----------------
__device__ __forceinline__ uint32_t f2tf(float x) {
    uint32_t r;
    asm("cvt.rna.tf32.f32 %0, %1;" : "=r"(r) : "f"(x));
    return r;
}

__device__ __forceinline__ void mma_tf32(float c[4], const uint32_t a[4], const uint32_t b[2]) {
    asm volatile(
        "mma.sync.aligned.m16n8k8.row.col.f32.tf32.tf32.f32 "
        "{%0,%1,%2,%3}, {%4,%5,%6,%7}, {%8,%9}, {%0,%1,%2,%3};"
        : "+f"(c[0]), "+f"(c[1]), "+f"(c[2]), "+f"(c[3])
        : "r"(a[0]), "r"(a[1]), "r"(a[2]), "r"(a[3]), "r"(b[0]), "r"(b[1]));
}

// ---------------- LayerNorm: one block per row of 1024 ----------------
__global__ __launch_bounds__(256) void ln_kernel(const float* __restrict__ x,
    const float* __restrict__ g, const float* __restrict__ b, float* __restrict__ out)
{
    __shared__ float red[256];
    const int row = blockIdx.x;
    const int t = threadIdx.x;
    const float4* xr = reinterpret_cast<const float4*>(x + (size_t)row * BDIM);
    float4 v = xr[t];
    float s = v.x + v.y + v.z + v.w;
    red[t] = s; __syncthreads();
    #pragma unroll
    for (int o = 128; o > 0; o >>= 1) { if (t < o) red[t] += red[t + o]; __syncthreads(); }
    const float mu = red[0] * (1.0f / BDIM);
    __syncthreads();
    float dx = v.x - mu, dy = v.y - mu, dz = v.z - mu, dw = v.w - mu;
    red[t] = dx*dx + dy*dy + dz*dz + dw*dw; __syncthreads();
    #pragma unroll
    for (int o = 128; o > 0; o >>= 1) { if (t < o) red[t] += red[t + o]; __syncthreads(); }
    const float var = red[0] * (1.0f / BDIM);
    const float rinv = rsqrtf(var + 1e-5f);
    float4 gg = reinterpret_cast<const float4*>(g)[t];
    float4 bb = reinterpret_cast<const float4*>(b)[t];
    float4 o4;
    o4.x = dx * rinv * gg.x + bb.x;
    o4.y = dy * rinv * gg.y + bb.y;
    o4.z = dz * rinv * gg.z + bb.z;
    o4.w = dw * rinv * gg.w + bb.w;
    reinterpret_cast<float4*>(out + (size_t)row * BDIM)[t] = o4;
}

// ---------------- TF32 tensor-core GEMM with fused epilogues ----------------
enum { EPI_BIAS = 0, EPI_GELU = 1, EPI_RESGATE = 2 };

template<int EPI>
__global__ __launch_bounds__(256, 2) void tf32gemm_kernel(
    const float* __restrict__ A, const float* __restrict__ B,
    const float* __restrict__ bias, const float* __restrict__ res,
    const float* __restrict__ gate, float* __restrict__ C,
    int M, int N, int K)
{
    constexpr int BM = 128, BN = 128, BK = 16;
    constexpr int AST = BK + 4;   // 20
    constexpr int BST = BN + 8;   // 136
    __shared__ uint32_t As[2][BM * AST];
    __shared__ uint32_t Bs[2][BK * BST];

    const int tid  = threadIdx.x;
    const int lane = tid & 31;
    const int wid  = tid >> 5;
    const int g    = lane >> 2;
    const int t4   = lane & 3;
    const int mWarp = (wid >> 2) * 64;
    const int nWarp = (wid & 3) * 32;

    const int aRow = tid >> 2;
    const int aCol = (tid & 3) * 4;
    const int bRow = tid >> 5;
    const int bCol = (tid & 31) * 4;

    const float* Ap = A + (size_t)(blockIdx.y * BM + aRow) * K + aCol;
    const float* Bp = B + (size_t)bRow * N + blockIdx.x * BN + bCol;

    float acc[4][4][4] = {};

    const int nT = K / BK;
    float4 pa0, pa1, pb0, pb1;

    pa0 = *reinterpret_cast<const float4*>(Ap);
    pa1 = *reinterpret_cast<const float4*>(Ap + (size_t)64 * K);
    pb0 = *reinterpret_cast<const float4*>(Bp);
    pb1 = *reinterpret_cast<const float4*>(Bp + (size_t)8 * N);
    {
        uint32_t* as = &As[0][aRow * AST + aCol];
        as[0] = f2tf(pa0.x); as[1] = f2tf(pa0.y); as[2] = f2tf(pa0.z); as[3] = f2tf(pa0.w);
        uint32_t* as2 = &As[0][(aRow + 64) * AST + aCol];
        as2[0] = f2tf(pa1.x); as2[1] = f2tf(pa1.y); as2[2] = f2tf(pa1.z); as2[3] = f2tf(pa1.w);
        uint32_t* bs = &Bs[0][bRow * BST + bCol];
        bs[0] = f2tf(pb0.x); bs[1] = f2tf(pb0.y); bs[2] = f2tf(pb0.z); bs[3] = f2tf(pb0.w);
        uint32_t* bs2 = &Bs[0][(bRow + 8) * BST + bCol];
        bs2[0] = f2tf(pb1.x); bs2[1] = f2tf(pb1.y); bs2[2] = f2tf(pb1.z); bs2[3] = f2tf(pb1.w);
    }
    __syncthreads();

    for (int t = 0; t < nT; t++) {
        const int cur = t & 1;
        if (t + 1 < nT) {
            const float* ap = Ap + (size_t)(t + 1) * BK;
            const float* bp = Bp + (size_t)(t + 1) * BK * N;
            pa0 = *reinterpret_cast<const float4*>(ap);
            pa1 = *reinterpret_cast<const float4*>(ap + (size_t)64 * K);
            pb0 = *reinterpret_cast<const float4*>(bp);
            pb1 = *reinterpret_cast<const float4*>(bp + (size_t)8 * N);
        }

        #pragma unroll
        for (int ks = 0; ks < 2; ks++) {
            const int k0 = ks * 8;
            uint32_t bf[4][2];
            #pragma unroll
            for (int ni = 0; ni < 4; ni++) {
                const int nb = nWarp + ni * 8;
                bf[ni][0] = Bs[cur][(k0 + t4) * BST + nb + g];
                bf[ni][1] = Bs[cur][(k0 + t4 + 4) * BST + nb + g];
            }
            #pragma unroll
            for (int mi = 0; mi < 4; mi++) {
                const int mb = mWarp + mi * 16;
                uint32_t af[4];
                af[0] = As[cur][(mb + g) * AST + k0 + t4];
                af[1] = As[cur][(mb + g + 8) * AST + k0 + t4];
                af[2] = As[cur][(mb + g) * AST + k0 + t4 + 4];
                af[3] = As[cur][(mb + g + 8) * AST + k0 + t4 + 4];
                #pragma unroll
                for (int ni = 0; ni < 4; ni++)
                    mma_tf32(acc[mi][ni], af, bf[ni]);
            }
        }

        if (t + 1 < nT) {
            const int nxt = cur ^ 1;
            uint32_t* as = &As[nxt][aRow * AST + aCol];
            as[0] = f2tf(pa0.x); as[1] = f2tf(pa0.y); as[2] = f2tf(pa0.z); as[3] = f2tf(pa0.w);
            uint32_t* as2 = &As[nxt][(aRow + 64) * AST + aCol];
            as2[0] = f2tf(pa1.x); as2[1] = f2tf(pa1.y); as2[2] = f2tf(pa1.z); as2[3] = f2tf(pa1.w);
            uint32_t* bs = &Bs[nxt][bRow * BST + bCol];
            bs[0] = f2tf(pb0.x); bs[1] = f2tf(pb0.y); bs[2] = f2tf(pb0.z); bs[3] = f2tf(pb0.w);
            uint32_t* bs2 = &Bs[nxt][(bRow + 8) * BST + bCol];
            bs2[0] = f2tf(pb1.x); bs2[1] = f2tf(pb1.y); bs2[2] = f2tf(pb1.z); bs2[3] = f2tf(pb1.w);
        }
        __syncthreads();
    }

    const float gt = (EPI == EPI_RESGATE) ? gate[0] : 0.0f;
    #pragma unroll
    for (int mi = 0; mi < 4; mi++) {
        const int row0 = blockIdx.y * BM + mWarp + mi * 16 + g;
        #pragma unroll
        for (int ni = 0; ni < 4; ni++) {
            const int col = blockIdx.x * BN + nWarp + ni * 8 + t4 * 2;
            const float b0 = bias[col], b1 = bias[col + 1];
            #pragma unroll
            for (int h = 0; h < 2; h++) {
                const int row = row0 + h * 8;
                float v0 = acc[mi][ni][2 * h + 0] + b0;
                float v1 = acc[mi][ni][2 * h + 1] + b1;
                if (EPI == EPI_GELU) {
                    v0 = 0.5f * v0 * (1.0f + erff(v0 * 0.70710678118654752f));
                    v1 = 0.5f * v1 * (1.0f + erff(v1 * 0.70710678118654752f));
                }
                if (EPI == EPI_RESGATE) {
                    const size_t off = (size_t)row * N + col;
                    v0 = res[off] + gt * v0;
                    v1 = res[off + 1] + gt * v1;
                }
                *reinterpret_cast<float2*>(C + (size_t)row * N + col) = make_float2(v0, v1);
            }
        }
    }
}

// ---------------- Fused flash attention (TF32 tensor cores) ----------------
// grid: (NSEQ/128, NB*NHEADS); block: 256 (8 warps x 16 query rows)
// ctx[b,i,h*64+d] = softmax(scale*QK^T + relbias, mask) @ V
__global__ __launch_bounds__(256) void flash_attn_kernel(
    const float* __restrict__ qkv, const int* __restrict__ mask,
    const float* __restrict__ rel, float* __restrict__ ctx)
{
    constexpr int KST = 68;   // K smem stride (banks 4g+t4: conflict-free)
    constexpr int VST = 72;   // V smem stride (banks 8t4+g: conflict-free)
    constexpr float SCALE = 0.125f;
    constexpr float L2E = 1.4426950408889634f;

    // smem: Ks[64][68] | Vs[64][72] | mk[64] | rel_s[2047]; Qst[128][68] overlays Ks+Vs
    __shared__ __align__(16) uint32_t smbuf[64*KST + 64*VST + 64 + 2047 + 1];
    uint32_t* Ks = smbuf;
    uint32_t* Vs = smbuf + 64*KST;
    float* mk    = reinterpret_cast<float*>(smbuf + 64*KST + 64*VST);
    float* rel_s = mk + 64;
    uint32_t* Qst = smbuf;  // [128][KST], 8704 words < 8960 (Ks+Vs region)

    const int bh = blockIdx.y;
    const int b = bh >> 4, h = bh & 15;
    const int i0 = blockIdx.x * 128;
    const int tid = threadIdx.x, lane = tid & 31, w = tid >> 5;
    const int g = lane >> 2, t4 = lane & 3;

    // rel column for this head (no overlap with Qst region)
    for (int idx = tid; idx < 2 * MAXSEQ - 1; idx += 256)
        rel_s[idx] = rel[(size_t)idx * NHEADS + h];

    // stage Q tile 128x64 -> tf32
    {
        const int r = tid >> 1;
        const int c0 = (tid & 1) * 32;
        const float* qp = qkv + ((size_t)(b * NSEQ + i0 + r)) * (3 * BDIM) + h * HDIM + c0;
        #pragma unroll
        for (int i = 0; i < 8; i++) {
            float4 v = *reinterpret_cast<const float4*>(qp + 4 * i);
            uint4 u;
            u.x = f2tf(v.x); u.y = f2tf(v.y); u.z = f2tf(v.z); u.w = f2tf(v.w);
            *reinterpret_cast<uint4*>(&Qst[r * KST + c0 + 4 * i]) = u;
        }
    }
    __syncthreads();

    // Q a-fragments into registers: warp rows [w*16, w*16+16)
    uint32_t Qa[8][4];
    #pragma unroll
    for (int kt = 0; kt < 8; kt++) {
        const int r0 = (w * 16 + g) * KST + kt * 8 + t4;
        Qa[kt][0] = Qst[r0];
        Qa[kt][1] = Qst[r0 + 8 * KST];
        Qa[kt][2] = Qst[r0 + 4];
        Qa[kt][3] = Qst[r0 + 8 * KST + 4];
    }
    __syncthreads();   // everyone done with Qst before K/V overwrite

    const int irow0 = i0 + w * 16 + g;
    const int irow1 = irow0 + 8;
    const float mi0 = (float)mask[b * NSEQ + irow0];
    const float mi1 = (float)mask[b * NSEQ + irow1];

    float m0 = -INFINITY, m1 = -INFINITY, l0 = 0.0f, l1 = 0.0f;
    float Oc[8][4] = {};

    for (int jt = 0; jt < NSEQ / 64; jt++) {
        // ---- load K, V tiles (64x64 each) + kv mask ----
        {
            const int r = tid >> 2, q4 = (tid & 3) * 16;
            const float* kp = qkv + ((size_t)(b * NSEQ + jt * 64 + r)) * (3 * BDIM) + BDIM + h * HDIM + q4;
            #pragma unroll
            for (int i = 0; i < 4; i++) {
                float4 kv = *reinterpret_cast<const float4*>(kp + 4 * i);
                uint4 u;
                u.x = f2tf(kv.x); u.y = f2tf(kv.y); u.z = f2tf(kv.z); u.w = f2tf(kv.w);
                *reinterpret_cast<uint4*>(&Ks[r * KST + q4 + 4 * i]) = u;
                float4 vv = *reinterpret_cast<const float4*>(kp + BDIM + 4 * i);
                uint4 uv;
                uv.x = f2tf(vv.x); uv.y = f2tf(vv.y); uv.z = f2tf(vv.z); uv.w = f2tf(vv.w);
                *reinterpret_cast<uint4*>(&Vs[r * VST + q4 + 4 * i]) = uv;
            }
            if (tid < 64) mk[tid] = (float)mask[b * NSEQ + jt * 64 + tid];
        }
        __syncthreads();

        // ---- S = Q @ K^T (per-warp 16x64 fragment) ----
        float S[8][4] = {};
        #pragma unroll
        for (int nt = 0; nt < 8; nt++) {
            #pragma unroll
            for (int kt = 0; kt < 8; kt++) {
                uint32_t bf[2];
                bf[0] = Ks[(nt * 8 + g) * KST + kt * 8 + t4];
                bf[1] = Ks[(nt * 8 + g) * KST + kt * 8 + t4 + 4];
                mma_tf32(S[nt], Qa[kt], bf);
            }
        }

        // ---- scale + rel bias + mask ----
        float tmax0 = -INFINITY, tmax1 = -INFINITY;
        #pragma unroll
        for (int nt = 0; nt < 8; nt++) {
            const int j0 = jt * 64 + nt * 8 + 2 * t4;
            const float mk0 = mk[nt * 8 + 2 * t4];
            const float mk1 = mk[nt * 8 + 2 * t4 + 1];
            float s0 = S[nt][0] * SCALE + rel_s[irow0 - j0 + (MAXSEQ - 1)];
            float s1 = S[nt][1] * SCALE + rel_s[irow0 - j0 - 1 + (MAXSEQ - 1)];
            float s2 = S[nt][2] * SCALE + rel_s[irow1 - j0 + (MAXSEQ - 1)];
            float s3 = S[nt][3] * SCALE + rel_s[irow1 - j0 - 1 + (MAXSEQ - 1)];
            if (mi0 * mk0 < 0.5f) s0 = -1e9f;
            if (mi0 * mk1 < 0.5f) s1 = -1e9f;
            if (mi1 * mk0 < 0.5f) s2 = -1e9f;
            if (mi1 * mk1 < 0.5f) s3 = -1e9f;
            S[nt][0] = s0; S[nt][1] = s1; S[nt][2] = s2; S[nt][3] = s3;
            tmax0 = fmaxf(tmax0, fmaxf(s0, s1));
            tmax1 = fmaxf(tmax1, fmaxf(s2, s3));
        }
        tmax0 = fmaxf(tmax0, __shfl_xor_sync(0xffffffffu, tmax0, 1));
        tmax0 = fmaxf(tmax0, __shfl_xor_sync(0xffffffffu, tmax0, 2));
        tmax1 = fmaxf(tmax1, __shfl_xor_sync(0xffffffffu, tmax1, 1));
        tmax1 = fmaxf(tmax1, __shfl_xor_sync(0xffffffffu, tmax1, 2));

        const float mn0 = fmaxf(m0, tmax0);
        const float mn1 = fmaxf(m1, tmax1);
        const float sc0 = exp2f((m0 - mn0) * L2E);
        const float sc1 = exp2f((m1 - mn1) * L2E);
        m0 = mn0; m1 = mn1;

        // ---- exponentiate + row sums ----
        float ts0 = 0.0f, ts1 = 0.0f;
        #pragma unroll
        for (int nt = 0; nt < 8; nt++) {
            S[nt][0] = exp2f((S[nt][0] - mn0) * L2E);
            S[nt][1] = exp2f((S[nt][1] - mn0) * L2E);
            S[nt][2] = exp2f((S[nt][2] - mn1) * L2E);
            S[nt][3] = exp2f((S[nt][3] - mn1) * L2E);
            ts0 += S[nt][0] + S[nt][1];
            ts1 += S[nt][2] + S[nt][3];
        }
        ts0 += __shfl_xor_sync(0xffffffffu, ts0, 1);
        ts0 += __shfl_xor_sync(0xffffffffu, ts0, 2);
        ts1 += __shfl_xor_sync(0xffffffffu, ts1, 1);
        ts1 += __shfl_xor_sync(0xffffffffu, ts1, 2);
        l0 = l0 * sc0 + ts0;
        l1 = l1 * sc1 + ts1;

        // ---- rescale O ----
        #pragma unroll
        for (int nt = 0; nt < 8; nt++) {
            Oc[nt][0] *= sc0; Oc[nt][1] *= sc0;
            Oc[nt][2] *= sc1; Oc[nt][3] *= sc1;
        }

        // ---- O += P @ V (permute c-frag -> a-frag via shfl) ----
        #pragma unroll
        for (int kt = 0; kt < 8; kt++) {
            const int srcA = 4 * g + (t4 >> 1);
            const int srcB = srcA + 2;
            const bool odd = (t4 & 1);
            float v0 = __shfl_sync(0xffffffffu, S[kt][0], srcA);
            float v1 = __shfl_sync(0xffffffffu, S[kt][1], srcA);
            float v2 = __shfl_sync(0xffffffffu, S[kt][2], srcA);
            float v3 = __shfl_sync(0xffffffffu, S[kt][3], srcA);
            float u0 = __shfl_sync(0xffffffffu, S[kt][0], srcB);
            float u1 = __shfl_sync(0xffffffffu, S[kt][1], srcB);
            float u2 = __shfl_sync(0xffffffffu, S[kt][2], srcB);
            float u3 = __shfl_sync(0xffffffffu, S[kt][3], srcB);
            uint32_t a[4];
            a[0] = f2tf(odd ? v1 : v0);
            a[1] = f2tf(odd ? v3 : v2);
            a[2] = f2tf(odd ? u1 : u0);
            a[3] = f2tf(odd ? u3 : u2);
            #pragma unroll
            for (int nt2 = 0; nt2 < 8; nt2++) {
                uint32_t bf[2];
                bf[0] = Vs[(kt * 8 + t4) * VST + nt2 * 8 + g];
                bf[1] = Vs[(kt * 8 + t4 + 4) * VST + nt2 * 8 + g];
                mma_tf32(Oc[nt2], a, bf);
            }
        }
        __syncthreads();   // done reading Ks/Vs before next tile overwrite
    }

    // ---- writeback ctx = O / l ----
    const float inv0 = 1.0f / l0;
    const float inv1 = 1.0f / l1;
    #pragma unroll
    for (int nt2 = 0; nt2 < 8; nt2++) {
        const int col = h * HDIM + nt2 * 8 + 2 * t4;
        *reinterpret_cast<float2*>(ctx + (size_t)(b * NSEQ + irow0) * BDIM + col) =
            make_float2(Oc[nt2][0] * inv0, Oc[nt2][1] * inv0);
        *reinterpret_cast<float2*>(ctx + (size_t)(b * NSEQ + irow1) * BDIM + col) =
            make_float2(Oc[nt2][2] * inv1, Oc[nt2][3] * inv1);
    }
}

// ---------------- launch ----------------
extern "C" void kernel_launch(void* const* d_in, const int* in_sizes, int n_in,
                              void* d_out, int out_size)
{
    const float* x      = (const float*)d_in[0];
    const int*   mask   = (const int*)  d_in[1];
    const float* ln1_g  = (const float*)d_in[2];
    const float* ln1_b  = (const float*)d_in[3];
    const float* qkv_w  = (const float*)d_in[4];
    const float* qkv_b  = (const float*)d_in[5];
    const float* proj_w = (const float*)d_in[6];
    const float* proj_b = (const float*)d_in[7];
    const float* rel    = (const float*)d_in[8];
    const float* ln2_g  = (const float*)d_in[9];
    const float* ln2_b  = (const float*)d_in[10];
    const float* w1     = (const float*)d_in[11];
    const float* b1     = (const float*)d_in[12];
    const float* w2     = (const float*)d_in[13];
    const float* b2     = (const float*)d_in[14];
    const float* gate1  = (const float*)d_in[15];
    const float* gate2  = (const float*)d_in[16];
    float* out = (float*)d_out;

    float *xn, *qkv, *ctx, *y, *mlp;
    cudaGetSymbolAddress((void**)&xn,  g_xn);
    cudaGetSymbolAddress((void**)&qkv, g_qkv);
    cudaGetSymbolAddress((void**)&ctx, g_ctx);
    cudaGetSymbolAddress((void**)&y,   g_y);
    cudaGetSymbolAddress((void**)&mlp, g_mlp);

    // 1) LN1
    ln_kernel<<<ROWS, 256>>>(x, ln1_g, ln1_b, xn);
    // 2) qkv = xn @ qkv_w + qkv_b
    tf32gemm_kernel<EPI_BIAS><<<dim3(3 * BDIM / 128, ROWS / 128), 256>>>(
        xn, qkv_w, qkv_b, nullptr, nullptr, qkv, ROWS, 3 * BDIM, BDIM);
    // 3) fused attention -> ctx
    flash_attn_kernel<<<dim3(NSEQ / 128, NB * NHEADS), 256>>>(qkv, mask, rel, ctx);
    // 4) y = x + gate1 * (ctx @ proj_w + proj_b)
    tf32gemm_kernel<EPI_RESGATE><<<dim3(BDIM / 128, ROWS / 128), 256>>>(
        ctx, proj_w, proj_b, x, gate1, y, ROWS, BDIM, BDIM);
    // 5) LN2
    ln_kernel<<<ROWS, 256>>>(y, ln2_g, ln2_b, xn);
    // 6) mlp = gelu(xn @ w1 + b1)
    tf32gemm_kernel<EPI_GELU><<<dim3(4 * BDIM / 128, ROWS / 128), 256>>>(
        xn, w1, b1, nullptr, nullptr, mlp, ROWS, 4 * BDIM, BDIM);
    // 7) out = y + gate2 * (mlp @ w2 + b2)
    tf32gemm_kernel<EPI_RESGATE><<<dim3(BDIM / 128, ROWS / 128), 256>>>(
        mlp, w2, b2, y, gate2, out, ROWS, BDIM, 4 * BDIM);
}

// round 4
// speedup vs baseline: 3.1119x; 1.0538x over previous
#include <cuda_runtime.h>
#include <math.h>
#include <stdint.h>

#define BDIM 1024
#define NB 4
#define NSEQ 1024
#define NHEADS 16
#define HDIM 64
#define ROWS (NB*NSEQ)   // 4096
#define MAXSEQ 1024

// ---------------- scratch (device globals; no allocation allowed) ----------------
__device__ float g_xn[(size_t)ROWS*BDIM];               // 16 MB
__device__ float g_qkv[(size_t)ROWS*3*BDIM];            // 48 MB
__device__ float g_ctx[(size_t)ROWS*BDIM];              // 16 MB
__device__ float g_y[(size_t)ROWS*BDIM];                // 16 MB
__device__ float g_mlp[(size_t)ROWS*4*BDIM];            // 64 MB
// tf32-rounded weights
__device__ float g_qkvw[(size_t)BDIM*3*BDIM];           // 12 MB
__device__ float g_projw[(size_t)BDIM*BDIM];            // 4 MB
__device__ float g_w1[(size_t)BDIM*4*BDIM];             // 16 MB
__device__ float g_w2[(size_t)4*BDIM*BDIM];             // 16 MB

// ---------------- helpers ----------------
__device__ __forceinline__ uint32_t f2tf(float x) {
    uint32_t r;
    asm("cvt.rna.tf32.f32 %0, %1;" : "=r"(r) : "f"(x));
    return r;
}
__device__ __forceinline__ float f2tff(float x) { return __uint_as_float(f2tf(x)); }

__device__ __forceinline__ void mma_tf32(float c[4], const uint32_t a[4], const uint32_t b[2]) {
    asm volatile(
        "mma.sync.aligned.m16n8k8.row.col.f32.tf32.tf32.f32 "
        "{%0,%1,%2,%3}, {%4,%5,%6,%7}, {%8,%9}, {%0,%1,%2,%3};"
        : "+f"(c[0]), "+f"(c[1]), "+f"(c[2]), "+f"(c[3])
        : "r"(a[0]), "r"(a[1]), "r"(a[2]), "r"(a[3]), "r"(b[0]), "r"(b[1]));
}

__device__ __forceinline__ void cp_async16(uint32_t smem_addr, const void* gptr) {
    asm volatile("cp.async.cg.shared.global [%0], [%1], 16;"
                 :: "r"(smem_addr), "l"(gptr));
}
__device__ __forceinline__ void cp_commit() { asm volatile("cp.async.commit_group;"); }
template<int N>
__device__ __forceinline__ void cp_wait() { asm volatile("cp.async.wait_group %0;" :: "n"(N)); }

// ---------------- weight -> tf32 rounding (per launch; deterministic) ----------------
__global__ __launch_bounds__(256) void cvt_tf32_kernel(const float* __restrict__ in,
                                                       float* __restrict__ out, int n4)
{
    int i = blockIdx.x * 256 + threadIdx.x;
    if (i < n4) {
        float4 v = reinterpret_cast<const float4*>(in)[i];
        v.x = f2tff(v.x); v.y = f2tff(v.y); v.z = f2tff(v.z); v.w = f2tff(v.w);
        reinterpret_cast<float4*>(out)[i] = v;
    }
}

// ---------------- LayerNorm: one block per row; output tf32-rounded ----------------
__global__ __launch_bounds__(256) void ln_kernel(const float* __restrict__ x,
    const float* __restrict__ g, const float* __restrict__ b, float* __restrict__ out)
{
    __shared__ float red[256];
    const int row = blockIdx.x;
    const int t = threadIdx.x;
    const float4* xr = reinterpret_cast<const float4*>(x + (size_t)row * BDIM);
    float4 v = xr[t];
    float s = v.x + v.y + v.z + v.w;
    red[t] = s; __syncthreads();
    #pragma unroll
    for (int o = 128; o > 0; o >>= 1) { if (t < o) red[t] += red[t + o]; __syncthreads(); }
    const float mu = red[0] * (1.0f / BDIM);
    __syncthreads();
    float dx = v.x - mu, dy = v.y - mu, dz = v.z - mu, dw = v.w - mu;
    red[t] = dx*dx + dy*dy + dz*dz + dw*dw; __syncthreads();
    #pragma unroll
    for (int o = 128; o > 0; o >>= 1) { if (t < o) red[t] += red[t + o]; __syncthreads(); }
    const float var = red[0] * (1.0f / BDIM);
    const float rinv = rsqrtf(var + 1e-5f);
    float4 gg = reinterpret_cast<const float4*>(g)[t];
    float4 bb = reinterpret_cast<const float4*>(b)[t];
    float4 o4;
    o4.x = f2tff(dx * rinv * gg.x + bb.x);
    o4.y = f2tff(dy * rinv * gg.y + bb.y);
    o4.z = f2tff(dz * rinv * gg.z + bb.z);
    o4.w = f2tff(dw * rinv * gg.w + bb.w);
    reinterpret_cast<float4*>(out + (size_t)row * BDIM)[t] = o4;
}

// ---------------- 4-stage cp.async TF32 GEMM (inputs pre-rounded to tf32) ----------------
enum { EPI_BIAS = 0, EPI_GELU = 1, EPI_RESGATE = 2 };

#define GSTAGES 4
#define G_AST 20
#define G_BST 136
#define G_ASW (128*G_AST)       // 2560 words / stage
#define G_BSW (16*G_BST)        // 2176 words / stage
#define GEMM_SMEM (GSTAGES*(G_ASW+G_BSW)*4)   // 75776 bytes

template<int EPI>
__global__ __launch_bounds__(256, 2) void tf32gemm_kernel(
    const float* __restrict__ A, const float* __restrict__ B,
    const float* __restrict__ bias, const float* __restrict__ res,
    const float* __restrict__ gate, float* __restrict__ C,
    int M, int N, int K)
{
    constexpr int BM = 128, BN = 128, BK = 16;
    extern __shared__ uint32_t sm[];
    uint32_t* As = sm;                       // [GSTAGES][G_ASW]
    uint32_t* Bs = sm + GSTAGES * G_ASW;     // [GSTAGES][G_BSW]
    const uint32_t As_u = (uint32_t)__cvta_generic_to_shared(As);
    const uint32_t Bs_u = (uint32_t)__cvta_generic_to_shared(Bs);

    const int tid  = threadIdx.x;
    const int lane = tid & 31;
    const int wid  = tid >> 5;
    const int g    = lane >> 2;
    const int t4   = lane & 3;
    const int mWarp = (wid >> 2) * 64;
    const int nWarp = (wid & 3) * 32;

    const int aRow = tid >> 2;             // 0..63 (+64)
    const int aCol = (tid & 3) * 4;
    const int bRow = tid >> 5;             // 0..7 (+8)
    const int bCol = (tid & 31) * 4;

    const float* Ap = A + (size_t)(blockIdx.y * BM + aRow) * K + aCol;
    const float* Bp = B + (size_t)bRow * N + blockIdx.x * BN + bCol;
    const uint32_t aDst = As_u + (uint32_t)(aRow * G_AST + aCol) * 4;
    const uint32_t bDst = Bs_u + (uint32_t)(bRow * G_BST + bCol) * 4;

    const int nT = K / BK;

    // prologue: stages 0..2
    #pragma unroll
    for (int t = 0; t < GSTAGES - 1; t++) {
        const uint32_t so = (uint32_t)(t * G_ASW) * 4;
        const uint32_t sb = (uint32_t)(t * G_BSW) * 4;
        cp_async16(aDst + so, Ap + (size_t)t * BK);
        cp_async16(aDst + so + 64 * G_AST * 4, Ap + (size_t)t * BK + (size_t)64 * K);
        cp_async16(bDst + sb, Bp + (size_t)t * BK * N);
        cp_async16(bDst + sb + 8 * G_BST * 4, Bp + (size_t)(t * BK + 8) * N);
        cp_commit();
    }

    float acc[4][4][4] = {};

    for (int t = 0; t < nT; t++) {
        cp_wait<GSTAGES - 2>();
        __syncthreads();

        // issue stage t+3
        const int tn = t + GSTAGES - 1;
        if (tn < nT) {
            const int slotn = tn & (GSTAGES - 1);
            const uint32_t so = (uint32_t)(slotn * G_ASW) * 4;
            const uint32_t sb = (uint32_t)(slotn * G_BSW) * 4;
            cp_async16(aDst + so, Ap + (size_t)tn * BK);
            cp_async16(aDst + so + 64 * G_AST * 4, Ap + (size_t)tn * BK + (size_t)64 * K);
            cp_async16(bDst + sb, Bp + (size_t)tn * BK * N);
            cp_async16(bDst + sb + 8 * G_BST * 4, Bp + (size_t)(tn * BK + 8) * N);
        }
        cp_commit();

        // compute on slot t
        const int slot = t & (GSTAGES - 1);
        const uint32_t* Ass = As + slot * G_ASW;
        const uint32_t* Bss = Bs + slot * G_BSW;
        #pragma unroll
        for (int ks = 0; ks < 2; ks++) {
            const int k0 = ks * 8;
            uint32_t bf[4][2];
            #pragma unroll
            for (int ni = 0; ni < 4; ni++) {
                const int nb = nWarp + ni * 8;
                bf[ni][0] = Bss[(k0 + t4) * G_BST + nb + g];
                bf[ni][1] = Bss[(k0 + t4 + 4) * G_BST + nb + g];
            }
            #pragma unroll
            for (int mi = 0; mi < 4; mi++) {
                const int mb = mWarp + mi * 16;
                uint32_t af[4];
                af[0] = Ass[(mb + g) * G_AST + k0 + t4];
                af[1] = Ass[(mb + g + 8) * G_AST + k0 + t4];
                af[2] = Ass[(mb + g) * G_AST + k0 + t4 + 4];
                af[3] = Ass[(mb + g + 8) * G_AST + k0 + t4 + 4];
                #pragma unroll
                for (int ni = 0; ni < 4; ni++)
                    mma_tf32(acc[mi][ni], af, bf[ni]);
            }
        }
        __syncthreads();
    }

    // epilogue
    const float gt = (EPI == EPI_RESGATE) ? gate[0] : 0.0f;
    #pragma unroll
    for (int mi = 0; mi < 4; mi++) {
        const int row0 = blockIdx.y * BM + mWarp + mi * 16 + g;
        #pragma unroll
        for (int ni = 0; ni < 4; ni++) {
            const int col = blockIdx.x * BN + nWarp + ni * 8 + t4 * 2;
            const float b0 = bias[col], b1 = bias[col + 1];
            #pragma unroll
            for (int h = 0; h < 2; h++) {
                const int row = row0 + h * 8;
                float v0 = acc[mi][ni][2 * h + 0] + b0;
                float v1 = acc[mi][ni][2 * h + 1] + b1;
                if (EPI == EPI_GELU) {
                    v0 = f2tff(0.5f * v0 * (1.0f + erff(v0 * 0.70710678118654752f)));
                    v1 = f2tff(0.5f * v1 * (1.0f + erff(v1 * 0.70710678118654752f)));
                }
                if (EPI == EPI_RESGATE) {
                    const size_t off = (size_t)row * N + col;
                    v0 = res[off] + gt * v0;
                    v1 = res[off + 1] + gt * v1;
                }
                *reinterpret_cast<float2*>(C + (size_t)row * N + col) = make_float2(v0, v1);
            }
        }
    }
}

// ---------------- Fused flash attention (TF32 tensor cores) ----------------
__global__ __launch_bounds__(256) void flash_attn_kernel(
    const float* __restrict__ qkv, const int* __restrict__ mask,
    const float* __restrict__ rel, float* __restrict__ ctx)
{
    constexpr int KST = 68;
    constexpr int VST = 72;
    constexpr float SCALE = 0.125f;
    constexpr float L2E = 1.4426950408889634f;

    __shared__ __align__(16) uint32_t smbuf[64*KST + 64*VST + 64 + 2047 + 1];
    uint32_t* Ks = smbuf;
    uint32_t* Vs = smbuf + 64*KST;
    float* mk    = reinterpret_cast<float*>(smbuf + 64*KST + 64*VST);
    float* rel_s = mk + 64;
    uint32_t* Qst = smbuf;

    const int bh = blockIdx.y;
    const int b = bh >> 4, h = bh & 15;
    const int i0 = blockIdx.x * 128;
    const int tid = threadIdx.x, lane = tid & 31, w = tid >> 5;
    const int g = lane >> 2, t4 = lane & 3;

    for (int idx = tid; idx < 2 * MAXSEQ - 1; idx += 256)
        rel_s[idx] = rel[(size_t)idx * NHEADS + h];

    {
        const int r = tid >> 1;
        const int c0 = (tid & 1) * 32;
        const float* qp = qkv + ((size_t)(b * NSEQ + i0 + r)) * (3 * BDIM) + h * HDIM + c0;
        #pragma unroll
        for (int i = 0; i < 8; i++) {
            float4 v = *reinterpret_cast<const float4*>(qp + 4 * i);
            uint4 u;
            u.x = f2tf(v.x); u.y = f2tf(v.y); u.z = f2tf(v.z); u.w = f2tf(v.w);
            *reinterpret_cast<uint4*>(&Qst[r * KST + c0 + 4 * i]) = u;
        }
    }
    __syncthreads();

    uint32_t Qa[8][4];
    #pragma unroll
    for (int kt = 0; kt < 8; kt++) {
        const int r0 = (w * 16 + g) * KST + kt * 8 + t4;
        Qa[kt][0] = Qst[r0];
        Qa[kt][1] = Qst[r0 + 8 * KST];
        Qa[kt][2] = Qst[r0 + 4];
        Qa[kt][3] = Qst[r0 + 8 * KST + 4];
    }
    __syncthreads();

    const int irow0 = i0 + w * 16 + g;
    const int irow1 = irow0 + 8;
    const float mi0 = (float)mask[b * NSEQ + irow0];
    const float mi1 = (float)mask[b * NSEQ + irow1];

    float m0 = -INFINITY, m1 = -INFINITY, l0 = 0.0f, l1 = 0.0f;
    float Oc[8][4] = {};

    for (int jt = 0; jt < NSEQ / 64; jt++) {
        {
            const int r = tid >> 2, q4 = (tid & 3) * 16;
            const float* kp = qkv + ((size_t)(b * NSEQ + jt * 64 + r)) * (3 * BDIM) + BDIM + h * HDIM + q4;
            #pragma unroll
            for (int i = 0; i < 4; i++) {
                float4 kv = *reinterpret_cast<const float4*>(kp + 4 * i);
                uint4 u;
                u.x = f2tf(kv.x); u.y = f2tf(kv.y); u.z = f2tf(kv.z); u.w = f2tf(kv.w);
                *reinterpret_cast<uint4*>(&Ks[r * KST + q4 + 4 * i]) = u;
                float4 vv = *reinterpret_cast<const float4*>(kp + BDIM + 4 * i);
                uint4 uv;
                uv.x = f2tf(vv.x); uv.y = f2tf(vv.y); uv.z = f2tf(vv.z); uv.w = f2tf(vv.w);
                *reinterpret_cast<uint4*>(&Vs[r * VST + q4 + 4 * i]) = uv;
            }
            if (tid < 64) mk[tid] = (float)mask[b * NSEQ + jt * 64 + tid];
        }
        __syncthreads();

        float S[8][4] = {};
        #pragma unroll
        for (int nt = 0; nt < 8; nt++) {
            #pragma unroll
            for (int kt = 0; kt < 8; kt++) {
                uint32_t bf[2];
                bf[0] = Ks[(nt * 8 + g) * KST + kt * 8 + t4];
                bf[1] = Ks[(nt * 8 + g) * KST + kt * 8 + t4 + 4];
                mma_tf32(S[nt], Qa[kt], bf);
            }
        }

        float tmax0 = -INFINITY, tmax1 = -INFINITY;
        #pragma unroll
        for (int nt = 0; nt < 8; nt++) {
            const int j0 = jt * 64 + nt * 8 + 2 * t4;
            const float mk0 = mk[nt * 8 + 2 * t4];
            const float mk1 = mk[nt * 8 + 2 * t4 + 1];
            float s0 = S[nt][0] * SCALE + rel_s[irow0 - j0 + (MAXSEQ - 1)];
            float s1 = S[nt][1] * SCALE + rel_s[irow0 - j0 - 1 + (MAXSEQ - 1)];
            float s2 = S[nt][2] * SCALE + rel_s[irow1 - j0 + (MAXSEQ - 1)];
            float s3 = S[nt][3] * SCALE + rel_s[irow1 - j0 - 1 + (MAXSEQ - 1)];
            if (mi0 * mk0 < 0.5f) s0 = -1e9f;
            if (mi0 * mk1 < 0.5f) s1 = -1e9f;
            if (mi1 * mk0 < 0.5f) s2 = -1e9f;
            if (mi1 * mk1 < 0.5f) s3 = -1e9f;
            S[nt][0] = s0; S[nt][1] = s1; S[nt][2] = s2; S[nt][3] = s3;
            tmax0 = fmaxf(tmax0, fmaxf(s0, s1));
            tmax1 = fmaxf(tmax1, fmaxf(s2, s3));
        }
        tmax0 = fmaxf(tmax0, __shfl_xor_sync(0xffffffffu, tmax0, 1));
        tmax0 = fmaxf(tmax0, __shfl_xor_sync(0xffffffffu, tmax0, 2));
        tmax1 = fmaxf(tmax1, __shfl_xor_sync(0xffffffffu, tmax1, 1));
        tmax1 = fmaxf(tmax1, __shfl_xor_sync(0xffffffffu, tmax1, 2));

        const float mn0 = fmaxf(m0, tmax0);
        const float mn1 = fmaxf(m1, tmax1);
        const float sc0 = exp2f((m0 - mn0) * L2E);
        const float sc1 = exp2f((m1 - mn1) * L2E);
        m0 = mn0; m1 = mn1;

        float ts0 = 0.0f, ts1 = 0.0f;
        #pragma unroll
        for (int nt = 0; nt < 8; nt++) {
            S[nt][0] = exp2f((S[nt][0] - mn0) * L2E);
            S[nt][1] = exp2f((S[nt][1] - mn0) * L2E);
            S[nt][2] = exp2f((S[nt][2] - mn1) * L2E);
            S[nt][3] = exp2f((S[nt][3] - mn1) * L2E);
            ts0 += S[nt][0] + S[nt][1];
            ts1 += S[nt][2] + S[nt][3];
        }
        ts0 += __shfl_xor_sync(0xffffffffu, ts0, 1);
        ts0 += __shfl_xor_sync(0xffffffffu, ts0, 2);
        ts1 += __shfl_xor_sync(0xffffffffu, ts1, 1);
        ts1 += __shfl_xor_sync(0xffffffffu, ts1, 2);
        l0 = l0 * sc0 + ts0;
        l1 = l1 * sc1 + ts1;

        #pragma unroll
        for (int nt = 0; nt < 8; nt++) {
            Oc[nt][0] *= sc0; Oc[nt][1] *= sc0;
            Oc[nt][2] *= sc1; Oc[nt][3] *= sc1;
        }

        #pragma unroll
        for (int kt = 0; kt < 8; kt++) {
            const int srcA = 4 * g + (t4 >> 1);
            const int srcB = srcA + 2;
            const bool odd = (t4 & 1);
            float v0 = __shfl_sync(0xffffffffu, S[kt][0], srcA);
            float v1 = __shfl_sync(0xffffffffu, S[kt][1], srcA);
            float v2 = __shfl_sync(0xffffffffu, S[kt][2], srcA);
            float v3 = __shfl_sync(0xffffffffu, S[kt][3], srcA);
            float u0 = __shfl_sync(0xffffffffu, S[kt][0], srcB);
            float u1 = __shfl_sync(0xffffffffu, S[kt][1], srcB);
            float u2 = __shfl_sync(0xffffffffu, S[kt][2], srcB);
            float u3 = __shfl_sync(0xffffffffu, S[kt][3], srcB);
            uint32_t a[4];
            a[0] = f2tf(odd ? v1 : v0);
            a[1] = f2tf(odd ? v3 : v2);
            a[2] = f2tf(odd ? u1 : u0);
            a[3] = f2tf(odd ? u3 : u2);
            #pragma unroll
            for (int nt2 = 0; nt2 < 8; nt2++) {
                uint32_t bf[2];
                bf[0] = Vs[(kt * 8 + t4) * VST + nt2 * 8 + g];
                bf[1] = Vs[(kt * 8 + t4 + 4) * VST + nt2 * 8 + g];
                mma_tf32(Oc[nt2], a, bf);
            }
        }
        __syncthreads();
    }

    // writeback ctx = O / l, tf32-rounded (feeds proj GEMM)
    const float inv0 = 1.0f / l0;
    const float inv1 = 1.0f / l1;
    #pragma unroll
    for (int nt2 = 0; nt2 < 8; nt2++) {
        const int col = h * HDIM + nt2 * 8 + 2 * t4;
        *reinterpret_cast<float2*>(ctx + (size_t)(b * NSEQ + irow0) * BDIM + col) =
            make_float2(f2tff(Oc[nt2][0] * inv0), f2tff(Oc[nt2][1] * inv0));
        *reinterpret_cast<float2*>(ctx + (size_t)(b * NSEQ + irow1) * BDIM + col) =
            make_float2(f2tff(Oc[nt2][2] * inv1), f2tff(Oc[nt2][3] * inv1));
    }
}

// ---------------- launch ----------------
extern "C" void kernel_launch(void* const* d_in, const int* in_sizes, int n_in,
                              void* d_out, int out_size)
{
    const float* x      = (const float*)d_in[0];
    const int*   mask   = (const int*)  d_in[1];
    const float* ln1_g  = (const float*)d_in[2];
    const float* ln1_b  = (const float*)d_in[3];
    const float* qkv_w  = (const float*)d_in[4];
    const float* qkv_b  = (const float*)d_in[5];
    const float* proj_w = (const float*)d_in[6];
    const float* proj_b = (const float*)d_in[7];
    const float* rel    = (const float*)d_in[8];
    const float* ln2_g  = (const float*)d_in[9];
    const float* ln2_b  = (const float*)d_in[10];
    const float* w1     = (const float*)d_in[11];
    const float* b1     = (const float*)d_in[12];
    const float* w2     = (const float*)d_in[13];
    const float* b2     = (const float*)d_in[14];
    const float* gate1  = (const float*)d_in[15];
    const float* gate2  = (const float*)d_in[16];
    float* out = (float*)d_out;

    float *xn, *qkv, *ctx, *y, *mlp, *qkvw, *projw, *w1t, *w2t;
    cudaGetSymbolAddress((void**)&xn,    g_xn);
    cudaGetSymbolAddress((void**)&qkv,   g_qkv);
    cudaGetSymbolAddress((void**)&ctx,   g_ctx);
    cudaGetSymbolAddress((void**)&y,     g_y);
    cudaGetSymbolAddress((void**)&mlp,   g_mlp);
    cudaGetSymbolAddress((void**)&qkvw,  g_qkvw);
    cudaGetSymbolAddress((void**)&projw, g_projw);
    cudaGetSymbolAddress((void**)&w1t,   g_w1);
    cudaGetSymbolAddress((void**)&w2t,   g_w2);

    static bool attr_set = false;
    if (!attr_set) {
        cudaFuncSetAttribute(tf32gemm_kernel<EPI_BIAS>,
                             cudaFuncAttributeMaxDynamicSharedMemorySize, GEMM_SMEM);
        cudaFuncSetAttribute(tf32gemm_kernel<EPI_GELU>,
                             cudaFuncAttributeMaxDynamicSharedMemorySize, GEMM_SMEM);
        cudaFuncSetAttribute(tf32gemm_kernel<EPI_RESGATE>,
                             cudaFuncAttributeMaxDynamicSharedMemorySize, GEMM_SMEM);
        attr_set = true;
    }

    // 0) round weights to tf32 (deterministic, every launch)
    cvt_tf32_kernel<<<(BDIM*3*BDIM/4 + 255)/256, 256>>>(qkv_w, qkvw, BDIM*3*BDIM/4);
    cvt_tf32_kernel<<<(BDIM*BDIM/4   + 255)/256, 256>>>(proj_w, projw, BDIM*BDIM/4);
    cvt_tf32_kernel<<<(BDIM*4*BDIM/4 + 255)/256, 256>>>(w1, w1t, BDIM*4*BDIM/4);
    cvt_tf32_kernel<<<(4*BDIM*BDIM/4 + 255)/256, 256>>>(w2, w2t, 4*BDIM*BDIM/4);

    // 1) LN1 (tf32-rounded output)
    ln_kernel<<<ROWS, 256>>>(x, ln1_g, ln1_b, xn);
    // 2) qkv = xn @ qkvw + qkv_b
    tf32gemm_kernel<EPI_BIAS><<<dim3(3 * BDIM / 128, ROWS / 128), 256, GEMM_SMEM>>>(
        xn, qkvw, qkv_b, nullptr, nullptr, qkv, ROWS, 3 * BDIM, BDIM);
    // 3) fused attention -> ctx (tf32-rounded)
    flash_attn_kernel<<<dim3(NSEQ / 128, NB * NHEADS), 256>>>(qkv, mask, rel, ctx);
    // 4) y = x + gate1 * (ctx @ projw + proj_b)
    tf32gemm_kernel<EPI_RESGATE><<<dim3(BDIM / 128, ROWS / 128), 256, GEMM_SMEM>>>(
        ctx, projw, proj_b, x, gate1, y, ROWS, BDIM, BDIM);
    // 5) LN2 (tf32-rounded output)
    ln_kernel<<<ROWS, 256>>>(y, ln2_g, ln2_b, xn);
    // 6) mlp = gelu(xn @ w1t + b1) (tf32-rounded)
    tf32gemm_kernel<EPI_GELU><<<dim3(4 * BDIM / 128, ROWS / 128), 256, GEMM_SMEM>>>(
        xn, w1t, b1, nullptr, nullptr, mlp, ROWS, 4 * BDIM, BDIM);
    // 7) out = y + gate2 * (mlp @ w2t + b2)
    tf32gemm_kernel<EPI_RESGATE><<<dim3(BDIM / 128, ROWS / 128), 256, GEMM_SMEM>>>(
        mlp, w2t, b2, y, gate2, out, ROWS, BDIM, 4 * BDIM);
}

// round 5
// speedup vs baseline: 3.3436x; 1.0745x over previous
#include <cuda_runtime.h>
#include <math.h>
#include <stdint.h>

#define BDIM 1024
#define NB 4
#define NSEQ 1024
#define NHEADS 16
#define HDIM 64
#define ROWS (NB*NSEQ)   // 4096
#define MAXSEQ 1024

// ---------------- scratch (device globals; no allocation allowed) ----------------
__device__ float g_xn[(size_t)ROWS*BDIM];               // 16 MB
__device__ float g_qkv[(size_t)ROWS*3*BDIM];            // 48 MB
__device__ float g_ctx[(size_t)ROWS*BDIM];              // 16 MB
__device__ float g_y[(size_t)ROWS*BDIM];                // 16 MB
__device__ float g_mlp[(size_t)ROWS*4*BDIM];            // 64 MB
// tf32-rounded weights
__device__ float g_qkvw[(size_t)BDIM*3*BDIM];           // 12 MB
__device__ float g_projw[(size_t)BDIM*BDIM];            // 4 MB
__device__ float g_w1[(size_t)BDIM*4*BDIM];             // 16 MB
__device__ float g_w2[(size_t)4*BDIM*BDIM];             // 16 MB

// ---------------- helpers ----------------
__device__ __forceinline__ uint32_t f2tf(float x) {
    uint32_t r;
    asm("cvt.rna.tf32.f32 %0, %1;" : "=r"(r) : "f"(x));
    return r;
}
__device__ __forceinline__ float f2tff(float x) { return __uint_as_float(f2tf(x)); }

__device__ __forceinline__ void mma_tf32(float c[4], const uint32_t a[4], const uint32_t b[2]) {
    asm volatile(
        "mma.sync.aligned.m16n8k8.row.col.f32.tf32.tf32.f32 "
        "{%0,%1,%2,%3}, {%4,%5,%6,%7}, {%8,%9}, {%0,%1,%2,%3};"
        : "+f"(c[0]), "+f"(c[1]), "+f"(c[2]), "+f"(c[3])
        : "r"(a[0]), "r"(a[1]), "r"(a[2]), "r"(a[3]), "r"(b[0]), "r"(b[1]));
}

__device__ __forceinline__ void cp_async16(uint32_t smem_addr, const void* gptr) {
    asm volatile("cp.async.cg.shared.global [%0], [%1], 16;"
                 :: "r"(smem_addr), "l"(gptr));
}
__device__ __forceinline__ void cp_commit() { asm volatile("cp.async.commit_group;"); }
template<int N>
__device__ __forceinline__ void cp_wait() { asm volatile("cp.async.wait_group %0;" :: "n"(N)); }

// ---------------- merged weight -> tf32 rounding (single launch) ----------------
#define N4_QKV  (BDIM*3*BDIM/4)   // 786432
#define N4_PROJ (BDIM*BDIM/4)     // 262144
#define N4_W1   (BDIM*4*BDIM/4)   // 1048576
#define N4_W2   (4*BDIM*BDIM/4)   // 1048576
#define N4_TOT  (N4_QKV+N4_PROJ+N4_W1+N4_W2)   // 3145728

__global__ __launch_bounds__(256) void cvt_all_kernel(
    const float* __restrict__ i0, float* __restrict__ o0,
    const float* __restrict__ i1, float* __restrict__ o1,
    const float* __restrict__ i2, float* __restrict__ o2,
    const float* __restrict__ i3, float* __restrict__ o3)
{
    int i = blockIdx.x * 256 + threadIdx.x;
    const float4* in;
    float4* out;
    if (i < N4_QKV) { in = (const float4*)i0; out = (float4*)o0; }
    else if (i < N4_QKV + N4_PROJ) { i -= N4_QKV; in = (const float4*)i1; out = (float4*)o1; }
    else if (i < N4_QKV + N4_PROJ + N4_W1) { i -= N4_QKV + N4_PROJ; in = (const float4*)i2; out = (float4*)o2; }
    else { i -= N4_QKV + N4_PROJ + N4_W1; in = (const float4*)i3; out = (float4*)o3; }
    float4 v = in[i];
    v.x = f2tff(v.x); v.y = f2tff(v.y); v.z = f2tff(v.z); v.w = f2tff(v.w);
    out[i] = v;
}

// ---------------- LayerNorm: one block per row; output tf32-rounded ----------------
__global__ __launch_bounds__(256) void ln_kernel(const float* __restrict__ x,
    const float* __restrict__ g, const float* __restrict__ b, float* __restrict__ out)
{
    __shared__ float red[256];
    const int row = blockIdx.x;
    const int t = threadIdx.x;
    const float4* xr = reinterpret_cast<const float4*>(x + (size_t)row * BDIM);
    float4 v = xr[t];
    float s = v.x + v.y + v.z + v.w;
    red[t] = s; __syncthreads();
    #pragma unroll
    for (int o = 128; o > 0; o >>= 1) { if (t < o) red[t] += red[t + o]; __syncthreads(); }
    const float mu = red[0] * (1.0f / BDIM);
    __syncthreads();
    float dx = v.x - mu, dy = v.y - mu, dz = v.z - mu, dw = v.w - mu;
    red[t] = dx*dx + dy*dy + dz*dz + dw*dw; __syncthreads();
    #pragma unroll
    for (int o = 128; o > 0; o >>= 1) { if (t < o) red[t] += red[t + o]; __syncthreads(); }
    const float var = red[0] * (1.0f / BDIM);
    const float rinv = rsqrtf(var + 1e-5f);
    float4 gg = reinterpret_cast<const float4*>(g)[t];
    float4 bb = reinterpret_cast<const float4*>(b)[t];
    float4 o4;
    o4.x = f2tff(dx * rinv * gg.x + bb.x);
    o4.y = f2tff(dy * rinv * gg.y + bb.y);
    o4.z = f2tff(dz * rinv * gg.z + bb.z);
    o4.w = f2tff(dw * rinv * gg.w + bb.w);
    reinterpret_cast<float4*>(out + (size_t)row * BDIM)[t] = o4;
}

// ---------------- 3-stage cp.async TF32 GEMM, BK=32 (inputs pre-rounded) ----------------
enum { EPI_BIAS = 0, EPI_GELU = 1, EPI_RESGATE = 2 };

#define GSTAGES 3
#define G_AST 36
#define G_BST 136
#define G_ASW (128*G_AST)       // 4608 words / stage
#define G_BSW (32*G_BST)        // 4352 words / stage
#define GEMM_SMEM (GSTAGES*(G_ASW+G_BSW)*4)   // 107520 bytes

template<int EPI>
__global__ __launch_bounds__(256, 2) void tf32gemm_kernel(
    const float* __restrict__ A, const float* __restrict__ B,
    const float* __restrict__ bias, const float* __restrict__ res,
    const float* __restrict__ gate, float* __restrict__ C,
    int M, int N, int K)
{
    constexpr int BM = 128, BN = 128, BK = 32;
    extern __shared__ uint32_t sm[];
    uint32_t* As = sm;                       // [GSTAGES][G_ASW]
    uint32_t* Bs = sm + GSTAGES * G_ASW;     // [GSTAGES][G_BSW]
    const uint32_t As_u = (uint32_t)__cvta_generic_to_shared(As);
    const uint32_t Bs_u = (uint32_t)__cvta_generic_to_shared(Bs);

    const int tid  = threadIdx.x;
    const int lane = tid & 31;
    const int wid  = tid >> 5;
    const int g    = lane >> 2;
    const int t4   = lane & 3;
    const int mWarp = (wid >> 2) * 64;
    const int nWarp = (wid & 3) * 32;

    // global load mapping (per stage: A 128x32, B 32x128; 8 cp.async / thread)
    const int aRow = tid >> 3;             // 0..31 (+32r)
    const int aCol = (tid & 7) * 4;        // 0..28
    const int bRow = tid >> 5;             // 0..7  (+8s)
    const int bCol = (tid & 31) * 4;       // 0..124

    const float* Ap = A + (size_t)(blockIdx.y * BM + aRow) * K + aCol;
    const float* Bp = B + (size_t)bRow * N + blockIdx.x * BN + bCol;
    const uint32_t aDst = As_u + (uint32_t)(aRow * G_AST + aCol) * 4;
    const uint32_t bDst = Bs_u + (uint32_t)(bRow * G_BST + bCol) * 4;

    const int nT = K / BK;

    // prologue: stages 0..1
    #pragma unroll
    for (int t = 0; t < GSTAGES - 1; t++) {
        const uint32_t so = (uint32_t)(t * G_ASW) * 4;
        const uint32_t sb = (uint32_t)(t * G_BSW) * 4;
        const float* ap = Ap + (size_t)t * BK;
        const float* bp = Bp + (size_t)(t * BK) * N;
        #pragma unroll
        for (int r = 0; r < 4; r++)
            cp_async16(aDst + so + (uint32_t)(r * 32 * G_AST) * 4, ap + (size_t)(r * 32) * K);
        #pragma unroll
        for (int s = 0; s < 4; s++)
            cp_async16(bDst + sb + (uint32_t)(s * 8 * G_BST) * 4, bp + (size_t)(s * 8) * N);
        cp_commit();
    }

    float acc[4][4][4] = {};

    int slot = 0;
    for (int t = 0; t < nT; t++) {
        cp_wait<GSTAGES - 2>();
        __syncthreads();

        // issue stage t+2 into the slot freed by iteration t-1
        const int tn = t + GSTAGES - 1;
        if (tn < nT) {
            const int slotn = (slot + GSTAGES - 1) >= GSTAGES ? slot - 1 : slot + GSTAGES - 1;
            const uint32_t so = (uint32_t)(slotn * G_ASW) * 4;
            const uint32_t sb = (uint32_t)(slotn * G_BSW) * 4;
            const float* ap = Ap + (size_t)tn * BK;
            const float* bp = Bp + (size_t)(tn * BK) * N;
            #pragma unroll
            for (int r = 0; r < 4; r++)
                cp_async16(aDst + so + (uint32_t)(r * 32 * G_AST) * 4, ap + (size_t)(r * 32) * K);
            #pragma unroll
            for (int s = 0; s < 4; s++)
                cp_async16(bDst + sb + (uint32_t)(s * 8 * G_BST) * 4, bp + (size_t)(s * 8) * N);
        }
        cp_commit();

        // compute on current slot (4 k-slices of 8)
        const uint32_t* Ass = As + slot * G_ASW;
        const uint32_t* Bss = Bs + slot * G_BSW;
        #pragma unroll
        for (int ks = 0; ks < 4; ks++) {
            const int k0 = ks * 8;
            uint32_t bf[4][2];
            #pragma unroll
            for (int ni = 0; ni < 4; ni++) {
                const int nb = nWarp + ni * 8;
                bf[ni][0] = Bss[(k0 + t4) * G_BST + nb + g];
                bf[ni][1] = Bss[(k0 + t4 + 4) * G_BST + nb + g];
            }
            #pragma unroll
            for (int mi = 0; mi < 4; mi++) {
                const int mb = mWarp + mi * 16;
                uint32_t af[4];
                af[0] = Ass[(mb + g) * G_AST + k0 + t4];
                af[1] = Ass[(mb + g + 8) * G_AST + k0 + t4];
                af[2] = Ass[(mb + g) * G_AST + k0 + t4 + 4];
                af[3] = Ass[(mb + g + 8) * G_AST + k0 + t4 + 4];
                #pragma unroll
                for (int ni = 0; ni < 4; ni++)
                    mma_tf32(acc[mi][ni], af, bf[ni]);
            }
        }
        // NOTE: no trailing __syncthreads — top-of-loop barrier orders slot reuse.
        slot = (slot + 1 == GSTAGES) ? 0 : slot + 1;
    }

    // epilogue
    const float gt = (EPI == EPI_RESGATE) ? gate[0] : 0.0f;
    #pragma unroll
    for (int mi = 0; mi < 4; mi++) {
        const int row0 = blockIdx.y * BM + mWarp + mi * 16 + g;
        #pragma unroll
        for (int ni = 0; ni < 4; ni++) {
            const int col = blockIdx.x * BN + nWarp + ni * 8 + t4 * 2;
            const float b0 = bias[col], b1 = bias[col + 1];
            #pragma unroll
            for (int h = 0; h < 2; h++) {
                const int row = row0 + h * 8;
                float v0 = acc[mi][ni][2 * h + 0] + b0;
                float v1 = acc[mi][ni][2 * h + 1] + b1;
                if (EPI == EPI_GELU) {
                    v0 = f2tff(0.5f * v0 * (1.0f + erff(v0 * 0.70710678118654752f)));
                    v1 = f2tff(0.5f * v1 * (1.0f + erff(v1 * 0.70710678118654752f)));
                }
                if (EPI == EPI_RESGATE) {
                    const size_t off = (size_t)row * N + col;
                    v0 = res[off] + gt * v0;
                    v1 = res[off + 1] + gt * v1;
                }
                *reinterpret_cast<float2*>(C + (size_t)row * N + col) = make_float2(v0, v1);
            }
        }
    }
}

// ---------------- Fused flash attention (TF32 tensor cores) ----------------
__global__ __launch_bounds__(256) void flash_attn_kernel(
    const float* __restrict__ qkv, const int* __restrict__ mask,
    const float* __restrict__ rel, float* __restrict__ ctx)
{
    constexpr int KST = 68;
    constexpr int VST = 72;
    constexpr float SCALE = 0.125f;
    constexpr float L2E = 1.4426950408889634f;

    __shared__ __align__(16) uint32_t smbuf[64*KST + 64*VST + 64 + 2047 + 1];
    uint32_t* Ks = smbuf;
    uint32_t* Vs = smbuf + 64*KST;
    float* mk    = reinterpret_cast<float*>(smbuf + 64*KST + 64*VST);
    float* rel_s = mk + 64;
    uint32_t* Qst = smbuf;

    const int bh = blockIdx.y;
    const int b = bh >> 4, h = bh & 15;
    const int i0 = blockIdx.x * 128;
    const int tid = threadIdx.x, lane = tid & 31, w = tid >> 5;
    const int g = lane >> 2, t4 = lane & 3;

    for (int idx = tid; idx < 2 * MAXSEQ - 1; idx += 256)
        rel_s[idx] = rel[(size_t)idx * NHEADS + h];

    {
        const int r = tid >> 1;
        const int c0 = (tid & 1) * 32;
        const float* qp = qkv + ((size_t)(b * NSEQ + i0 + r)) * (3 * BDIM) + h * HDIM + c0;
        #pragma unroll
        for (int i = 0; i < 8; i++) {
            float4 v = *reinterpret_cast<const float4*>(qp + 4 * i);
            uint4 u;
            u.x = f2tf(v.x); u.y = f2tf(v.y); u.z = f2tf(v.z); u.w = f2tf(v.w);
            *reinterpret_cast<uint4*>(&Qst[r * KST + c0 + 4 * i]) = u;
        }
    }
    __syncthreads();

    uint32_t Qa[8][4];
    #pragma unroll
    for (int kt = 0; kt < 8; kt++) {
        const int r0 = (w * 16 + g) * KST + kt * 8 + t4;
        Qa[kt][0] = Qst[r0];
        Qa[kt][1] = Qst[r0 + 8 * KST];
        Qa[kt][2] = Qst[r0 + 4];
        Qa[kt][3] = Qst[r0 + 8 * KST + 4];
    }
    __syncthreads();

    const int irow0 = i0 + w * 16 + g;
    const int irow1 = irow0 + 8;
    const float mi0 = (float)mask[b * NSEQ + irow0];
    const float mi1 = (float)mask[b * NSEQ + irow1];

    float m0 = -INFINITY, m1 = -INFINITY, l0 = 0.0f, l1 = 0.0f;
    float Oc[8][4] = {};

    for (int jt = 0; jt < NSEQ / 64; jt++) {
        {
            const int r = tid >> 2, q4 = (tid & 3) * 16;
            const float* kp = qkv + ((size_t)(b * NSEQ + jt * 64 + r)) * (3 * BDIM) + BDIM + h * HDIM + q4;
            #pragma unroll
            for (int i = 0; i < 4; i++) {
                float4 kv = *reinterpret_cast<const float4*>(kp + 4 * i);
                uint4 u;
                u.x = f2tf(kv.x); u.y = f2tf(kv.y); u.z = f2tf(kv.z); u.w = f2tf(kv.w);
                *reinterpret_cast<uint4*>(&Ks[r * KST + q4 + 4 * i]) = u;
                float4 vv = *reinterpret_cast<const float4*>(kp + BDIM + 4 * i);
                uint4 uv;
                uv.x = f2tf(vv.x); uv.y = f2tf(vv.y); uv.z = f2tf(vv.z); uv.w = f2tf(vv.w);
                *reinterpret_cast<uint4*>(&Vs[r * VST + q4 + 4 * i]) = uv;
            }
            if (tid < 64) mk[tid] = (float)mask[b * NSEQ + jt * 64 + tid];
        }
        __syncthreads();

        float S[8][4] = {};
        #pragma unroll
        for (int nt = 0; nt < 8; nt++) {
            #pragma unroll
            for (int kt = 0; kt < 8; kt++) {
                uint32_t bf[2];
                bf[0] = Ks[(nt * 8 + g) * KST + kt * 8 + t4];
                bf[1] = Ks[(nt * 8 + g) * KST + kt * 8 + t4 + 4];
                mma_tf32(S[nt], Qa[kt], bf);
            }
        }

        float tmax0 = -INFINITY, tmax1 = -INFINITY;
        #pragma unroll
        for (int nt = 0; nt < 8; nt++) {
            const int j0 = jt * 64 + nt * 8 + 2 * t4;
            const float mk0 = mk[nt * 8 + 2 * t4];
            const float mk1 = mk[nt * 8 + 2 * t4 + 1];
            float s0 = S[nt][0] * SCALE + rel_s[irow0 - j0 + (MAXSEQ - 1)];
            float s1 = S[nt][1] * SCALE + rel_s[irow0 - j0 - 1 + (MAXSEQ - 1)];
            float s2 = S[nt][2] * SCALE + rel_s[irow1 - j0 + (MAXSEQ - 1)];
            float s3 = S[nt][3] * SCALE + rel_s[irow1 - j0 - 1 + (MAXSEQ - 1)];
            if (mi0 * mk0 < 0.5f) s0 = -1e9f;
            if (mi0 * mk1 < 0.5f) s1 = -1e9f;
            if (mi1 * mk0 < 0.5f) s2 = -1e9f;
            if (mi1 * mk1 < 0.5f) s3 = -1e9f;
            S[nt][0] = s0; S[nt][1] = s1; S[nt][2] = s2; S[nt][3] = s3;
            tmax0 = fmaxf(tmax0, fmaxf(s0, s1));
            tmax1 = fmaxf(tmax1, fmaxf(s2, s3));
        }
        tmax0 = fmaxf(tmax0, __shfl_xor_sync(0xffffffffu, tmax0, 1));
        tmax0 = fmaxf(tmax0, __shfl_xor_sync(0xffffffffu, tmax0, 2));
        tmax1 = fmaxf(tmax1, __shfl_xor_sync(0xffffffffu, tmax1, 1));
        tmax1 = fmaxf(tmax1, __shfl_xor_sync(0xffffffffu, tmax1, 2));

        const float mn0 = fmaxf(m0, tmax0);
        const float mn1 = fmaxf(m1, tmax1);
        const float sc0 = exp2f((m0 - mn0) * L2E);
        const float sc1 = exp2f((m1 - mn1) * L2E);
        m0 = mn0; m1 = mn1;

        float ts0 = 0.0f, ts1 = 0.0f;
        #pragma unroll
        for (int nt = 0; nt < 8; nt++) {
            S[nt][0] = exp2f((S[nt][0] - mn0) * L2E);
            S[nt][1] = exp2f((S[nt][1] - mn0) * L2E);
            S[nt][2] = exp2f((S[nt][2] - mn1) * L2E);
            S[nt][3] = exp2f((S[nt][3] - mn1) * L2E);
            ts0 += S[nt][0] + S[nt][1];
            ts1 += S[nt][2] + S[nt][3];
        }
        ts0 += __shfl_xor_sync(0xffffffffu, ts0, 1);
        ts0 += __shfl_xor_sync(0xffffffffu, ts0, 2);
        ts1 += __shfl_xor_sync(0xffffffffu, ts1, 1);
        ts1 += __shfl_xor_sync(0xffffffffu, ts1, 2);
        l0 = l0 * sc0 + ts0;
        l1 = l1 * sc1 + ts1;

        #pragma unroll
        for (int nt = 0; nt < 8; nt++) {
            Oc[nt][0] *= sc0; Oc[nt][1] *= sc0;
            Oc[nt][2] *= sc1; Oc[nt][3] *= sc1;
        }

        #pragma unroll
        for (int kt = 0; kt < 8; kt++) {
            const int srcA = 4 * g + (t4 >> 1);
            const int srcB = srcA + 2;
            const bool odd = (t4 & 1);
            float v0 = __shfl_sync(0xffffffffu, S[kt][0], srcA);
            float v1 = __shfl_sync(0xffffffffu, S[kt][1], srcA);
            float v2 = __shfl_sync(0xffffffffu, S[kt][2], srcA);
            float v3 = __shfl_sync(0xffffffffu, S[kt][3], srcA);
            float u0 = __shfl_sync(0xffffffffu, S[kt][0], srcB);
            float u1 = __shfl_sync(0xffffffffu, S[kt][1], srcB);
            float u2 = __shfl_sync(0xffffffffu, S[kt][2], srcB);
            float u3 = __shfl_sync(0xffffffffu, S[kt][3], srcB);
            uint32_t a[4];
            a[0] = f2tf(odd ? v1 : v0);
            a[1] = f2tf(odd ? v3 : v2);
            a[2] = f2tf(odd ? u1 : u0);
            a[3] = f2tf(odd ? u3 : u2);
            #pragma unroll
            for (int nt2 = 0; nt2 < 8; nt2++) {
                uint32_t bf[2];
                bf[0] = Vs[(kt * 8 + t4) * VST + nt2 * 8 + g];
                bf[1] = Vs[(kt * 8 + t4 + 4) * VST + nt2 * 8 + g];
                mma_tf32(Oc[nt2], a, bf);
            }
        }
        __syncthreads();
    }

    // writeback ctx = O / l, tf32-rounded (feeds proj GEMM)
    const float inv0 = 1.0f / l0;
    const float inv1 = 1.0f / l1;
    #pragma unroll
    for (int nt2 = 0; nt2 < 8; nt2++) {
        const int col = h * HDIM + nt2 * 8 + 2 * t4;
        *reinterpret_cast<float2*>(ctx + (size_t)(b * NSEQ + irow0) * BDIM + col) =
            make_float2(f2tff(Oc[nt2][0] * inv0), f2tff(Oc[nt2][1] * inv0));
        *reinterpret_cast<float2*>(ctx + (size_t)(b * NSEQ + irow1) * BDIM + col) =
            make_float2(f2tff(Oc[nt2][2] * inv1), f2tff(Oc[nt2][3] * inv1));
    }
}

// ---------------- launch ----------------
extern "C" void kernel_launch(void* const* d_in, const int* in_sizes, int n_in,
                              void* d_out, int out_size)
{
    const float* x      = (const float*)d_in[0];
    const int*   mask   = (const int*)  d_in[1];
    const float* ln1_g  = (const float*)d_in[2];
    const float* ln1_b  = (const float*)d_in[3];
    const float* qkv_w  = (const float*)d_in[4];
    const float* qkv_b  = (const float*)d_in[5];
    const float* proj_w = (const float*)d_in[6];
    const float* proj_b = (const float*)d_in[7];
    const float* rel    = (const float*)d_in[8];
    const float* ln2_g  = (const float*)d_in[9];
    const float* ln2_b  = (const float*)d_in[10];
    const float* w1     = (const float*)d_in[11];
    const float* b1     = (const float*)d_in[12];
    const float* w2     = (const float*)d_in[13];
    const float* b2     = (const float*)d_in[14];
    const float* gate1  = (const float*)d_in[15];
    const float* gate2  = (const float*)d_in[16];
    float* out = (float*)d_out;

    float *xn, *qkv, *ctx, *y, *mlp, *qkvw, *projw, *w1t, *w2t;
    cudaGetSymbolAddress((void**)&xn,    g_xn);
    cudaGetSymbolAddress((void**)&qkv,   g_qkv);
    cudaGetSymbolAddress((void**)&ctx,   g_ctx);
    cudaGetSymbolAddress((void**)&y,     g_y);
    cudaGetSymbolAddress((void**)&mlp,   g_mlp);
    cudaGetSymbolAddress((void**)&qkvw,  g_qkvw);
    cudaGetSymbolAddress((void**)&projw, g_projw);
    cudaGetSymbolAddress((void**)&w1t,   g_w1);
    cudaGetSymbolAddress((void**)&w2t,   g_w2);

    static bool attr_set = false;
    if (!attr_set) {
        cudaFuncSetAttribute(tf32gemm_kernel<EPI_BIAS>,
                             cudaFuncAttributeMaxDynamicSharedMemorySize, GEMM_SMEM);
        cudaFuncSetAttribute(tf32gemm_kernel<EPI_GELU>,
                             cudaFuncAttributeMaxDynamicSharedMemorySize, GEMM_SMEM);
        cudaFuncSetAttribute(tf32gemm_kernel<EPI_RESGATE>,
                             cudaFuncAttributeMaxDynamicSharedMemorySize, GEMM_SMEM);
        attr_set = true;
    }

    // 0) round all weights to tf32 (single launch)
    cvt_all_kernel<<<N4_TOT / 256, 256>>>(qkv_w, qkvw, proj_w, projw, w1, w1t, w2, w2t);

    // 1) LN1 (tf32-rounded output)
    ln_kernel<<<ROWS, 256>>>(x, ln1_g, ln1_b, xn);
    // 2) qkv = xn @ qkvw + qkv_b
    tf32gemm_kernel<EPI_BIAS><<<dim3(3 * BDIM / 128, ROWS / 128), 256, GEMM_SMEM>>>(
        xn, qkvw, qkv_b, nullptr, nullptr, qkv, ROWS, 3 * BDIM, BDIM);
    // 3) fused attention -> ctx (tf32-rounded)
    flash_attn_kernel<<<dim3(NSEQ / 128, NB * NHEADS), 256>>>(qkv, mask, rel, ctx);
    // 4) y = x + gate1 * (ctx @ projw + proj_b)
    tf32gemm_kernel<EPI_RESGATE><<<dim3(BDIM / 128, ROWS / 128), 256, GEMM_SMEM>>>(
        ctx, projw, proj_b, x, gate1, y, ROWS, BDIM, BDIM);
    // 5) LN2 (tf32-rounded output)
    ln_kernel<<<ROWS, 256>>>(y, ln2_g, ln2_b, xn);
    // 6) mlp = gelu(xn @ w1t + b1) (tf32-rounded)
    tf32gemm_kernel<EPI_GELU><<<dim3(4 * BDIM / 128, ROWS / 128), 256, GEMM_SMEM>>>(
        xn, w1t, b1, nullptr, nullptr, mlp, ROWS, 4 * BDIM, BDIM);
    // 7) out = y + gate2 * (mlp @ w2t + b2)
    tf32gemm_kernel<EPI_RESGATE><<<dim3(BDIM / 128, ROWS / 128), 256, GEMM_SMEM>>>(
        mlp, w2t, b2, y, gate2, out, ROWS, BDIM, 4 * BDIM);
}

// round 6
// speedup vs baseline: 3.5778x; 1.0700x over previous
#include <cuda_runtime.h>
#include <math.h>
#include <stdint.h>

#define BDIM 1024
#define NB 4
#define NSEQ 1024
#define NHEADS 16
#define HDIM 64
#define ROWS (NB*NSEQ)   // 4096
#define MAXSEQ 1024

// ---------------- scratch (device globals; no allocation allowed) ----------------
__device__ float g_xn[(size_t)ROWS*BDIM];               // 16 MB
__device__ float g_qkv[(size_t)ROWS*3*BDIM];            // 48 MB
__device__ float g_ctx[(size_t)ROWS*BDIM];              // 16 MB
__device__ float g_y[(size_t)ROWS*BDIM];                // 16 MB
__device__ float g_mlp[(size_t)ROWS*4*BDIM];            // 64 MB
// tf32-rounded weights
__device__ float g_qkvw[(size_t)BDIM*3*BDIM];           // 12 MB
__device__ float g_projw[(size_t)BDIM*BDIM];            // 4 MB
__device__ float g_w1[(size_t)BDIM*4*BDIM];             // 16 MB
__device__ float g_w2[(size_t)4*BDIM*BDIM];             // 16 MB

// ---------------- helpers ----------------
__device__ __forceinline__ uint32_t f2tf(float x) {
    uint32_t r;
    asm("cvt.rna.tf32.f32 %0, %1;" : "=r"(r) : "f"(x));
    return r;
}
__device__ __forceinline__ float f2tff(float x) { return __uint_as_float(f2tf(x)); }

__device__ __forceinline__ void mma_tf32(float c[4], const uint32_t a[4], const uint32_t b[2]) {
    asm volatile(
        "mma.sync.aligned.m16n8k8.row.col.f32.tf32.tf32.f32 "
        "{%0,%1,%2,%3}, {%4,%5,%6,%7}, {%8,%9}, {%0,%1,%2,%3};"
        : "+f"(c[0]), "+f"(c[1]), "+f"(c[2]), "+f"(c[3])
        : "r"(a[0]), "r"(a[1]), "r"(a[2]), "r"(a[3]), "r"(b[0]), "r"(b[1]));
}

__device__ __forceinline__ void cp_async16(uint32_t smem_addr, const void* gptr) {
    asm volatile("cp.async.cg.shared.global [%0], [%1], 16;"
                 :: "r"(smem_addr), "l"(gptr));
}
__device__ __forceinline__ void cp_commit() { asm volatile("cp.async.commit_group;"); }
template<int N>
__device__ __forceinline__ void cp_wait() { asm volatile("cp.async.wait_group %0;" :: "n"(N)); }

// ---------------- merged weight -> tf32 rounding (single launch) ----------------
#define N4_QKV  (BDIM*3*BDIM/4)
#define N4_PROJ (BDIM*BDIM/4)
#define N4_W1   (BDIM*4*BDIM/4)
#define N4_W2   (4*BDIM*BDIM/4)
#define N4_TOT  (N4_QKV+N4_PROJ+N4_W1+N4_W2)

__global__ __launch_bounds__(256) void cvt_all_kernel(
    const float* __restrict__ i0, float* __restrict__ o0,
    const float* __restrict__ i1, float* __restrict__ o1,
    const float* __restrict__ i2, float* __restrict__ o2,
    const float* __restrict__ i3, float* __restrict__ o3)
{
    int i = blockIdx.x * 256 + threadIdx.x;
    const float4* in;
    float4* out;
    if (i < N4_QKV) { in = (const float4*)i0; out = (float4*)o0; }
    else if (i < N4_QKV + N4_PROJ) { i -= N4_QKV; in = (const float4*)i1; out = (float4*)o1; }
    else if (i < N4_QKV + N4_PROJ + N4_W1) { i -= N4_QKV + N4_PROJ; in = (const float4*)i2; out = (float4*)o2; }
    else { i -= N4_QKV + N4_PROJ + N4_W1; in = (const float4*)i3; out = (float4*)o3; }
    float4 v = in[i];
    v.x = f2tff(v.x); v.y = f2tff(v.y); v.z = f2tff(v.z); v.w = f2tff(v.w);
    out[i] = v;
}

// ---------------- LayerNorm: one block per row; output tf32-rounded ----------------
__global__ __launch_bounds__(256) void ln_kernel(const float* __restrict__ x,
    const float* __restrict__ g, const float* __restrict__ b, float* __restrict__ out)
{
    __shared__ float red[256];
    const int row = blockIdx.x;
    const int t = threadIdx.x;
    const float4* xr = reinterpret_cast<const float4*>(x + (size_t)row * BDIM);
    float4 v = xr[t];
    float s = v.x + v.y + v.z + v.w;
    red[t] = s; __syncthreads();
    #pragma unroll
    for (int o = 128; o > 0; o >>= 1) { if (t < o) red[t] += red[t + o]; __syncthreads(); }
    const float mu = red[0] * (1.0f / BDIM);
    __syncthreads();
    float dx = v.x - mu, dy = v.y - mu, dz = v.z - mu, dw = v.w - mu;
    red[t] = dx*dx + dy*dy + dz*dz + dw*dw; __syncthreads();
    #pragma unroll
    for (int o = 128; o > 0; o >>= 1) { if (t < o) red[t] += red[t + o]; __syncthreads(); }
    const float var = red[0] * (1.0f / BDIM);
    const float rinv = rsqrtf(var + 1e-5f);
    float4 gg = reinterpret_cast<const float4*>(g)[t];
    float4 bb = reinterpret_cast<const float4*>(b)[t];
    float4 o4;
    o4.x = f2tff(dx * rinv * gg.x + bb.x);
    o4.y = f2tff(dy * rinv * gg.y + bb.y);
    o4.z = f2tff(dz * rinv * gg.z + bb.z);
    o4.w = f2tff(dw * rinv * gg.w + bb.w);
    reinterpret_cast<float4*>(out + (size_t)row * BDIM)[t] = o4;
}

// ---------------- 3-stage cp.async TF32 GEMM, BK=32 (inputs pre-rounded) ----------------
// k-slot bijection: lane t4 carries logical k = {k0+2*t4, k0+2*t4+1} in its
// (lo, hi) mma slots — A pair is smem-adjacent (1x LDS.64), B rows chosen to match.
enum { EPI_BIAS = 0, EPI_GELU = 1, EPI_RESGATE = 2 };

#define GSTAGES 3
#define G_AST 40                 // conflict-free LDS.64 on A pairs (banks 8g+2t4)
#define G_BST 132                // conflict-free B frag under remap (banks 8t4+g)
#define G_ASW (128*G_AST)        // 5120 words / stage
#define G_BSW (32*G_BST)         // 4224 words / stage
#define GEMM_SMEM (GSTAGES*(G_ASW+G_BSW)*4)   // 112128 bytes

template<int EPI>
__global__ __launch_bounds__(256, 2) void tf32gemm_kernel(
    const float* __restrict__ A, const float* __restrict__ B,
    const float* __restrict__ bias, const float* __restrict__ res,
    const float* __restrict__ gate, float* __restrict__ C,
    int M, int N, int K)
{
    constexpr int BM = 128, BN = 128, BK = 32;
    extern __shared__ uint32_t sm[];
    uint32_t* As = sm;
    uint32_t* Bs = sm + GSTAGES * G_ASW;
    const uint32_t As_u = (uint32_t)__cvta_generic_to_shared(As);
    const uint32_t Bs_u = (uint32_t)__cvta_generic_to_shared(Bs);

    const int tid  = threadIdx.x;
    const int lane = tid & 31;
    const int wid  = tid >> 5;
    const int g    = lane >> 2;
    const int t4   = lane & 3;
    const int mWarp = (wid >> 2) * 64;
    const int nWarp = (wid & 3) * 32;

    const int aRow = tid >> 3;             // 0..31 (+32r)
    const int aCol = (tid & 7) * 4;
    const int bRow = tid >> 5;             // 0..7 (+8s)
    const int bCol = (tid & 31) * 4;

    const float* Ap = A + (size_t)(blockIdx.y * BM + aRow) * K + aCol;
    const float* Bp = B + (size_t)bRow * N + blockIdx.x * BN + bCol;
    const uint32_t aDst = As_u + (uint32_t)(aRow * G_AST + aCol) * 4;
    const uint32_t bDst = Bs_u + (uint32_t)(bRow * G_BST + bCol) * 4;

    const int nT = K / BK;

    #pragma unroll
    for (int t = 0; t < GSTAGES - 1; t++) {
        const uint32_t so = (uint32_t)(t * G_ASW) * 4;
        const uint32_t sb = (uint32_t)(t * G_BSW) * 4;
        const float* ap = Ap + (size_t)t * BK;
        const float* bp = Bp + (size_t)(t * BK) * N;
        #pragma unroll
        for (int r = 0; r < 4; r++)
            cp_async16(aDst + so + (uint32_t)(r * 32 * G_AST) * 4, ap + (size_t)(r * 32) * K);
        #pragma unroll
        for (int s = 0; s < 4; s++)
            cp_async16(bDst + sb + (uint32_t)(s * 8 * G_BST) * 4, bp + (size_t)(s * 8) * N);
        cp_commit();
    }

    float acc[4][4][4] = {};

    int slot = 0;
    for (int t = 0; t < nT; t++) {
        cp_wait<GSTAGES - 2>();
        __syncthreads();

        const int tn = t + GSTAGES - 1;
        if (tn < nT) {
            const int slotn = (slot + GSTAGES - 1) >= GSTAGES ? slot - 1 : slot + GSTAGES - 1;
            const uint32_t so = (uint32_t)(slotn * G_ASW) * 4;
            const uint32_t sb = (uint32_t)(slotn * G_BSW) * 4;
            const float* ap = Ap + (size_t)tn * BK;
            const float* bp = Bp + (size_t)(tn * BK) * N;
            #pragma unroll
            for (int r = 0; r < 4; r++)
                cp_async16(aDst + so + (uint32_t)(r * 32 * G_AST) * 4, ap + (size_t)(r * 32) * K);
            #pragma unroll
            for (int s = 0; s < 4; s++)
                cp_async16(bDst + sb + (uint32_t)(s * 8 * G_BST) * 4, bp + (size_t)(s * 8) * N);
        }
        cp_commit();

        const uint32_t* Ass = As + slot * G_ASW;
        const uint32_t* Bss = Bs + slot * G_BSW;
        #pragma unroll
        for (int ks = 0; ks < 4; ks++) {
            const int k0 = ks * 8;
            const int kA = k0 + 2 * t4;           // this lane's logical k pair (kA, kA+1)
            uint32_t bf[4][2];
            #pragma unroll
            for (int ni = 0; ni < 4; ni++) {
                const int nb = nWarp + ni * 8;
                bf[ni][0] = Bss[kA * G_BST + nb + g];
                bf[ni][1] = Bss[(kA + 1) * G_BST + nb + g];
            }
            #pragma unroll
            for (int mi = 0; mi < 4; mi++) {
                const int mb = mWarp + mi * 16;
                uint2 a0 = *reinterpret_cast<const uint2*>(&Ass[(mb + g) * G_AST + kA]);
                uint2 a1 = *reinterpret_cast<const uint2*>(&Ass[(mb + g + 8) * G_AST + kA]);
                uint32_t af[4] = { a0.x, a1.x, a0.y, a1.y };
                #pragma unroll
                for (int ni = 0; ni < 4; ni++)
                    mma_tf32(acc[mi][ni], af, bf[ni]);
            }
        }
        slot = (slot + 1 == GSTAGES) ? 0 : slot + 1;
    }

    // epilogue
    const float gt = (EPI == EPI_RESGATE) ? gate[0] : 0.0f;
    #pragma unroll
    for (int mi = 0; mi < 4; mi++) {
        const int row0 = blockIdx.y * BM + mWarp + mi * 16 + g;
        #pragma unroll
        for (int ni = 0; ni < 4; ni++) {
            const int col = blockIdx.x * BN + nWarp + ni * 8 + t4 * 2;
            const float b0 = bias[col], b1 = bias[col + 1];
            #pragma unroll
            for (int h = 0; h < 2; h++) {
                const int row = row0 + h * 8;
                float v0 = acc[mi][ni][2 * h + 0] + b0;
                float v1 = acc[mi][ni][2 * h + 1] + b1;
                if (EPI == EPI_BIAS) {            // qkv GEMM: pre-round q/k/v for flash
                    v0 = f2tff(v0);
                    v1 = f2tff(v1);
                }
                if (EPI == EPI_GELU) {
                    v0 = f2tff(0.5f * v0 * (1.0f + erff(v0 * 0.70710678118654752f)));
                    v1 = f2tff(0.5f * v1 * (1.0f + erff(v1 * 0.70710678118654752f)));
                }
                if (EPI == EPI_RESGATE) {
                    const size_t off = (size_t)row * N + col;
                    v0 = res[off] + gt * v0;
                    v1 = res[off + 1] + gt * v1;
                }
                *reinterpret_cast<float2*>(C + (size_t)row * N + col) = make_float2(v0, v1);
            }
        }
    }
}

// ---------------- Fused flash attention (TF32; q/k/v pre-rounded in gmem) ----------------
__global__ __launch_bounds__(256, 2) void flash_attn_kernel(
    const float* __restrict__ qkv, const int* __restrict__ mask,
    const float* __restrict__ rel, float* __restrict__ ctx)
{
    constexpr int KST = 72;   // banks 8g+2t4 -> LDS.64 conflict-free
    constexpr int VST = 72;   // banks 8t4+g  -> LDS.32 conflict-free
    constexpr float SCALE = 0.125f;
    constexpr float L2E = 1.4426950408889634f;

    // Ks[64][72] | Vs[64][72] | mk[64] | rel_s[2047]; Qst[128][72] overlays Ks+Vs (9216 words)
    __shared__ __align__(16) uint32_t smbuf[64*KST + 64*VST + 64 + 2048];
    uint32_t* Ks = smbuf;
    uint32_t* Vs = smbuf + 64*KST;
    float* mk    = reinterpret_cast<float*>(smbuf + 64*KST + 64*VST);
    float* rel_s = mk + 64;
    uint32_t* Qst = smbuf;  // [128][KST] = 9216 words == Ks+Vs region exactly

    const int bh = blockIdx.y;
    const int b = bh >> 4, h = bh & 15;
    const int i0 = blockIdx.x * 128;
    const int tid = threadIdx.x, lane = tid & 31, w = tid >> 5;
    const int g = lane >> 2, t4 = lane & 3;

    for (int idx = tid; idx < 2 * MAXSEQ - 1; idx += 256)
        rel_s[idx] = rel[(size_t)idx * NHEADS + h];

    // stage Q tile 128x64 (values already tf32 in gmem)
    {
        const int r = tid >> 1;
        const int c0 = (tid & 1) * 32;
        const float* qp = qkv + ((size_t)(b * NSEQ + i0 + r)) * (3 * BDIM) + h * HDIM + c0;
        #pragma unroll
        for (int i = 0; i < 8; i++)
            *reinterpret_cast<uint4*>(&Qst[r * KST + c0 + 4 * i]) =
                *reinterpret_cast<const uint4*>(qp + 4 * i);
    }
    __syncthreads();

    // Q a-fragments (k-slot bijection: lane t4 -> logical k {2t4, 2t4+1})
    uint32_t Qa[8][4];
    #pragma unroll
    for (int kt = 0; kt < 8; kt++) {
        uint2 q0 = *reinterpret_cast<const uint2*>(&Qst[(w * 16 + g) * KST + kt * 8 + 2 * t4]);
        uint2 q1 = *reinterpret_cast<const uint2*>(&Qst[(w * 16 + g + 8) * KST + kt * 8 + 2 * t4]);
        Qa[kt][0] = q0.x; Qa[kt][1] = q1.x; Qa[kt][2] = q0.y; Qa[kt][3] = q1.y;
    }
    __syncthreads();

    const int irow0 = i0 + w * 16 + g;
    const int irow1 = irow0 + 8;
    const float mi0 = (float)mask[b * NSEQ + irow0];
    const float mi1 = (float)mask[b * NSEQ + irow1];

    float m0 = -INFINITY, m1 = -INFINITY, l0 = 0.0f, l1 = 0.0f;
    float Oc[8][4] = {};

    for (int jt = 0; jt < NSEQ / 64; jt++) {
        // load K, V tiles (plain copies — already tf32 bits)
        {
            const int r = tid >> 2, q4 = (tid & 3) * 16;
            const float* kp = qkv + ((size_t)(b * NSEQ + jt * 64 + r)) * (3 * BDIM) + BDIM + h * HDIM + q4;
            #pragma unroll
            for (int i = 0; i < 4; i++) {
                *reinterpret_cast<uint4*>(&Ks[r * KST + q4 + 4 * i]) =
                    *reinterpret_cast<const uint4*>(kp + 4 * i);
                *reinterpret_cast<uint4*>(&Vs[r * VST + q4 + 4 * i]) =
                    *reinterpret_cast<const uint4*>(kp + BDIM + 4 * i);
            }
            if (tid < 64) mk[tid] = (float)mask[b * NSEQ + jt * 64 + tid];
        }
        __syncthreads();

        // S = Q @ K^T ; K b-fragment pair is adjacent -> single LDS.64
        float S[8][4] = {};
        #pragma unroll
        for (int nt = 0; nt < 8; nt++) {
            #pragma unroll
            for (int kt = 0; kt < 8; kt++) {
                uint2 kk = *reinterpret_cast<const uint2*>(&Ks[(nt * 8 + g) * KST + kt * 8 + 2 * t4]);
                uint32_t bf[2] = { kk.x, kk.y };
                mma_tf32(S[nt], Qa[kt], bf);
            }
        }

        float tmax0 = -INFINITY, tmax1 = -INFINITY;
        #pragma unroll
        for (int nt = 0; nt < 8; nt++) {
            const int j0 = jt * 64 + nt * 8 + 2 * t4;
            const float mk0 = mk[nt * 8 + 2 * t4];
            const float mk1 = mk[nt * 8 + 2 * t4 + 1];
            float s0 = S[nt][0] * SCALE + rel_s[irow0 - j0 + (MAXSEQ - 1)];
            float s1 = S[nt][1] * SCALE + rel_s[irow0 - j0 - 1 + (MAXSEQ - 1)];
            float s2 = S[nt][2] * SCALE + rel_s[irow1 - j0 + (MAXSEQ - 1)];
            float s3 = S[nt][3] * SCALE + rel_s[irow1 - j0 - 1 + (MAXSEQ - 1)];
            if (mi0 * mk0 < 0.5f) s0 = -1e9f;
            if (mi0 * mk1 < 0.5f) s1 = -1e9f;
            if (mi1 * mk0 < 0.5f) s2 = -1e9f;
            if (mi1 * mk1 < 0.5f) s3 = -1e9f;
            S[nt][0] = s0; S[nt][1] = s1; S[nt][2] = s2; S[nt][3] = s3;
            tmax0 = fmaxf(tmax0, fmaxf(s0, s1));
            tmax1 = fmaxf(tmax1, fmaxf(s2, s3));
        }
        tmax0 = fmaxf(tmax0, __shfl_xor_sync(0xffffffffu, tmax0, 1));
        tmax0 = fmaxf(tmax0, __shfl_xor_sync(0xffffffffu, tmax0, 2));
        tmax1 = fmaxf(tmax1, __shfl_xor_sync(0xffffffffu, tmax1, 1));
        tmax1 = fmaxf(tmax1, __shfl_xor_sync(0xffffffffu, tmax1, 2));

        const float mn0 = fmaxf(m0, tmax0);
        const float mn1 = fmaxf(m1, tmax1);
        const float sc0 = exp2f((m0 - mn0) * L2E);
        const float sc1 = exp2f((m1 - mn1) * L2E);
        m0 = mn0; m1 = mn1;

        float ts0 = 0.0f, ts1 = 0.0f;
        #pragma unroll
        for (int nt = 0; nt < 8; nt++) {
            S[nt][0] = exp2f((S[nt][0] - mn0) * L2E);
            S[nt][1] = exp2f((S[nt][1] - mn0) * L2E);
            S[nt][2] = exp2f((S[nt][2] - mn1) * L2E);
            S[nt][3] = exp2f((S[nt][3] - mn1) * L2E);
            ts0 += S[nt][0] + S[nt][1];
            ts1 += S[nt][2] + S[nt][3];
        }
        ts0 += __shfl_xor_sync(0xffffffffu, ts0, 1);
        ts0 += __shfl_xor_sync(0xffffffffu, ts0, 2);
        ts1 += __shfl_xor_sync(0xffffffffu, ts1, 1);
        ts1 += __shfl_xor_sync(0xffffffffu, ts1, 2);
        l0 = l0 * sc0 + ts0;
        l1 = l1 * sc1 + ts1;

        #pragma unroll
        for (int nt = 0; nt < 8; nt++) {
            Oc[nt][0] *= sc0; Oc[nt][1] *= sc0;
            Oc[nt][2] *= sc1; Oc[nt][3] *= sc1;
        }

        // O += P @ V (permute c-frag -> a-frag via shfl)
        #pragma unroll
        for (int kt = 0; kt < 8; kt++) {
            const int srcA = 4 * g + (t4 >> 1);
            const int srcB = srcA + 2;
            const bool odd = (t4 & 1);
            float v0 = __shfl_sync(0xffffffffu, S[kt][0], srcA);
            float v1 = __shfl_sync(0xffffffffu, S[kt][1], srcA);
            float v2 = __shfl_sync(0xffffffffu, S[kt][2], srcA);
            float v3 = __shfl_sync(0xffffffffu, S[kt][3], srcA);
            float u0 = __shfl_sync(0xffffffffu, S[kt][0], srcB);
            float u1 = __shfl_sync(0xffffffffu, S[kt][1], srcB);
            float u2 = __shfl_sync(0xffffffffu, S[kt][2], srcB);
            float u3 = __shfl_sync(0xffffffffu, S[kt][3], srcB);
            uint32_t a[4];
            a[0] = f2tf(odd ? v1 : v0);
            a[1] = f2tf(odd ? v3 : v2);
            a[2] = f2tf(odd ? u1 : u0);
            a[3] = f2tf(odd ? u3 : u2);
            #pragma unroll
            for (int nt2 = 0; nt2 < 8; nt2++) {
                uint32_t bf[2];
                bf[0] = Vs[(kt * 8 + t4) * VST + nt2 * 8 + g];
                bf[1] = Vs[(kt * 8 + t4 + 4) * VST + nt2 * 8 + g];
                mma_tf32(Oc[nt2], a, bf);
            }
        }
        __syncthreads();
    }

    // writeback ctx = O / l, tf32-rounded (feeds proj GEMM)
    const float inv0 = 1.0f / l0;
    const float inv1 = 1.0f / l1;
    #pragma unroll
    for (int nt2 = 0; nt2 < 8; nt2++) {
        const int col = h * HDIM + nt2 * 8 + 2 * t4;
        *reinterpret_cast<float2*>(ctx + (size_t)(b * NSEQ + irow0) * BDIM + col) =
            make_float2(f2tff(Oc[nt2][0] * inv0), f2tff(Oc[nt2][1] * inv0));
        *reinterpret_cast<float2*>(ctx + (size_t)(b * NSEQ + irow1) * BDIM + col) =
            make_float2(f2tff(Oc[nt2][2] * inv1), f2tff(Oc[nt2][3] * inv1));
    }
}

// ---------------- launch ----------------
extern "C" void kernel_launch(void* const* d_in, const int* in_sizes, int n_in,
                              void* d_out, int out_size)
{
    const float* x      = (const float*)d_in[0];
    const int*   mask   = (const int*)  d_in[1];
    const float* ln1_g  = (const float*)d_in[2];
    const float* ln1_b  = (const float*)d_in[3];
    const float* qkv_w  = (const float*)d_in[4];
    const float* qkv_b  = (const float*)d_in[5];
    const float* proj_w = (const float*)d_in[6];
    const float* proj_b = (const float*)d_in[7];
    const float* rel    = (const float*)d_in[8];
    const float* ln2_g  = (const float*)d_in[9];
    const float* ln2_b  = (const float*)d_in[10];
    const float* w1     = (const float*)d_in[11];
    const float* b1     = (const float*)d_in[12];
    const float* w2     = (const float*)d_in[13];
    const float* b2     = (const float*)d_in[14];
    const float* gate1  = (const float*)d_in[15];
    const float* gate2  = (const float*)d_in[16];
    float* out = (float*)d_out;

    float *xn, *qkv, *ctx, *y, *mlp, *qkvw, *projw, *w1t, *w2t;
    cudaGetSymbolAddress((void**)&xn,    g_xn);
    cudaGetSymbolAddress((void**)&qkv,   g_qkv);
    cudaGetSymbolAddress((void**)&ctx,   g_ctx);
    cudaGetSymbolAddress((void**)&y,     g_y);
    cudaGetSymbolAddress((void**)&mlp,   g_mlp);
    cudaGetSymbolAddress((void**)&qkvw,  g_qkvw);
    cudaGetSymbolAddress((void**)&projw, g_projw);
    cudaGetSymbolAddress((void**)&w1t,   g_w1);
    cudaGetSymbolAddress((void**)&w2t,   g_w2);

    static bool attr_set = false;
    if (!attr_set) {
        cudaFuncSetAttribute(tf32gemm_kernel<EPI_BIAS>,
                             cudaFuncAttributeMaxDynamicSharedMemorySize, GEMM_SMEM);
        cudaFuncSetAttribute(tf32gemm_kernel<EPI_GELU>,
                             cudaFuncAttributeMaxDynamicSharedMemorySize, GEMM_SMEM);
        cudaFuncSetAttribute(tf32gemm_kernel<EPI_RESGATE>,
                             cudaFuncAttributeMaxDynamicSharedMemorySize, GEMM_SMEM);
        attr_set = true;
    }

    // 0) round all weights to tf32 (single launch)
    cvt_all_kernel<<<N4_TOT / 256, 256>>>(qkv_w, qkvw, proj_w, projw, w1, w1t, w2, w2t);

    // 1) LN1 (tf32-rounded output)
    ln_kernel<<<ROWS, 256>>>(x, ln1_g, ln1_b, xn);
    // 2) qkv = xn @ qkvw + qkv_b (output tf32-rounded for flash)
    tf32gemm_kernel<EPI_BIAS><<<dim3(3 * BDIM / 128, ROWS / 128), 256, GEMM_SMEM>>>(
        xn, qkvw, qkv_b, nullptr, nullptr, qkv, ROWS, 3 * BDIM, BDIM);
    // 3) fused attention -> ctx (tf32-rounded)
    flash_attn_kernel<<<dim3(NSEQ / 128, NB * NHEADS), 256>>>(qkv, mask, rel, ctx);
    // 4) y = x + gate1 * (ctx @ projw + proj_b)
    tf32gemm_kernel<EPI_RESGATE><<<dim3(BDIM / 128, ROWS / 128), 256, GEMM_SMEM>>>(
        ctx, projw, proj_b, x, gate1, y, ROWS, BDIM, BDIM);
    // 5) LN2 (tf32-rounded output)
    ln_kernel<<<ROWS, 256>>>(y, ln2_g, ln2_b, xn);
    // 6) mlp = gelu(xn @ w1t + b1) (tf32-rounded)
    tf32gemm_kernel<EPI_GELU><<<dim3(4 * BDIM / 128, ROWS / 128), 256, GEMM_SMEM>>>(
        xn, w1t, b1, nullptr, nullptr, mlp, ROWS, 4 * BDIM, BDIM);
    // 7) out = y + gate2 * (mlp @ w2t + b2)
    tf32gemm_kernel<EPI_RESGATE><<<dim3(BDIM / 128, ROWS / 128), 256, GEMM_SMEM>>>(
        mlp, w2t, b2, y, gate2, out, ROWS, BDIM, 4 * BDIM);
}

// round 7
// speedup vs baseline: 3.6480x; 1.0196x over previous
#include <cuda_runtime.h>
#include <math.h>
#include <stdint.h>

#define BDIM 1024
#define NB 4
#define NSEQ 1024
#define NHEADS 16
#define HDIM 64
#define ROWS (NB*NSEQ)   // 4096
#define MAXSEQ 1024

// ---------------- scratch (device globals; no allocation allowed) ----------------
__device__ float g_xn[(size_t)ROWS*BDIM];               // 16 MB
__device__ float g_qkv[(size_t)ROWS*3*BDIM];            // 48 MB
__device__ float g_ctx[(size_t)ROWS*BDIM];              // 16 MB
__device__ float g_y[(size_t)ROWS*BDIM];                // 16 MB
__device__ float g_mlp[(size_t)ROWS*4*BDIM];            // 64 MB
// tf32-rounded weights
__device__ float g_qkvw[(size_t)BDIM*3*BDIM];           // 12 MB
__device__ float g_projw[(size_t)BDIM*BDIM];            // 4 MB
__device__ float g_w1[(size_t)BDIM*4*BDIM];             // 16 MB
__device__ float g_w2[(size_t)4*BDIM*BDIM];             // 16 MB

// ---------------- helpers ----------------
__device__ __forceinline__ uint32_t f2tf(float x) {
    uint32_t r;
    asm("cvt.rna.tf32.f32 %0, %1;" : "=r"(r) : "f"(x));
    return r;
}
__device__ __forceinline__ float f2tff(float x) { return __uint_as_float(f2tf(x)); }

__device__ __forceinline__ void mma_tf32(float c[4], const uint32_t a[4], const uint32_t b[2]) {
    asm volatile(
        "mma.sync.aligned.m16n8k8.row.col.f32.tf32.tf32.f32 "
        "{%0,%1,%2,%3}, {%4,%5,%6,%7}, {%8,%9}, {%0,%1,%2,%3};"
        : "+f"(c[0]), "+f"(c[1]), "+f"(c[2]), "+f"(c[3])
        : "r"(a[0]), "r"(a[1]), "r"(a[2]), "r"(a[3]), "r"(b[0]), "r"(b[1]));
}

__device__ __forceinline__ void cp_async16(uint32_t smem_addr, const void* gptr) {
    asm volatile("cp.async.cg.shared.global [%0], [%1], 16;"
                 :: "r"(smem_addr), "l"(gptr));
}
__device__ __forceinline__ void cp_commit() { asm volatile("cp.async.commit_group;"); }
template<int N>
__device__ __forceinline__ void cp_wait() { asm volatile("cp.async.wait_group %0;" :: "n"(N)); }

// ---------------- merged weight -> tf32 rounding (single launch) ----------------
#define N4_QKV  (BDIM*3*BDIM/4)
#define N4_PROJ (BDIM*BDIM/4)
#define N4_W1   (BDIM*4*BDIM/4)
#define N4_W2   (4*BDIM*BDIM/4)
#define N4_TOT  (N4_QKV+N4_PROJ+N4_W1+N4_W2)

__global__ __launch_bounds__(256) void cvt_all_kernel(
    const float* __restrict__ i0, float* __restrict__ o0,
    const float* __restrict__ i1, float* __restrict__ o1,
    const float* __restrict__ i2, float* __restrict__ o2,
    const float* __restrict__ i3, float* __restrict__ o3)
{
    int i = blockIdx.x * 256 + threadIdx.x;
    const float4* in;
    float4* out;
    if (i < N4_QKV) { in = (const float4*)i0; out = (float4*)o0; }
    else if (i < N4_QKV + N4_PROJ) { i -= N4_QKV; in = (const float4*)i1; out = (float4*)o1; }
    else if (i < N4_QKV + N4_PROJ + N4_W1) { i -= N4_QKV + N4_PROJ; in = (const float4*)i2; out = (float4*)o2; }
    else { i -= N4_QKV + N4_PROJ + N4_W1; in = (const float4*)i3; out = (float4*)o3; }
    float4 v = in[i];
    v.x = f2tff(v.x); v.y = f2tff(v.y); v.z = f2tff(v.z); v.w = f2tff(v.w);
    out[i] = v;
}

// ---------------- LayerNorm: warp per row (no smem, no barriers) ----------------
__global__ __launch_bounds__(256) void ln_kernel(const float* __restrict__ x,
    const float* __restrict__ g, const float* __restrict__ b, float* __restrict__ out)
{
    const int row  = blockIdx.x * 8 + (threadIdx.x >> 5);
    const int lane = threadIdx.x & 31;
    const float4* xr = reinterpret_cast<const float4*>(x + (size_t)row * BDIM);
    float4 v[8];
    float s = 0.0f;
    #pragma unroll
    for (int i = 0; i < 8; i++) {
        v[i] = xr[lane + 32 * i];
        s += v[i].x + v[i].y + v[i].z + v[i].w;
    }
    #pragma unroll
    for (int o = 16; o > 0; o >>= 1) s += __shfl_xor_sync(0xffffffffu, s, o);
    const float mu = s * (1.0f / BDIM);
    float q = 0.0f;
    #pragma unroll
    for (int i = 0; i < 8; i++) {
        v[i].x -= mu; v[i].y -= mu; v[i].z -= mu; v[i].w -= mu;
        q += v[i].x*v[i].x + v[i].y*v[i].y + v[i].z*v[i].z + v[i].w*v[i].w;
    }
    #pragma unroll
    for (int o = 16; o > 0; o >>= 1) q += __shfl_xor_sync(0xffffffffu, q, o);
    const float rinv = rsqrtf(q * (1.0f / BDIM) + 1e-5f);
    float4* orow = reinterpret_cast<float4*>(out + (size_t)row * BDIM);
    #pragma unroll
    for (int i = 0; i < 8; i++) {
        float4 gg = reinterpret_cast<const float4*>(g)[lane + 32 * i];
        float4 bb = reinterpret_cast<const float4*>(b)[lane + 32 * i];
        float4 o4;
        o4.x = f2tff(v[i].x * rinv * gg.x + bb.x);
        o4.y = f2tff(v[i].y * rinv * gg.y + bb.y);
        o4.z = f2tff(v[i].z * rinv * gg.z + bb.z);
        o4.w = f2tff(v[i].w * rinv * gg.w + bb.w);
        orow[lane + 32 * i] = o4;
    }
}

// ---------------- 3-stage cp.async TF32 GEMM, BK=32 (inputs pre-rounded) ----------------
enum { EPI_BIAS = 0, EPI_GELU = 1, EPI_RESGATE = 2 };

#define GSTAGES 3
#define G_AST 40
#define G_BST 132
#define G_ASW (128*G_AST)
#define G_BSW (32*G_BST)
#define GEMM_SMEM (GSTAGES*(G_ASW+G_BSW)*4)   // 112128 bytes

template<int EPI>
__global__ __launch_bounds__(256, 2) void tf32gemm_kernel(
    const float* __restrict__ A, const float* __restrict__ B,
    const float* __restrict__ bias, const float* __restrict__ res,
    const float* __restrict__ gate, float* __restrict__ C,
    int M, int N, int K)
{
    constexpr int BM = 128, BN = 128, BK = 32;
    extern __shared__ uint32_t sm[];
    uint32_t* As = sm;
    uint32_t* Bs = sm + GSTAGES * G_ASW;
    const uint32_t As_u = (uint32_t)__cvta_generic_to_shared(As);
    const uint32_t Bs_u = (uint32_t)__cvta_generic_to_shared(Bs);

    const int tid  = threadIdx.x;
    const int lane = tid & 31;
    const int wid  = tid >> 5;
    const int g    = lane >> 2;
    const int t4   = lane & 3;
    const int mWarp = (wid >> 2) * 64;
    const int nWarp = (wid & 3) * 32;

    const int aRow = tid >> 3;
    const int aCol = (tid & 7) * 4;
    const int bRow = tid >> 5;
    const int bCol = (tid & 31) * 4;

    const float* Ap = A + (size_t)(blockIdx.y * BM + aRow) * K + aCol;
    const float* Bp = B + (size_t)bRow * N + blockIdx.x * BN + bCol;
    const uint32_t aDst = As_u + (uint32_t)(aRow * G_AST + aCol) * 4;
    const uint32_t bDst = Bs_u + (uint32_t)(bRow * G_BST + bCol) * 4;

    const int nT = K / BK;

    #pragma unroll
    for (int t = 0; t < GSTAGES - 1; t++) {
        const uint32_t so = (uint32_t)(t * G_ASW) * 4;
        const uint32_t sb = (uint32_t)(t * G_BSW) * 4;
        const float* ap = Ap + (size_t)t * BK;
        const float* bp = Bp + (size_t)(t * BK) * N;
        #pragma unroll
        for (int r = 0; r < 4; r++)
            cp_async16(aDst + so + (uint32_t)(r * 32 * G_AST) * 4, ap + (size_t)(r * 32) * K);
        #pragma unroll
        for (int s = 0; s < 4; s++)
            cp_async16(bDst + sb + (uint32_t)(s * 8 * G_BST) * 4, bp + (size_t)(s * 8) * N);
        cp_commit();
    }

    float acc[4][4][4] = {};

    int slot = 0;
    for (int t = 0; t < nT; t++) {
        cp_wait<GSTAGES - 2>();
        __syncthreads();

        const int tn = t + GSTAGES - 1;
        if (tn < nT) {
            const int slotn = (slot + GSTAGES - 1) >= GSTAGES ? slot - 1 : slot + GSTAGES - 1;
            const uint32_t so = (uint32_t)(slotn * G_ASW) * 4;
            const uint32_t sb = (uint32_t)(slotn * G_BSW) * 4;
            const float* ap = Ap + (size_t)tn * BK;
            const float* bp = Bp + (size_t)(tn * BK) * N;
            #pragma unroll
            for (int r = 0; r < 4; r++)
                cp_async16(aDst + so + (uint32_t)(r * 32 * G_AST) * 4, ap + (size_t)(r * 32) * K);
            #pragma unroll
            for (int s = 0; s < 4; s++)
                cp_async16(bDst + sb + (uint32_t)(s * 8 * G_BST) * 4, bp + (size_t)(s * 8) * N);
        }
        cp_commit();

        const uint32_t* Ass = As + slot * G_ASW;
        const uint32_t* Bss = Bs + slot * G_BSW;
        #pragma unroll
        for (int ks = 0; ks < 4; ks++) {
            const int kA = ks * 8 + 2 * t4;
            uint32_t bf[4][2];
            #pragma unroll
            for (int ni = 0; ni < 4; ni++) {
                const int nb = nWarp + ni * 8;
                bf[ni][0] = Bss[kA * G_BST + nb + g];
                bf[ni][1] = Bss[(kA + 1) * G_BST + nb + g];
            }
            #pragma unroll
            for (int mi = 0; mi < 4; mi++) {
                const int mb = mWarp + mi * 16;
                uint2 a0 = *reinterpret_cast<const uint2*>(&Ass[(mb + g) * G_AST + kA]);
                uint2 a1 = *reinterpret_cast<const uint2*>(&Ass[(mb + g + 8) * G_AST + kA]);
                uint32_t af[4] = { a0.x, a1.x, a0.y, a1.y };
                #pragma unroll
                for (int ni = 0; ni < 4; ni++)
                    mma_tf32(acc[mi][ni], af, bf[ni]);
            }
        }
        slot = (slot + 1 == GSTAGES) ? 0 : slot + 1;
    }

    const float gt = (EPI == EPI_RESGATE) ? gate[0] : 0.0f;
    #pragma unroll
    for (int mi = 0; mi < 4; mi++) {
        const int row0 = blockIdx.y * BM + mWarp + mi * 16 + g;
        #pragma unroll
        for (int ni = 0; ni < 4; ni++) {
            const int col = blockIdx.x * BN + nWarp + ni * 8 + t4 * 2;
            const float b0 = bias[col], b1 = bias[col + 1];
            #pragma unroll
            for (int h = 0; h < 2; h++) {
                const int row = row0 + h * 8;
                float v0 = acc[mi][ni][2 * h + 0] + b0;
                float v1 = acc[mi][ni][2 * h + 1] + b1;
                if (EPI == EPI_BIAS) {
                    v0 = f2tff(v0);
                    v1 = f2tff(v1);
                }
                if (EPI == EPI_GELU) {
                    v0 = f2tff(0.5f * v0 * (1.0f + erff(v0 * 0.70710678118654752f)));
                    v1 = f2tff(0.5f * v1 * (1.0f + erff(v1 * 0.70710678118654752f)));
                }
                if (EPI == EPI_RESGATE) {
                    const size_t off = (size_t)row * N + col;
                    v0 = res[off] + gt * v0;
                    v1 = res[off + 1] + gt * v1;
                }
                *reinterpret_cast<float2*>(C + (size_t)row * N + col) = make_float2(v0, v1);
            }
        }
    }
}

// ---------------- Fused flash attention (TF32; O^T formulation, no P permute) ----------------
__global__ __launch_bounds__(256, 2) void flash_attn_kernel(
    const float* __restrict__ qkv, const int* __restrict__ mask,
    const float* __restrict__ rel, float* __restrict__ ctx)
{
    constexpr int KST = 72;   // K: LDS.64 pairs, banks 8g+2t4 -> conflict-free
    constexpr int VST = 76;   // V^T a-frag reads: banks 24t4+g -> conflict-free
    constexpr float SCALE = 0.125f;
    constexpr float L2E = 1.4426950408889634f;

    // Ks[64][72] | Vs[64][76] | mk[64] | rel_s[2047]; Qst[128][72]=9216 overlays Ks+Vs (9472)
    __shared__ __align__(16) uint32_t smbuf[64*KST + 64*VST + 64 + 2048];
    uint32_t* Ks = smbuf;
    uint32_t* Vs = smbuf + 64*KST;
    float* mk    = reinterpret_cast<float*>(smbuf + 64*KST + 64*VST);
    float* rel_s = mk + 64;
    uint32_t* Qst = smbuf;

    const int bh = blockIdx.y;
    const int b = bh >> 4, h = bh & 15;
    const int i0 = blockIdx.x * 128;
    const int tid = threadIdx.x, lane = tid & 31, w = tid >> 5;
    const int g = lane >> 2, t4 = lane & 3;

    for (int idx = tid; idx < 2 * MAXSEQ - 1; idx += 256)
        rel_s[idx] = rel[(size_t)idx * NHEADS + h];

    // stage Q tile 128x64 (already tf32 bits in gmem)
    {
        const int r = tid >> 1;
        const int c0 = (tid & 1) * 32;
        const float* qp = qkv + ((size_t)(b * NSEQ + i0 + r)) * (3 * BDIM) + h * HDIM + c0;
        #pragma unroll
        for (int i = 0; i < 8; i++)
            *reinterpret_cast<uint4*>(&Qst[r * KST + c0 + 4 * i]) =
                *reinterpret_cast<const uint4*>(qp + 4 * i);
    }
    __syncthreads();

    // Q a-fragments (k-slot bijection: lane t4 -> logical k {2t4, 2t4+1})
    uint32_t Qa[8][4];
    #pragma unroll
    for (int kt = 0; kt < 8; kt++) {
        uint2 q0 = *reinterpret_cast<const uint2*>(&Qst[(w * 16 + g) * KST + kt * 8 + 2 * t4]);
        uint2 q1 = *reinterpret_cast<const uint2*>(&Qst[(w * 16 + g + 8) * KST + kt * 8 + 2 * t4]);
        Qa[kt][0] = q0.x; Qa[kt][1] = q1.x; Qa[kt][2] = q0.y; Qa[kt][3] = q1.y;
    }
    __syncthreads();

    const int irow0 = i0 + w * 16 + g;
    const int irow1 = irow0 + 8;
    const float mi0 = (float)mask[b * NSEQ + irow0];
    const float mi1 = (float)mask[b * NSEQ + irow1];

    float m0 = -INFINITY, m1 = -INFINITY, l0 = 0.0f, l1 = 0.0f;
    // O^T accumulators: OcT[mi][ni] = c-frag rows d=mi*16+g(+8), cols i=ni*8+2t4(+1)
    float OcT[4][2][4] = {};

    for (int jt = 0; jt < NSEQ / 64; jt++) {
        // load K (row-major) and V (row-major j x d, stride VST)
        {
            const int r = tid >> 2, q4 = (tid & 3) * 16;
            const float* kp = qkv + ((size_t)(b * NSEQ + jt * 64 + r)) * (3 * BDIM) + BDIM + h * HDIM + q4;
            #pragma unroll
            for (int i = 0; i < 4; i++) {
                *reinterpret_cast<uint4*>(&Ks[r * KST + q4 + 4 * i]) =
                    *reinterpret_cast<const uint4*>(kp + 4 * i);
                *reinterpret_cast<uint4*>(&Vs[r * VST + q4 + 4 * i]) =
                    *reinterpret_cast<const uint4*>(kp + BDIM + 4 * i);
            }
            if (tid < 64) mk[tid] = (float)mask[b * NSEQ + jt * 64 + tid];
        }
        __syncthreads();

        // S = Q @ K^T
        float S[8][4] = {};
        #pragma unroll
        for (int nt = 0; nt < 8; nt++) {
            #pragma unroll
            for (int kt = 0; kt < 8; kt++) {
                uint2 kk = *reinterpret_cast<const uint2*>(&Ks[(nt * 8 + g) * KST + kt * 8 + 2 * t4]);
                uint32_t bf[2] = { kk.x, kk.y };
                mma_tf32(S[nt], Qa[kt], bf);
            }
        }

        // scale + rel bias + mask; row max
        float tmax0 = -INFINITY, tmax1 = -INFINITY;
        #pragma unroll
        for (int nt = 0; nt < 8; nt++) {
            const int j0 = jt * 64 + nt * 8 + 2 * t4;
            const float mk0 = mk[nt * 8 + 2 * t4];
            const float mk1 = mk[nt * 8 + 2 * t4 + 1];
            float s0 = S[nt][0] * SCALE + rel_s[irow0 - j0 + (MAXSEQ - 1)];
            float s1 = S[nt][1] * SCALE + rel_s[irow0 - j0 - 1 + (MAXSEQ - 1)];
            float s2 = S[nt][2] * SCALE + rel_s[irow1 - j0 + (MAXSEQ - 1)];
            float s3 = S[nt][3] * SCALE + rel_s[irow1 - j0 - 1 + (MAXSEQ - 1)];
            if (mi0 * mk0 < 0.5f) s0 = -1e9f;
            if (mi0 * mk1 < 0.5f) s1 = -1e9f;
            if (mi1 * mk0 < 0.5f) s2 = -1e9f;
            if (mi1 * mk1 < 0.5f) s3 = -1e9f;
            S[nt][0] = s0; S[nt][1] = s1; S[nt][2] = s2; S[nt][3] = s3;
            tmax0 = fmaxf(tmax0, fmaxf(s0, s1));
            tmax1 = fmaxf(tmax1, fmaxf(s2, s3));
        }
        tmax0 = fmaxf(tmax0, __shfl_xor_sync(0xffffffffu, tmax0, 1));
        tmax0 = fmaxf(tmax0, __shfl_xor_sync(0xffffffffu, tmax0, 2));
        tmax1 = fmaxf(tmax1, __shfl_xor_sync(0xffffffffu, tmax1, 1));
        tmax1 = fmaxf(tmax1, __shfl_xor_sync(0xffffffffu, tmax1, 2));

        const float mn0 = fmaxf(m0, tmax0);
        const float mn1 = fmaxf(m1, tmax1);
        const float sc0 = exp2f((m0 - mn0) * L2E);
        const float sc1 = exp2f((m1 - mn1) * L2E);
        m0 = mn0; m1 = mn1;

        float ts0 = 0.0f, ts1 = 0.0f;
        #pragma unroll
        for (int nt = 0; nt < 8; nt++) {
            S[nt][0] = exp2f((S[nt][0] - mn0) * L2E);
            S[nt][1] = exp2f((S[nt][1] - mn0) * L2E);
            S[nt][2] = exp2f((S[nt][2] - mn1) * L2E);
            S[nt][3] = exp2f((S[nt][3] - mn1) * L2E);
            ts0 += S[nt][0] + S[nt][1];
            ts1 += S[nt][2] + S[nt][3];
        }
        ts0 += __shfl_xor_sync(0xffffffffu, ts0, 1);
        ts0 += __shfl_xor_sync(0xffffffffu, ts0, 2);
        ts1 += __shfl_xor_sync(0xffffffffu, ts1, 1);
        ts1 += __shfl_xor_sync(0xffffffffu, ts1, 2);
        l0 = l0 * sc0 + ts0;
        l1 = l1 * sc1 + ts1;

        // broadcast per-i rescale factors: rows 2t4, 2t4+1 (sc0 set), 8+2t4, 8+2t4+1 (sc1 set)
        const float scA = __shfl_sync(0xffffffffu, sc0, 8 * t4);
        const float scB = __shfl_sync(0xffffffffu, sc0, 8 * t4 + 4);
        const float scC = __shfl_sync(0xffffffffu, sc1, 8 * t4);
        const float scD = __shfl_sync(0xffffffffu, sc1, 8 * t4 + 4);
        #pragma unroll
        for (int mi = 0; mi < 4; mi++) {
            OcT[mi][0][0] *= scA; OcT[mi][0][1] *= scB;
            OcT[mi][0][2] *= scA; OcT[mi][0][3] *= scB;
            OcT[mi][1][0] *= scC; OcT[mi][1][1] *= scD;
            OcT[mi][1][2] *= scC; OcT[mi][1][3] *= scD;
        }

        // O^T += V^T @ P^T : b-frag = S regs directly (bijection), a-frag = Vs transposed reads
        #pragma unroll
        for (int kt = 0; kt < 8; kt++) {
            uint32_t b0t[2] = { f2tf(S[kt][0]), f2tf(S[kt][1]) };   // n-tile 0: i rows 0..7 (i=g)
            uint32_t b1t[2] = { f2tf(S[kt][2]), f2tf(S[kt][3]) };   // n-tile 1: i rows 8..15
            const uint32_t* vr0 = &Vs[(kt * 8 + 2 * t4) * VST];
            const uint32_t* vr1 = vr0 + VST;
            #pragma unroll
            for (int mi = 0; mi < 4; mi++) {
                const int d0 = mi * 16 + g;
                uint32_t a[4];
                a[0] = vr0[d0];
                a[1] = vr0[d0 + 8];
                a[2] = vr1[d0];
                a[3] = vr1[d0 + 8];
                mma_tf32(OcT[mi][0], a, b0t);
                mma_tf32(OcT[mi][1], a, b1t);
            }
        }
        __syncthreads();
    }

    // writeback ctx = O / l (O^T c-frag scatter), tf32-rounded
    const float inv0 = 1.0f / l0;
    const float inv1 = 1.0f / l1;
    const float iA = __shfl_sync(0xffffffffu, inv0, 8 * t4);
    const float iB = __shfl_sync(0xffffffffu, inv0, 8 * t4 + 4);
    const float iC = __shfl_sync(0xffffffffu, inv1, 8 * t4);
    const float iD = __shfl_sync(0xffffffffu, inv1, 8 * t4 + 4);
    #pragma unroll
    for (int mi = 0; mi < 4; mi++) {
        const int col = h * HDIM + mi * 16 + g;
        #pragma unroll
        for (int ni = 0; ni < 2; ni++) {
            const int r0 = i0 + w * 16 + ni * 8 + 2 * t4;
            const float f0 = ni ? iC : iA;
            const float f1 = ni ? iD : iB;
            float* c0 = ctx + (size_t)(b * NSEQ + r0) * BDIM + col;
            float* c1 = ctx + (size_t)(b * NSEQ + r0 + 1) * BDIM + col;
            c0[0] = f2tff(OcT[mi][ni][0] * f0);
            c1[0] = f2tff(OcT[mi][ni][1] * f1);
            c0[8] = f2tff(OcT[mi][ni][2] * f0);
            c1[8] = f2tff(OcT[mi][ni][3] * f1);
        }
    }
}

// ---------------- launch ----------------
extern "C" void kernel_launch(void* const* d_in, const int* in_sizes, int n_in,
                              void* d_out, int out_size)
{
    const float* x      = (const float*)d_in[0];
    const int*   mask   = (const int*)  d_in[1];
    const float* ln1_g  = (const float*)d_in[2];
    const float* ln1_b  = (const float*)d_in[3];
    const float* qkv_w  = (const float*)d_in[4];
    const float* qkv_b  = (const float*)d_in[5];
    const float* proj_w = (const float*)d_in[6];
    const float* proj_b = (const float*)d_in[7];
    const float* rel    = (const float*)d_in[8];
    const float* ln2_g  = (const float*)d_in[9];
    const float* ln2_b  = (const float*)d_in[10];
    const float* w1     = (const float*)d_in[11];
    const float* b1     = (const float*)d_in[12];
    const float* w2     = (const float*)d_in[13];
    const float* b2     = (const float*)d_in[14];
    const float* gate1  = (const float*)d_in[15];
    const float* gate2  = (const float*)d_in[16];
    float* out = (float*)d_out;

    float *xn, *qkv, *ctx, *y, *mlp, *qkvw, *projw, *w1t, *w2t;
    cudaGetSymbolAddress((void**)&xn,    g_xn);
    cudaGetSymbolAddress((void**)&qkv,   g_qkv);
    cudaGetSymbolAddress((void**)&ctx,   g_ctx);
    cudaGetSymbolAddress((void**)&y,     g_y);
    cudaGetSymbolAddress((void**)&mlp,   g_mlp);
    cudaGetSymbolAddress((void**)&qkvw,  g_qkvw);
    cudaGetSymbolAddress((void**)&projw, g_projw);
    cudaGetSymbolAddress((void**)&w1t,   g_w1);
    cudaGetSymbolAddress((void**)&w2t,   g_w2);

    static bool attr_set = false;
    if (!attr_set) {
        cudaFuncSetAttribute(tf32gemm_kernel<EPI_BIAS>,
                             cudaFuncAttributeMaxDynamicSharedMemorySize, GEMM_SMEM);
        cudaFuncSetAttribute(tf32gemm_kernel<EPI_GELU>,
                             cudaFuncAttributeMaxDynamicSharedMemorySize, GEMM_SMEM);
        cudaFuncSetAttribute(tf32gemm_kernel<EPI_RESGATE>,
                             cudaFuncAttributeMaxDynamicSharedMemorySize, GEMM_SMEM);
        attr_set = true;
    }

    // 0) round all weights to tf32 (single launch)
    cvt_all_kernel<<<N4_TOT / 256, 256>>>(qkv_w, qkvw, proj_w, projw, w1, w1t, w2, w2t);

    // 1) LN1 (tf32-rounded output)
    ln_kernel<<<ROWS / 8, 256>>>(x, ln1_g, ln1_b, xn);
    // 2) qkv = xn @ qkvw + qkv_b (output tf32-rounded for flash)
    tf32gemm_kernel<EPI_BIAS><<<dim3(3 * BDIM / 128, ROWS / 128), 256, GEMM_SMEM>>>(
        xn, qkvw, qkv_b, nullptr, nullptr, qkv, ROWS, 3 * BDIM, BDIM);
    // 3) fused attention -> ctx (tf32-rounded)
    flash_attn_kernel<<<dim3(NSEQ / 128, NB * NHEADS), 256>>>(qkv, mask, rel, ctx);
    // 4) y = x + gate1 * (ctx @ projw + proj_b)
    tf32gemm_kernel<EPI_RESGATE><<<dim3(BDIM / 128, ROWS / 128), 256, GEMM_SMEM>>>(
        ctx, projw, proj_b, x, gate1, y, ROWS, BDIM, BDIM);
    // 5) LN2 (tf32-rounded output)
    ln_kernel<<<ROWS / 8, 256>>>(y, ln2_g, ln2_b, xn);
    // 6) mlp = gelu(xn @ w1t + b1) (tf32-rounded)
    tf32gemm_kernel<EPI_GELU><<<dim3(4 * BDIM / 128, ROWS / 128), 256, GEMM_SMEM>>>(
        xn, w1t, b1, nullptr, nullptr, mlp, ROWS, 4 * BDIM, BDIM);
    // 7) out = y + gate2 * (mlp @ w2t + b2)
    tf32gemm_kernel<EPI_RESGATE><<<dim3(BDIM / 128, ROWS / 128), 256, GEMM_SMEM>>>(
        mlp, w2t, b2, y, gate2, out, ROWS, BDIM, 4 * BDIM);
}

// round 9
// speedup vs baseline: 3.7072x; 1.0162x over previous
#include <cuda_runtime.h>
#include <math.h>
#include <stdint.h>

#define BDIM 1024
#define NB 4
#define NSEQ 1024
#define NHEADS 16
#define HDIM 64
#define ROWS (NB*NSEQ)   // 4096
#define MAXSEQ 1024

// ---------------- scratch (device globals; no allocation allowed) ----------------
__device__ float g_xn[(size_t)ROWS*BDIM];               // 16 MB
__device__ float g_qkv[(size_t)ROWS*3*BDIM];            // 48 MB
__device__ float g_ctx[(size_t)ROWS*BDIM];              // 16 MB
__device__ float g_y[(size_t)ROWS*BDIM];                // 16 MB
__device__ float g_mlp[(size_t)ROWS*4*BDIM];            // 64 MB
// tf32-rounded weights
__device__ float g_qkvw[(size_t)BDIM*3*BDIM];           // 12 MB
__device__ float g_projw[(size_t)BDIM*BDIM];            // 4 MB
__device__ float g_w1[(size_t)BDIM*4*BDIM];             // 16 MB
__device__ float g_w2[(size_t)4*BDIM*BDIM];             // 16 MB

// ---------------- helpers ----------------
__device__ __forceinline__ uint32_t f2tf(float x) {
    uint32_t r;
    asm("cvt.rna.tf32.f32 %0, %1;" : "=r"(r) : "f"(x));
    return r;
}
__device__ __forceinline__ float f2tff(float x) { return __uint_as_float(f2tf(x)); }

__device__ __forceinline__ void mma_tf32(float c[4], const uint32_t a[4], const uint32_t b[2]) {
    asm volatile(
        "mma.sync.aligned.m16n8k8.row.col.f32.tf32.tf32.f32 "
        "{%0,%1,%2,%3}, {%4,%5,%6,%7}, {%8,%9}, {%0,%1,%2,%3};"
        : "+f"(c[0]), "+f"(c[1]), "+f"(c[2]), "+f"(c[3])
        : "r"(a[0]), "r"(a[1]), "r"(a[2]), "r"(a[3]), "r"(b[0]), "r"(b[1]));
}

__device__ __forceinline__ void cp_async16(uint32_t smem_addr, const void* gptr) {
    asm volatile("cp.async.cg.shared.global [%0], [%1], 16;"
                 :: "r"(smem_addr), "l"(gptr));
}
__device__ __forceinline__ void cp_commit() { asm volatile("cp.async.commit_group;"); }
template<int N>
__device__ __forceinline__ void cp_wait() { asm volatile("cp.async.wait_group %0;" :: "n"(N)); }

// ---------------- merged weight -> tf32 rounding (single launch) ----------------
#define N4_QKV  (BDIM*3*BDIM/4)
#define N4_PROJ (BDIM*BDIM/4)
#define N4_W1   (BDIM*4*BDIM/4)
#define N4_W2   (4*BDIM*BDIM/4)
#define N4_TOT  (N4_QKV+N4_PROJ+N4_W1+N4_W2)

__global__ __launch_bounds__(256) void cvt_all_kernel(
    const float* __restrict__ i0, float* __restrict__ o0,
    const float* __restrict__ i1, float* __restrict__ o1,
    const float* __restrict__ i2, float* __restrict__ o2,
    const float* __restrict__ i3, float* __restrict__ o3)
{
    int i = blockIdx.x * 256 + threadIdx.x;
    const float4* in;
    float4* out;
    if (i < N4_QKV) { in = (const float4*)i0; out = (float4*)o0; }
    else if (i < N4_QKV + N4_PROJ) { i -= N4_QKV; in = (const float4*)i1; out = (float4*)o1; }
    else if (i < N4_QKV + N4_PROJ + N4_W1) { i -= N4_QKV + N4_PROJ; in = (const float4*)i2; out = (float4*)o2; }
    else { i -= N4_QKV + N4_PROJ + N4_W1; in = (const float4*)i3; out = (float4*)o3; }
    float4 v = in[i];
    v.x = f2tff(v.x); v.y = f2tff(v.y); v.z = f2tff(v.z); v.w = f2tff(v.w);
    out[i] = v;
}

// ---------------- LayerNorm: warp per row (no smem, no barriers) ----------------
__global__ __launch_bounds__(256) void ln_kernel(const float* __restrict__ x,
    const float* __restrict__ g, const float* __restrict__ b, float* __restrict__ out)
{
    const int row  = blockIdx.x * 8 + (threadIdx.x >> 5);
    const int lane = threadIdx.x & 31;
    const float4* xr = reinterpret_cast<const float4*>(x + (size_t)row * BDIM);
    float4 v[8];
    float s = 0.0f;
    #pragma unroll
    for (int i = 0; i < 8; i++) {
        v[i] = xr[lane + 32 * i];
        s += v[i].x + v[i].y + v[i].z + v[i].w;
    }
    #pragma unroll
    for (int o = 16; o > 0; o >>= 1) s += __shfl_xor_sync(0xffffffffu, s, o);
    const float mu = s * (1.0f / BDIM);
    float q = 0.0f;
    #pragma unroll
    for (int i = 0; i < 8; i++) {
        v[i].x -= mu; v[i].y -= mu; v[i].z -= mu; v[i].w -= mu;
        q += v[i].x*v[i].x + v[i].y*v[i].y + v[i].z*v[i].z + v[i].w*v[i].w;
    }
    #pragma unroll
    for (int o = 16; o > 0; o >>= 1) q += __shfl_xor_sync(0xffffffffu, q, o);
    const float rinv = rsqrtf(q * (1.0f / BDIM) + 1e-5f);
    float4* orow = reinterpret_cast<float4*>(out + (size_t)row * BDIM);
    #pragma unroll
    for (int i = 0; i < 8; i++) {
        float4 gg = reinterpret_cast<const float4*>(g)[lane + 32 * i];
        float4 bb = reinterpret_cast<const float4*>(b)[lane + 32 * i];
        float4 o4;
        o4.x = f2tff(v[i].x * rinv * gg.x + bb.x);
        o4.y = f2tff(v[i].y * rinv * gg.y + bb.y);
        o4.z = f2tff(v[i].z * rinv * gg.z + bb.z);
        o4.w = f2tff(v[i].w * rinv * gg.w + bb.w);
        orow[lane + 32 * i] = o4;
    }
}

// ---------------- 3-stage cp.async TF32 GEMM, BK=32 (inputs pre-rounded) ----------------
enum { EPI_BIAS = 0, EPI_GELU = 1, EPI_RESGATE = 2 };

#define GSTAGES 3
#define G_AST 40
#define G_BST 132
#define G_ASW (128*G_AST)
#define G_BSW (32*G_BST)
#define GEMM_SMEM (GSTAGES*(G_ASW+G_BSW)*4)   // 112128 bytes

template<int EPI>
__global__ __launch_bounds__(256, 2) void tf32gemm_kernel(
    const float* __restrict__ A, const float* __restrict__ B,
    const float* __restrict__ bias, const float* __restrict__ res,
    const float* __restrict__ gate, float* __restrict__ C,
    int M, int N, int K)
{
    constexpr int BM = 128, BN = 128, BK = 32;
    extern __shared__ uint32_t sm[];
    uint32_t* As = sm;
    uint32_t* Bs = sm + GSTAGES * G_ASW;
    const uint32_t As_u = (uint32_t)__cvta_generic_to_shared(As);
    const uint32_t Bs_u = (uint32_t)__cvta_generic_to_shared(Bs);

    const int tid  = threadIdx.x;
    const int lane = tid & 31;
    const int wid  = tid >> 5;
    const int g    = lane >> 2;
    const int t4   = lane & 3;
    const int mWarp = (wid >> 2) * 64;
    const int nWarp = (wid & 3) * 32;

    const int aRow = tid >> 3;
    const int aCol = (tid & 7) * 4;
    const int bRow = tid >> 5;
    const int bCol = (tid & 31) * 4;

    const float* Ap = A + (size_t)(blockIdx.y * BM + aRow) * K + aCol;
    const float* Bp = B + (size_t)bRow * N + blockIdx.x * BN + bCol;
    const uint32_t aDst = As_u + (uint32_t)(aRow * G_AST + aCol) * 4;
    const uint32_t bDst = Bs_u + (uint32_t)(bRow * G_BST + bCol) * 4;

    const int nT = K / BK;

    #pragma unroll
    for (int t = 0; t < GSTAGES - 1; t++) {
        const uint32_t so = (uint32_t)(t * G_ASW) * 4;
        const uint32_t sb = (uint32_t)(t * G_BSW) * 4;
        const float* ap = Ap + (size_t)t * BK;
        const float* bp = Bp + (size_t)(t * BK) * N;
        #pragma unroll
        for (int r = 0; r < 4; r++)
            cp_async16(aDst + so + (uint32_t)(r * 32 * G_AST) * 4, ap + (size_t)(r * 32) * K);
        #pragma unroll
        for (int s = 0; s < 4; s++)
            cp_async16(bDst + sb + (uint32_t)(s * 8 * G_BST) * 4, bp + (size_t)(s * 8) * N);
        cp_commit();
    }

    float acc[4][4][4] = {};

    int slot = 0;
    for (int t = 0; t < nT; t++) {
        cp_wait<GSTAGES - 2>();
        __syncthreads();

        const int tn = t + GSTAGES - 1;
        if (tn < nT) {
            const int slotn = (slot + GSTAGES - 1) >= GSTAGES ? slot - 1 : slot + GSTAGES - 1;
            const uint32_t so = (uint32_t)(slotn * G_ASW) * 4;
            const uint32_t sb = (uint32_t)(slotn * G_BSW) * 4;
            const float* ap = Ap + (size_t)tn * BK;
            const float* bp = Bp + (size_t)(tn * BK) * N;
            #pragma unroll
            for (int r = 0; r < 4; r++)
                cp_async16(aDst + so + (uint32_t)(r * 32 * G_AST) * 4, ap + (size_t)(r * 32) * K);
            #pragma unroll
            for (int s = 0; s < 4; s++)
                cp_async16(bDst + sb + (uint32_t)(s * 8 * G_BST) * 4, bp + (size_t)(s * 8) * N);
        }
        cp_commit();

        const uint32_t* Ass = As + slot * G_ASW;
        const uint32_t* Bss = Bs + slot * G_BSW;
        #pragma unroll
        for (int ks = 0; ks < 4; ks++) {
            const int kA = ks * 8 + 2 * t4;
            uint32_t bf[4][2];
            #pragma unroll
            for (int ni = 0; ni < 4; ni++) {
                const int nb = nWarp + ni * 8;
                bf[ni][0] = Bss[kA * G_BST + nb + g];
                bf[ni][1] = Bss[(kA + 1) * G_BST + nb + g];
            }
            #pragma unroll
            for (int mi = 0; mi < 4; mi++) {
                const int mb = mWarp + mi * 16;
                uint2 a0 = *reinterpret_cast<const uint2*>(&Ass[(mb + g) * G_AST + kA]);
                uint2 a1 = *reinterpret_cast<const uint2*>(&Ass[(mb + g + 8) * G_AST + kA]);
                uint32_t af[4] = { a0.x, a1.x, a0.y, a1.y };
                #pragma unroll
                for (int ni = 0; ni < 4; ni++)
                    mma_tf32(acc[mi][ni], af, bf[ni]);
            }
        }
        slot = (slot + 1 == GSTAGES) ? 0 : slot + 1;
    }

    const float gt = (EPI == EPI_RESGATE) ? gate[0] : 0.0f;
    #pragma unroll
    for (int mi = 0; mi < 4; mi++) {
        const int row0 = blockIdx.y * BM + mWarp + mi * 16 + g;
        #pragma unroll
        for (int ni = 0; ni < 4; ni++) {
            const int col = blockIdx.x * BN + nWarp + ni * 8 + t4 * 2;
            const float b0 = bias[col], b1 = bias[col + 1];
            #pragma unroll
            for (int h = 0; h < 2; h++) {
                const int row = row0 + h * 8;
                float v0 = acc[mi][ni][2 * h + 0] + b0;
                float v1 = acc[mi][ni][2 * h + 1] + b1;
                if (EPI == EPI_BIAS) {
                    v0 = f2tff(v0);
                    v1 = f2tff(v1);
                }
                if (EPI == EPI_GELU) {
                    v0 = f2tff(0.5f * v0 * (1.0f + erff(v0 * 0.70710678118654752f)));
                    v1 = f2tff(0.5f * v1 * (1.0f + erff(v1 * 0.70710678118654752f)));
                }
                if (EPI == EPI_RESGATE) {
                    const size_t off = (size_t)row * N + col;
                    v0 = res[off] + gt * v0;
                    v1 = res[off + 1] + gt * v1;
                }
                *reinterpret_cast<float2*>(C + (size_t)row * N + col) = make_float2(v0, v1);
            }
        }
    }
}

// ---------------- Fused flash attention (TF32; O^T form; cp.async K/V pipeline) ----------------
#define KST 72
#define VST 76
#define FL_SLOTW (64*KST + 64*VST)               // 9472 words per KV slot
#define FL_MK    (2*FL_SLOTW)                    // 18944: mki[2][64]
#define FL_REL   (FL_MK + 128)                   // 19072: rel_s[2047]
#define FL_WORDS (FL_REL + 2048)                 // 21120 words
#define FL_SMEM  (FL_WORDS*4)                    // 84480 bytes

__global__ __launch_bounds__(256, 2) void flash_attn_kernel(
    const float* __restrict__ qkv, const int* __restrict__ mask,
    const float* __restrict__ rel, float* __restrict__ ctx)
{
    constexpr float SCALE = 0.125f;
    constexpr float L2E = 1.4426950408889634f;

    extern __shared__ __align__(16) uint32_t sm[];
    const uint32_t sm_u = (uint32_t)__cvta_generic_to_shared(sm);
    const int* mki  = reinterpret_cast<const int*>(sm + FL_MK);
    float* rel_s    = reinterpret_cast<float*>(sm + FL_REL);
    uint32_t* Qst   = sm + FL_SLOTW;   // overlays KV slot 1

    const int bh = blockIdx.y;
    const int b = bh >> 4, h = bh & 15;
    const int i0 = blockIdx.x * 128;
    const int tid = threadIdx.x, lane = tid & 31, w = tid >> 5;
    const int g = lane >> 2, t4 = lane & 3;

    // per-thread K/V load mapping
    const int ldr = tid >> 2;              // 0..63 (j row)
    const int ldc = (tid & 3) * 16;        // word col {0,16,32,48}
    const float* kvbase = qkv + (size_t)(b * NSEQ + ldr) * (3 * BDIM) + BDIM + h * HDIM + ldc;

    // prologue: prefetch tile 0 -> slot 0
    {
        const float* kp = kvbase;   // jt = 0
        const uint32_t kdst = sm_u + (uint32_t)(ldr * KST + ldc) * 4;
        const uint32_t vdst = sm_u + (uint32_t)(64 * KST + ldr * VST + ldc) * 4;
        #pragma unroll
        for (int i = 0; i < 4; i++) {
            cp_async16(kdst + 16 * i, kp + 4 * i);
            cp_async16(vdst + 16 * i, kp + BDIM + 4 * i);
        }
        if (tid < 16)
            cp_async16(sm_u + (uint32_t)(FL_MK + tid * 4) * 4, mask + b * NSEQ + tid * 4);
        cp_commit();
    }

    // rel column for this head
    for (int idx = tid; idx < 2 * MAXSEQ - 1; idx += 256)
        rel_s[idx] = rel[(size_t)idx * NHEADS + h];

    // stage Q tile 128x64 into slot-1 region (tf32 bits already in gmem)
    {
        const int r = tid >> 1;
        const int c0 = (tid & 1) * 32;
        const float* qp = qkv + ((size_t)(b * NSEQ + i0 + r)) * (3 * BDIM) + h * HDIM + c0;
        #pragma unroll
        for (int i = 0; i < 8; i++)
            *reinterpret_cast<uint4*>(&Qst[r * KST + c0 + 4 * i]) =
                *reinterpret_cast<const uint4*>(qp + 4 * i);
    }
    __syncthreads();

    // Q a-fragments (k-slot bijection: lane t4 -> logical k {2t4, 2t4+1})
    uint32_t Qa[8][4];
    #pragma unroll
    for (int kt = 0; kt < 8; kt++) {
        uint2 q0 = *reinterpret_cast<const uint2*>(&Qst[(w * 16 + g) * KST + kt * 8 + 2 * t4]);
        uint2 q1 = *reinterpret_cast<const uint2*>(&Qst[(w * 16 + g + 8) * KST + kt * 8 + 2 * t4]);
        Qa[kt][0] = q0.x; Qa[kt][1] = q1.x; Qa[kt][2] = q0.y; Qa[kt][3] = q1.y;
    }

    const int irow0 = i0 + w * 16 + g;
    const int irow1 = irow0 + 8;
    const int mi0 = mask[b * NSEQ + irow0];
    const int mi1 = mask[b * NSEQ + irow1];

    float m0 = -INFINITY, m1 = -INFINITY, l0 = 0.0f, l1 = 0.0f;
    float OcT[4][2][4] = {};

    for (int jt = 0; jt < NSEQ / 64; jt++) {
        cp_wait<0>();
        __syncthreads();   // tile jt resident in slot jt&1; also orders prior-slot reads

        // prefetch tile jt+1 -> other slot
        if (jt + 1 < NSEQ / 64) {
            const int ns = (jt + 1) & 1;
            const float* kp = kvbase + (size_t)(jt + 1) * 64 * (3 * BDIM);
            const uint32_t kdst = sm_u + (uint32_t)(ns * FL_SLOTW + ldr * KST + ldc) * 4;
            const uint32_t vdst = sm_u + (uint32_t)(ns * FL_SLOTW + 64 * KST + ldr * VST + ldc) * 4;
            #pragma unroll
            for (int i = 0; i < 4; i++) {
                cp_async16(kdst + 16 * i, kp + 4 * i);
                cp_async16(vdst + 16 * i, kp + BDIM + 4 * i);
            }
            if (tid < 16)
                cp_async16(sm_u + (uint32_t)(FL_MK + ns * 64 + tid * 4) * 4,
                           mask + b * NSEQ + (jt + 1) * 64 + tid * 4);
            cp_commit();
        }

        const int slot = jt & 1;
        const uint32_t* Ks = sm + slot * FL_SLOTW;
        const uint32_t* Vs = sm + slot * FL_SLOTW + 64 * KST;
        const int* mkp = mki + slot * 64;

        // S = Q @ K^T
        float S[8][4] = {};
        #pragma unroll
        for (int nt = 0; nt < 8; nt++) {
            #pragma unroll
            for (int kt = 0; kt < 8; kt++) {
                uint2 kk = *reinterpret_cast<const uint2*>(&Ks[(nt * 8 + g) * KST + kt * 8 + 2 * t4]);
                uint32_t bf[2] = { kk.x, kk.y };
                mma_tf32(S[nt], Qa[kt], bf);
            }
        }

        // scale + rel bias + mask; row max
        float tmax0 = -INFINITY, tmax1 = -INFINITY;
        #pragma unroll
        for (int nt = 0; nt < 8; nt++) {
            const int j0 = jt * 64 + nt * 8 + 2 * t4;
            const int mk0 = mkp[nt * 8 + 2 * t4];
            const int mk1 = mkp[nt * 8 + 2 * t4 + 1];
            float s0 = S[nt][0] * SCALE + rel_s[irow0 - j0 + (MAXSEQ - 1)];
            float s1 = S[nt][1] * SCALE + rel_s[irow0 - j0 - 1 + (MAXSEQ - 1)];
            float s2 = S[nt][2] * SCALE + rel_s[irow1 - j0 + (MAXSEQ - 1)];
            float s3 = S[nt][3] * SCALE + rel_s[irow1 - j0 - 1 + (MAXSEQ - 1)];
            if (mi0 == 0 || mk0 == 0) s0 = -1e9f;
            if (mi0 == 0 || mk1 == 0) s1 = -1e9f;
            if (mi1 == 0 || mk0 == 0) s2 = -1e9f;
            if (mi1 == 0 || mk1 == 0) s3 = -1e9f;
            S[nt][0] = s0; S[nt][1] = s1; S[nt][2] = s2; S[nt][3] = s3;
            tmax0 = fmaxf(tmax0, fmaxf(s0, s1));
            tmax1 = fmaxf(tmax1, fmaxf(s2, s3));
        }
        tmax0 = fmaxf(tmax0, __shfl_xor_sync(0xffffffffu, tmax0, 1));
        tmax0 = fmaxf(tmax0, __shfl_xor_sync(0xffffffffu, tmax0, 2));
        tmax1 = fmaxf(tmax1, __shfl_xor_sync(0xffffffffu, tmax1, 1));
        tmax1 = fmaxf(tmax1, __shfl_xor_sync(0xffffffffu, tmax1, 2));

        const float mn0 = fmaxf(m0, tmax0);
        const float mn1 = fmaxf(m1, tmax1);
        const float sc0 = exp2f((m0 - mn0) * L2E);
        const float sc1 = exp2f((m1 - mn1) * L2E);
        m0 = mn0; m1 = mn1;

        float ts0 = 0.0f, ts1 = 0.0f;
        #pragma unroll
        for (int nt = 0; nt < 8; nt++) {
            S[nt][0] = exp2f((S[nt][0] - mn0) * L2E);
            S[nt][1] = exp2f((S[nt][1] - mn0) * L2E);
            S[nt][2] = exp2f((S[nt][2] - mn1) * L2E);
            S[nt][3] = exp2f((S[nt][3] - mn1) * L2E);
            ts0 += S[nt][0] + S[nt][1];
            ts1 += S[nt][2] + S[nt][3];
        }
        ts0 += __shfl_xor_sync(0xffffffffu, ts0, 1);
        ts0 += __shfl_xor_sync(0xffffffffu, ts0, 2);
        ts1 += __shfl_xor_sync(0xffffffffu, ts1, 1);
        ts1 += __shfl_xor_sync(0xffffffffu, ts1, 2);
        l0 = l0 * sc0 + ts0;
        l1 = l1 * sc1 + ts1;

        const float scA = __shfl_sync(0xffffffffu, sc0, 8 * t4);
        const float scB = __shfl_sync(0xffffffffu, sc0, 8 * t4 + 4);
        const float scC = __shfl_sync(0xffffffffu, sc1, 8 * t4);
        const float scD = __shfl_sync(0xffffffffu, sc1, 8 * t4 + 4);
        #pragma unroll
        for (int mi = 0; mi < 4; mi++) {
            OcT[mi][0][0] *= scA; OcT[mi][0][1] *= scB;
            OcT[mi][0][2] *= scA; OcT[mi][0][3] *= scB;
            OcT[mi][1][0] *= scC; OcT[mi][1][1] *= scD;
            OcT[mi][1][2] *= scC; OcT[mi][1][3] *= scD;
        }

        // O^T += V^T @ P^T : b-frag = S regs directly, a-frag = Vs transposed reads
        #pragma unroll
        for (int kt = 0; kt < 8; kt++) {
            uint32_t b0t[2] = { f2tf(S[kt][0]), f2tf(S[kt][1]) };
            uint32_t b1t[2] = { f2tf(S[kt][2]), f2tf(S[kt][3]) };
            const uint32_t* vr0 = &Vs[(kt * 8 + 2 * t4) * VST];
            const uint32_t* vr1 = vr0 + VST;
            #pragma unroll
            for (int mi = 0; mi < 4; mi++) {
                const int d0 = mi * 16 + g;
                uint32_t a[4];
                a[0] = vr0[d0];
                a[1] = vr0[d0 + 8];
                a[2] = vr1[d0];
                a[3] = vr1[d0 + 8];
                mma_tf32(OcT[mi][0], a, b0t);
                mma_tf32(OcT[mi][1], a, b1t);
            }
        }
    }

    // writeback ctx = O / l (O^T c-frag scatter), tf32-rounded
    const float inv0 = 1.0f / l0;
    const float inv1 = 1.0f / l1;
    const float iA = __shfl_sync(0xffffffffu, inv0, 8 * t4);
    const float iB = __shfl_sync(0xffffffffu, inv0, 8 * t4 + 4);
    const float iC = __shfl_sync(0xffffffffu, inv1, 8 * t4);
    const float iD = __shfl_sync(0xffffffffu, inv1, 8 * t4 + 4);
    #pragma unroll
    for (int mi = 0; mi < 4; mi++) {
        const int col = h * HDIM + mi * 16 + g;
        #pragma unroll
        for (int ni = 0; ni < 2; ni++) {
            const int r0 = i0 + w * 16 + ni * 8 + 2 * t4;
            const float f0 = ni ? iC : iA;
            const float f1 = ni ? iD : iB;
            float* c0 = ctx + (size_t)(b * NSEQ + r0) * BDIM + col;
            float* c1 = ctx + (size_t)(b * NSEQ + r0 + 1) * BDIM + col;
            c0[0] = f2tff(OcT[mi][ni][0] * f0);
            c1[0] = f2tff(OcT[mi][ni][1] * f1);
            c0[8] = f2tff(OcT[mi][ni][2] * f0);
            c1[8] = f2tff(OcT[mi][ni][3] * f1);
        }
    }
}

// ---------------- launch ----------------
extern "C" void kernel_launch(void* const* d_in, const int* in_sizes, int n_in,
                              void* d_out, int out_size)
{
    const float* x      = (const float*)d_in[0];
    const int*   mask   = (const int*)  d_in[1];
    const float* ln1_g  = (const float*)d_in[2];
    const float* ln1_b  = (const float*)d_in[3];
    const float* qkv_w  = (const float*)d_in[4];
    const float* qkv_b  = (const float*)d_in[5];
    const float* proj_w = (const float*)d_in[6];
    const float* proj_b = (const float*)d_in[7];
    const float* rel    = (const float*)d_in[8];
    const float* ln2_g  = (const float*)d_in[9];
    const float* ln2_b  = (const float*)d_in[10];
    const float* w1     = (const float*)d_in[11];
    const float* b1     = (const float*)d_in[12];
    const float* w2     = (const float*)d_in[13];
    const float* b2     = (const float*)d_in[14];
    const float* gate1  = (const float*)d_in[15];
    const float* gate2  = (const float*)d_in[16];
    float* out = (float*)d_out;

    float *xn, *qkv, *ctx, *y, *mlp, *qkvw, *projw, *w1t, *w2t;
    cudaGetSymbolAddress((void**)&xn,    g_xn);
    cudaGetSymbolAddress((void**)&qkv,   g_qkv);
    cudaGetSymbolAddress((void**)&ctx,   g_ctx);
    cudaGetSymbolAddress((void**)&y,     g_y);
    cudaGetSymbolAddress((void**)&mlp,   g_mlp);
    cudaGetSymbolAddress((void**)&qkvw,  g_qkvw);
    cudaGetSymbolAddress((void**)&projw, g_projw);
    cudaGetSymbolAddress((void**)&w1t,   g_w1);
    cudaGetSymbolAddress((void**)&w2t,   g_w2);

    static bool attr_set = false;
    if (!attr_set) {
        cudaFuncSetAttribute(tf32gemm_kernel<EPI_BIAS>,
                             cudaFuncAttributeMaxDynamicSharedMemorySize, GEMM_SMEM);
        cudaFuncSetAttribute(tf32gemm_kernel<EPI_GELU>,
                             cudaFuncAttributeMaxDynamicSharedMemorySize, GEMM_SMEM);
        cudaFuncSetAttribute(tf32gemm_kernel<EPI_RESGATE>,
                             cudaFuncAttributeMaxDynamicSharedMemorySize, GEMM_SMEM);
        cudaFuncSetAttribute(flash_attn_kernel,
                             cudaFuncAttributeMaxDynamicSharedMemorySize, FL_SMEM);
        attr_set = true;
    }

    // 0) round all weights to tf32 (single launch)
    cvt_all_kernel<<<N4_TOT / 256, 256>>>(qkv_w, qkvw, proj_w, projw, w1, w1t, w2, w2t);

    // 1) LN1 (tf32-rounded output)
    ln_kernel<<<ROWS / 8, 256>>>(x, ln1_g, ln1_b, xn);
    // 2) qkv = xn @ qkvw + qkv_b (output tf32-rounded for flash)
    tf32gemm_kernel<EPI_BIAS><<<dim3(3 * BDIM / 128, ROWS / 128), 256, GEMM_SMEM>>>(
        xn, qkvw, qkv_b, nullptr, nullptr, qkv, ROWS, 3 * BDIM, BDIM);
    // 3) fused attention -> ctx (tf32-rounded)
    flash_attn_kernel<<<dim3(NSEQ / 128, NB * NHEADS), 256, FL_SMEM>>>(qkv, mask, rel, ctx);
    // 4) y = x + gate1 * (ctx @ projw + proj_b)
    tf32gemm_kernel<EPI_RESGATE><<<dim3(BDIM / 128, ROWS / 128), 256, GEMM_SMEM>>>(
        ctx, projw, proj_b, x, gate1, y, ROWS, BDIM, BDIM);
    // 5) LN2 (tf32-rounded output)
    ln_kernel<<<ROWS / 8, 256>>>(y, ln2_g, ln2_b, xn);
    // 6) mlp = gelu(xn @ w1t + b1) (tf32-rounded)
    tf32gemm_kernel<EPI_GELU><<<dim3(4 * BDIM / 128, ROWS / 128), 256, GEMM_SMEM>>>(
        xn, w1t, b1, nullptr, nullptr, mlp, ROWS, 4 * BDIM, BDIM);
    // 7) out = y + gate2 * (mlp @ w2t + b2)
    tf32gemm_kernel<EPI_RESGATE><<<dim3(BDIM / 128, ROWS / 128), 256, GEMM_SMEM>>>(
        mlp, w2t, b2, y, gate2, out, ROWS, BDIM, 4 * BDIM);
}

// round 10
// speedup vs baseline: 3.8235x; 1.0314x over previous
#include <cuda_runtime.h>
#include <math.h>
#include <stdint.h>

#define BDIM 1024
#define NB 4
#define NSEQ 1024
#define NHEADS 16
#define HDIM 64
#define ROWS (NB*NSEQ)   // 4096
#define MAXSEQ 1024

// ---------------- scratch (device globals; no allocation allowed) ----------------
__device__ float g_xn[(size_t)ROWS*BDIM];               // 16 MB
__device__ float g_qkv[(size_t)ROWS*3*BDIM];            // 48 MB
__device__ float g_ctx[(size_t)ROWS*BDIM];              // 16 MB
__device__ float g_y[(size_t)ROWS*BDIM];                // 16 MB
__device__ float g_mlp[(size_t)ROWS*4*BDIM];            // 64 MB
// tf32-rounded TRANSPOSED weights [N, K] K-major
__device__ float g_qkvw[(size_t)BDIM*3*BDIM];           // 12 MB
__device__ float g_projw[(size_t)BDIM*BDIM];            // 4 MB
__device__ float g_w1[(size_t)BDIM*4*BDIM];             // 16 MB
__device__ float g_w2[(size_t)4*BDIM*BDIM];             // 16 MB

// ---------------- helpers ----------------
__device__ __forceinline__ uint32_t f2tf(float x) {
    uint32_t r;
    asm("cvt.rna.tf32.f32 %0, %1;" : "=r"(r) : "f"(x));
    return r;
}
__device__ __forceinline__ float f2tff(float x) { return __uint_as_float(f2tf(x)); }

__device__ __forceinline__ void mma_tf32(float c[4], const uint32_t a[4], const uint32_t b[2]) {
    asm volatile(
        "mma.sync.aligned.m16n8k8.row.col.f32.tf32.tf32.f32 "
        "{%0,%1,%2,%3}, {%4,%5,%6,%7}, {%8,%9}, {%0,%1,%2,%3};"
        : "+f"(c[0]), "+f"(c[1]), "+f"(c[2]), "+f"(c[3])
        : "r"(a[0]), "r"(a[1]), "r"(a[2]), "r"(a[3]), "r"(b[0]), "r"(b[1]));
}

__device__ __forceinline__ void cp_async16(uint32_t smem_addr, const void* gptr) {
    asm volatile("cp.async.cg.shared.global [%0], [%1], 16;"
                 :: "r"(smem_addr), "l"(gptr));
}
__device__ __forceinline__ void cp_commit() { asm volatile("cp.async.commit_group;"); }
template<int N>
__device__ __forceinline__ void cp_wait() { asm volatile("cp.async.wait_group %0;" :: "n"(N)); }

// ---------------- weight transpose + tf32 round: out[n*K+k] = tf32(in[k*N+n]) ----------------
__global__ __launch_bounds__(256) void transpose_tf32_kernel(
    const float* __restrict__ in, float* __restrict__ out, int K, int N)
{
    __shared__ float t[32][33];
    const int n0 = blockIdx.x * 32, k0 = blockIdx.y * 32;
    const int tx = threadIdx.x & 31, ty = threadIdx.x >> 5;  // 32 x 8
    #pragma unroll
    for (int i = 0; i < 32; i += 8)
        t[ty + i][tx] = in[(size_t)(k0 + ty + i) * N + n0 + tx];
    __syncthreads();
    #pragma unroll
    for (int i = 0; i < 32; i += 8)
        out[(size_t)(n0 + ty + i) * K + k0 + tx] = f2tff(t[tx][ty + i]);
}

// ---------------- LayerNorm: warp per row (no smem, no barriers) ----------------
__global__ __launch_bounds__(256) void ln_kernel(const float* __restrict__ x,
    const float* __restrict__ g, const float* __restrict__ b, float* __restrict__ out)
{
    const int row  = blockIdx.x * 8 + (threadIdx.x >> 5);
    const int lane = threadIdx.x & 31;
    const float4* xr = reinterpret_cast<const float4*>(x + (size_t)row * BDIM);
    float4 v[8];
    float s = 0.0f;
    #pragma unroll
    for (int i = 0; i < 8; i++) {
        v[i] = xr[lane + 32 * i];
        s += v[i].x + v[i].y + v[i].z + v[i].w;
    }
    #pragma unroll
    for (int o = 16; o > 0; o >>= 1) s += __shfl_xor_sync(0xffffffffu, s, o);
    const float mu = s * (1.0f / BDIM);
    float q = 0.0f;
    #pragma unroll
    for (int i = 0; i < 8; i++) {
        v[i].x -= mu; v[i].y -= mu; v[i].z -= mu; v[i].w -= mu;
        q += v[i].x*v[i].x + v[i].y*v[i].y + v[i].z*v[i].z + v[i].w*v[i].w;
    }
    #pragma unroll
    for (int o = 16; o > 0; o >>= 1) q += __shfl_xor_sync(0xffffffffu, q, o);
    const float rinv = rsqrtf(q * (1.0f / BDIM) + 1e-5f);
    float4* orow = reinterpret_cast<float4*>(out + (size_t)row * BDIM);
    #pragma unroll
    for (int i = 0; i < 8; i++) {
        float4 gg = reinterpret_cast<const float4*>(g)[lane + 32 * i];
        float4 bb = reinterpret_cast<const float4*>(b)[lane + 32 * i];
        float4 o4;
        o4.x = f2tff(v[i].x * rinv * gg.x + bb.x);
        o4.y = f2tff(v[i].y * rinv * gg.y + bb.y);
        o4.z = f2tff(v[i].z * rinv * gg.z + bb.z);
        o4.w = f2tff(v[i].w * rinv * gg.w + bb.w);
        orow[lane + 32 * i] = o4;
    }
}

// ---------------- 2-stage cp.async TF32 GEMM v2: both operands [row][K] K-major ----------------
// CTA 128x128, 4 warps, warp tile 64x64. C[M,N] = epi(A[M,K] @ Wt[N,K]^T + bias).
// Per ks-slice: 32 HMMA vs 16 LDS.64 (A pairs + B pairs adjacent under k-slot bijection).
enum { EPI_BIAS = 0, EPI_GELU = 1, EPI_RESGATE = 2 };

#define G_ST 40                       // row stride words: dual-bank 4g+t4 -> conflict-free
#define G_OPW (128*G_ST)              // 5120 words per operand per stage
#define GEMM_SMEM (2*2*G_OPW*4)       // 81920 bytes (2 stages x (A+B))

template<int EPI>
__global__ __launch_bounds__(128, 2) void tf32gemm_kernel(
    const float* __restrict__ A, const float* __restrict__ Wt,
    const float* __restrict__ bias, const float* __restrict__ res,
    const float* __restrict__ gate, float* __restrict__ C,
    int M, int N, int K)
{
    constexpr int BK = 32;
    extern __shared__ uint32_t sm[];
    const uint32_t sm_u = (uint32_t)__cvta_generic_to_shared(sm);

    const int tid  = threadIdx.x;
    const int lane = tid & 31;
    const int wid  = tid >> 5;
    const int g    = lane >> 2;
    const int t4   = lane & 3;
    const int mWarp = (wid >> 1) * 64;
    const int nWarp = (wid & 1) * 64;

    // global->smem mapping: 16 rows x 8 chunks per pass, 8 passes per operand
    const int lr = tid >> 3;           // 0..15
    const int lc = (tid & 7) * 4;      // word col 0..28

    const float* Ap = A  + (size_t)(blockIdx.y * 128 + lr) * K + lc;
    const float* Bp = Wt + (size_t)(blockIdx.x * 128 + lr) * K + lc;
    const uint32_t aDst = sm_u + (uint32_t)(lr * G_ST + lc) * 4;
    const uint32_t bDst = aDst + G_OPW * 4;

    const int nT = K / BK;

    // prologue: tile 0 -> stage 0
    #pragma unroll
    for (int p = 0; p < 8; p++) {
        cp_async16(aDst + (uint32_t)(p * 16 * G_ST) * 4, Ap + (size_t)(p * 16) * K);
        cp_async16(bDst + (uint32_t)(p * 16 * G_ST) * 4, Bp + (size_t)(p * 16) * K);
    }
    cp_commit();

    float acc[4][8][4] = {};

    for (int t = 0; t < nT; t++) {
        cp_wait<0>();
        __syncthreads();

        if (t + 1 < nT) {
            const uint32_t so = (uint32_t)(((t + 1) & 1) * 2 * G_OPW) * 4;
            const float* ap = Ap + (size_t)(t + 1) * BK;
            const float* bp = Bp + (size_t)(t + 1) * BK;
            #pragma unroll
            for (int p = 0; p < 8; p++) {
                cp_async16(aDst + so + (uint32_t)(p * 16 * G_ST) * 4, ap + (size_t)(p * 16) * K);
                cp_async16(bDst + so + (uint32_t)(p * 16 * G_ST) * 4, bp + (size_t)(p * 16) * K);
            }
            cp_commit();
        }

        const uint32_t* As = sm + (t & 1) * 2 * G_OPW;
        const uint32_t* Bs = As + G_OPW;
        #pragma unroll
        for (int ks = 0; ks < 4; ks++) {
            const int kA = ks * 8 + 2 * t4;    // k-slot bijection: lane t4 -> k {kA, kA+1}
            uint32_t bf[8][2];
            #pragma unroll
            for (int ni = 0; ni < 8; ni++) {
                uint2 bb = *reinterpret_cast<const uint2*>(&Bs[(nWarp + ni * 8 + g) * G_ST + kA]);
                bf[ni][0] = bb.x; bf[ni][1] = bb.y;
            }
            #pragma unroll
            for (int mi = 0; mi < 4; mi++) {
                const int mb = mWarp + mi * 16;
                uint2 a0 = *reinterpret_cast<const uint2*>(&As[(mb + g) * G_ST + kA]);
                uint2 a1 = *reinterpret_cast<const uint2*>(&As[(mb + g + 8) * G_ST + kA]);
                uint32_t af[4] = { a0.x, a1.x, a0.y, a1.y };
                #pragma unroll
                for (int ni = 0; ni < 8; ni++)
                    mma_tf32(acc[mi][ni], af, bf[ni]);
            }
        }
        // slot reuse ordered by next iteration's top-of-loop barrier
    }

    // epilogue
    const float gt = (EPI == EPI_RESGATE) ? gate[0] : 0.0f;
    #pragma unroll
    for (int mi = 0; mi < 4; mi++) {
        const int row0 = blockIdx.y * 128 + mWarp + mi * 16 + g;
        #pragma unroll
        for (int ni = 0; ni < 8; ni++) {
            const int col = blockIdx.x * 128 + nWarp + ni * 8 + t4 * 2;
            const float b0 = bias[col], b1 = bias[col + 1];
            #pragma unroll
            for (int h = 0; h < 2; h++) {
                const int row = row0 + h * 8;
                float v0 = acc[mi][ni][2 * h + 0] + b0;
                float v1 = acc[mi][ni][2 * h + 1] + b1;
                if (EPI == EPI_BIAS) {
                    v0 = f2tff(v0);
                    v1 = f2tff(v1);
                }
                if (EPI == EPI_GELU) {
                    v0 = f2tff(0.5f * v0 * (1.0f + erff(v0 * 0.70710678118654752f)));
                    v1 = f2tff(0.5f * v1 * (1.0f + erff(v1 * 0.70710678118654752f)));
                }
                if (EPI == EPI_RESGATE) {
                    const size_t off = (size_t)row * N + col;
                    v0 = res[off] + gt * v0;
                    v1 = res[off + 1] + gt * v1;
                }
                *reinterpret_cast<float2*>(C + (size_t)row * N + col) = make_float2(v0, v1);
            }
        }
    }
}

// ---------------- Fused flash attention (TF32; O^T form; cp.async K/V pipeline) ----------------
#define KST 72
#define VST 76
#define FL_SLOTW (64*KST + 64*VST)               // 9472 words per KV slot
#define FL_MK    (2*FL_SLOTW)                    // mki[2][64]
#define FL_REL   (FL_MK + 128)                   // rel_s[2047]
#define FL_WORDS (FL_REL + 2048)
#define FL_SMEM  (FL_WORDS*4)                    // 84480 bytes

__global__ __launch_bounds__(256, 2) void flash_attn_kernel(
    const float* __restrict__ qkv, const int* __restrict__ mask,
    const float* __restrict__ rel, float* __restrict__ ctx)
{
    constexpr float SCALE = 0.125f;
    constexpr float L2E = 1.4426950408889634f;

    extern __shared__ __align__(16) uint32_t sm[];
    const uint32_t sm_u = (uint32_t)__cvta_generic_to_shared(sm);
    const int* mki  = reinterpret_cast<const int*>(sm + FL_MK);
    float* rel_s    = reinterpret_cast<float*>(sm + FL_REL);
    uint32_t* Qst   = sm + FL_SLOTW;   // overlays KV slot 1

    const int bh = blockIdx.y;
    const int b = bh >> 4, h = bh & 15;
    const int i0 = blockIdx.x * 128;
    const int tid = threadIdx.x, lane = tid & 31, w = tid >> 5;
    const int g = lane >> 2, t4 = lane & 3;

    const int ldr = tid >> 2;
    const int ldc = (tid & 3) * 16;
    const float* kvbase = qkv + (size_t)(b * NSEQ + ldr) * (3 * BDIM) + BDIM + h * HDIM + ldc;

    // prologue: prefetch tile 0 -> slot 0
    {
        const float* kp = kvbase;
        const uint32_t kdst = sm_u + (uint32_t)(ldr * KST + ldc) * 4;
        const uint32_t vdst = sm_u + (uint32_t)(64 * KST + ldr * VST + ldc) * 4;
        #pragma unroll
        for (int i = 0; i < 4; i++) {
            cp_async16(kdst + 16 * i, kp + 4 * i);
            cp_async16(vdst + 16 * i, kp + BDIM + 4 * i);
        }
        if (tid < 16)
            cp_async16(sm_u + (uint32_t)(FL_MK + tid * 4) * 4, mask + b * NSEQ + tid * 4);
        cp_commit();
    }

    for (int idx = tid; idx < 2 * MAXSEQ - 1; idx += 256)
        rel_s[idx] = rel[(size_t)idx * NHEADS + h];

    {
        const int r = tid >> 1;
        const int c0 = (tid & 1) * 32;
        const float* qp = qkv + ((size_t)(b * NSEQ + i0 + r)) * (3 * BDIM) + h * HDIM + c0;
        #pragma unroll
        for (int i = 0; i < 8; i++)
            *reinterpret_cast<uint4*>(&Qst[r * KST + c0 + 4 * i]) =
                *reinterpret_cast<const uint4*>(qp + 4 * i);
    }
    __syncthreads();

    uint32_t Qa[8][4];
    #pragma unroll
    for (int kt = 0; kt < 8; kt++) {
        uint2 q0 = *reinterpret_cast<const uint2*>(&Qst[(w * 16 + g) * KST + kt * 8 + 2 * t4]);
        uint2 q1 = *reinterpret_cast<const uint2*>(&Qst[(w * 16 + g + 8) * KST + kt * 8 + 2 * t4]);
        Qa[kt][0] = q0.x; Qa[kt][1] = q1.x; Qa[kt][2] = q0.y; Qa[kt][3] = q1.y;
    }

    const int irow0 = i0 + w * 16 + g;
    const int irow1 = irow0 + 8;
    const int mi0 = mask[b * NSEQ + irow0];
    const int mi1 = mask[b * NSEQ + irow1];

    float m0 = -INFINITY, m1 = -INFINITY, l0 = 0.0f, l1 = 0.0f;
    float OcT[4][2][4] = {};

    for (int jt = 0; jt < NSEQ / 64; jt++) {
        cp_wait<0>();
        __syncthreads();

        if (jt + 1 < NSEQ / 64) {
            const int ns = (jt + 1) & 1;
            const float* kp = kvbase + (size_t)(jt + 1) * 64 * (3 * BDIM);
            const uint32_t kdst = sm_u + (uint32_t)(ns * FL_SLOTW + ldr * KST + ldc) * 4;
            const uint32_t vdst = sm_u + (uint32_t)(ns * FL_SLOTW + 64 * KST + ldr * VST + ldc) * 4;
            #pragma unroll
            for (int i = 0; i < 4; i++) {
                cp_async16(kdst + 16 * i, kp + 4 * i);
                cp_async16(vdst + 16 * i, kp + BDIM + 4 * i);
            }
            if (tid < 16)
                cp_async16(sm_u + (uint32_t)(FL_MK + ns * 64 + tid * 4) * 4,
                           mask + b * NSEQ + (jt + 1) * 64 + tid * 4);
            cp_commit();
        }

        const int slot = jt & 1;
        const uint32_t* Ks = sm + slot * FL_SLOTW;
        const uint32_t* Vs = sm + slot * FL_SLOTW + 64 * KST;
        const int* mkp = mki + slot * 64;

        float S[8][4] = {};
        #pragma unroll
        for (int nt = 0; nt < 8; nt++) {
            #pragma unroll
            for (int kt = 0; kt < 8; kt++) {
                uint2 kk = *reinterpret_cast<const uint2*>(&Ks[(nt * 8 + g) * KST + kt * 8 + 2 * t4]);
                uint32_t bf[2] = { kk.x, kk.y };
                mma_tf32(S[nt], Qa[kt], bf);
            }
        }

        float tmax0 = -INFINITY, tmax1 = -INFINITY;
        #pragma unroll
        for (int nt = 0; nt < 8; nt++) {
            const int j0 = jt * 64 + nt * 8 + 2 * t4;
            const int mk0 = mkp[nt * 8 + 2 * t4];
            const int mk1 = mkp[nt * 8 + 2 * t4 + 1];
            float s0 = S[nt][0] * SCALE + rel_s[irow0 - j0 + (MAXSEQ - 1)];
            float s1 = S[nt][1] * SCALE + rel_s[irow0 - j0 - 1 + (MAXSEQ - 1)];
            float s2 = S[nt][2] * SCALE + rel_s[irow1 - j0 + (MAXSEQ - 1)];
            float s3 = S[nt][3] * SCALE + rel_s[irow1 - j0 - 1 + (MAXSEQ - 1)];
            if (mi0 == 0 || mk0 == 0) s0 = -1e9f;
            if (mi0 == 0 || mk1 == 0) s1 = -1e9f;
            if (mi1 == 0 || mk0 == 0) s2 = -1e9f;
            if (mi1 == 0 || mk1 == 0) s3 = -1e9f;
            S[nt][0] = s0; S[nt][1] = s1; S[nt][2] = s2; S[nt][3] = s3;
            tmax0 = fmaxf(tmax0, fmaxf(s0, s1));
            tmax1 = fmaxf(tmax1, fmaxf(s2, s3));
        }
        tmax0 = fmaxf(tmax0, __shfl_xor_sync(0xffffffffu, tmax0, 1));
        tmax0 = fmaxf(tmax0, __shfl_xor_sync(0xffffffffu, tmax0, 2));
        tmax1 = fmaxf(tmax1, __shfl_xor_sync(0xffffffffu, tmax1, 1));
        tmax1 = fmaxf(tmax1, __shfl_xor_sync(0xffffffffu, tmax1, 2));

        const float mn0 = fmaxf(m0, tmax0);
        const float mn1 = fmaxf(m1, tmax1);
        const float sc0 = exp2f((m0 - mn0) * L2E);
        const float sc1 = exp2f((m1 - mn1) * L2E);
        m0 = mn0; m1 = mn1;

        float ts0 = 0.0f, ts1 = 0.0f;
        #pragma unroll
        for (int nt = 0; nt < 8; nt++) {
            S[nt][0] = exp2f((S[nt][0] - mn0) * L2E);
            S[nt][1] = exp2f((S[nt][1] - mn0) * L2E);
            S[nt][2] = exp2f((S[nt][2] - mn1) * L2E);
            S[nt][3] = exp2f((S[nt][3] - mn1) * L2E);
            ts0 += S[nt][0] + S[nt][1];
            ts1 += S[nt][2] + S[nt][3];
        }
        ts0 += __shfl_xor_sync(0xffffffffu, ts0, 1);
        ts0 += __shfl_xor_sync(0xffffffffu, ts0, 2);
        ts1 += __shfl_xor_sync(0xffffffffu, ts1, 1);
        ts1 += __shfl_xor_sync(0xffffffffu, ts1, 2);
        l0 = l0 * sc0 + ts0;
        l1 = l1 * sc1 + ts1;

        const float scA = __shfl_sync(0xffffffffu, sc0, 8 * t4);
        const float scB = __shfl_sync(0xffffffffu, sc0, 8 * t4 + 4);
        const float scC = __shfl_sync(0xffffffffu, sc1, 8 * t4);
        const float scD = __shfl_sync(0xffffffffu, sc1, 8 * t4 + 4);
        #pragma unroll
        for (int mi = 0; mi < 4; mi++) {
            OcT[mi][0][0] *= scA; OcT[mi][0][1] *= scB;
            OcT[mi][0][2] *= scA; OcT[mi][0][3] *= scB;
            OcT[mi][1][0] *= scC; OcT[mi][1][1] *= scD;
            OcT[mi][1][2] *= scC; OcT[mi][1][3] *= scD;
        }

        #pragma unroll
        for (int kt = 0; kt < 8; kt++) {
            uint32_t b0t[2] = { f2tf(S[kt][0]), f2tf(S[kt][1]) };
            uint32_t b1t[2] = { f2tf(S[kt][2]), f2tf(S[kt][3]) };
            const uint32_t* vr0 = &Vs[(kt * 8 + 2 * t4) * VST];
            const uint32_t* vr1 = vr0 + VST;
            #pragma unroll
            for (int mi = 0; mi < 4; mi++) {
                const int d0 = mi * 16 + g;
                uint32_t a[4];
                a[0] = vr0[d0];
                a[1] = vr0[d0 + 8];
                a[2] = vr1[d0];
                a[3] = vr1[d0 + 8];
                mma_tf32(OcT[mi][0], a, b0t);
                mma_tf32(OcT[mi][1], a, b1t);
            }
        }
    }

    const float inv0 = 1.0f / l0;
    const float inv1 = 1.0f / l1;
    const float iA = __shfl_sync(0xffffffffu, inv0, 8 * t4);
    const float iB = __shfl_sync(0xffffffffu, inv0, 8 * t4 + 4);
    const float iC = __shfl_sync(0xffffffffu, inv1, 8 * t4);
    const float iD = __shfl_sync(0xffffffffu, inv1, 8 * t4 + 4);
    #pragma unroll
    for (int mi = 0; mi < 4; mi++) {
        const int col = h * HDIM + mi * 16 + g;
        #pragma unroll
        for (int ni = 0; ni < 2; ni++) {
            const int r0 = i0 + w * 16 + ni * 8 + 2 * t4;
            const float f0 = ni ? iC : iA;
            const float f1 = ni ? iD : iB;
            float* c0 = ctx + (size_t)(b * NSEQ + r0) * BDIM + col;
            float* c1 = ctx + (size_t)(b * NSEQ + r0 + 1) * BDIM + col;
            c0[0] = f2tff(OcT[mi][ni][0] * f0);
            c1[0] = f2tff(OcT[mi][ni][1] * f1);
            c0[8] = f2tff(OcT[mi][ni][2] * f0);
            c1[8] = f2tff(OcT[mi][ni][3] * f1);
        }
    }
}

// ---------------- launch ----------------
extern "C" void kernel_launch(void* const* d_in, const int* in_sizes, int n_in,
                              void* d_out, int out_size)
{
    const float* x      = (const float*)d_in[0];
    const int*   mask   = (const int*)  d_in[1];
    const float* ln1_g  = (const float*)d_in[2];
    const float* ln1_b  = (const float*)d_in[3];
    const float* qkv_w  = (const float*)d_in[4];
    const float* qkv_b  = (const float*)d_in[5];
    const float* proj_w = (const float*)d_in[6];
    const float* proj_b = (const float*)d_in[7];
    const float* rel    = (const float*)d_in[8];
    const float* ln2_g  = (const float*)d_in[9];
    const float* ln2_b  = (const float*)d_in[10];
    const float* w1     = (const float*)d_in[11];
    const float* b1     = (const float*)d_in[12];
    const float* w2     = (const float*)d_in[13];
    const float* b2     = (const float*)d_in[14];
    const float* gate1  = (const float*)d_in[15];
    const float* gate2  = (const float*)d_in[16];
    float* out = (float*)d_out;

    float *xn, *qkv, *ctx, *y, *mlp, *qkvw, *projw, *w1t, *w2t;
    cudaGetSymbolAddress((void**)&xn,    g_xn);
    cudaGetSymbolAddress((void**)&qkv,   g_qkv);
    cudaGetSymbolAddress((void**)&ctx,   g_ctx);
    cudaGetSymbolAddress((void**)&y,     g_y);
    cudaGetSymbolAddress((void**)&mlp,   g_mlp);
    cudaGetSymbolAddress((void**)&qkvw,  g_qkvw);
    cudaGetSymbolAddress((void**)&projw, g_projw);
    cudaGetSymbolAddress((void**)&w1t,   g_w1);
    cudaGetSymbolAddress((void**)&w2t,   g_w2);

    static bool attr_set = false;
    if (!attr_set) {
        cudaFuncSetAttribute(tf32gemm_kernel<EPI_BIAS>,
                             cudaFuncAttributeMaxDynamicSharedMemorySize, GEMM_SMEM);
        cudaFuncSetAttribute(tf32gemm_kernel<EPI_GELU>,
                             cudaFuncAttributeMaxDynamicSharedMemorySize, GEMM_SMEM);
        cudaFuncSetAttribute(tf32gemm_kernel<EPI_RESGATE>,
                             cudaFuncAttributeMaxDynamicSharedMemorySize, GEMM_SMEM);
        cudaFuncSetAttribute(flash_attn_kernel,
                             cudaFuncAttributeMaxDynamicSharedMemorySize, FL_SMEM);
        attr_set = true;
    }

    // 0) transpose + tf32-round weights -> [N, K] K-major
    transpose_tf32_kernel<<<dim3(3*BDIM/32, BDIM/32), 256>>>(qkv_w, qkvw, BDIM, 3*BDIM);
    transpose_tf32_kernel<<<dim3(BDIM/32,   BDIM/32), 256>>>(proj_w, projw, BDIM, BDIM);
    transpose_tf32_kernel<<<dim3(4*BDIM/32, BDIM/32), 256>>>(w1, w1t, BDIM, 4*BDIM);
    transpose_tf32_kernel<<<dim3(BDIM/32, 4*BDIM/32), 256>>>(w2, w2t, 4*BDIM, BDIM);

    // 1) LN1 (tf32-rounded output)
    ln_kernel<<<ROWS / 8, 256>>>(x, ln1_g, ln1_b, xn);
    // 2) qkv = xn @ qkv_w + qkv_b (output tf32-rounded for flash)
    tf32gemm_kernel<EPI_BIAS><<<dim3(3 * BDIM / 128, ROWS / 128), 128, GEMM_SMEM>>>(
        xn, qkvw, qkv_b, nullptr, nullptr, qkv, ROWS, 3 * BDIM, BDIM);
    // 3) fused attention -> ctx (tf32-rounded)
    flash_attn_kernel<<<dim3(NSEQ / 128, NB * NHEADS), 256, FL_SMEM>>>(qkv, mask, rel, ctx);
    // 4) y = x + gate1 * (ctx @ proj_w + proj_b)
    tf32gemm_kernel<EPI_RESGATE><<<dim3(BDIM / 128, ROWS / 128), 128, GEMM_SMEM>>>(
        ctx, projw, proj_b, x, gate1, y, ROWS, BDIM, BDIM);
    // 5) LN2 (tf32-rounded output)
    ln_kernel<<<ROWS / 8, 256>>>(y, ln2_g, ln2_b, xn);
    // 6) mlp = gelu(xn @ w1 + b1) (tf32-rounded)
    tf32gemm_kernel<EPI_GELU><<<dim3(4 * BDIM / 128, ROWS / 128), 128, GEMM_SMEM>>>(
        xn, w1t, b1, nullptr, nullptr, mlp, ROWS, 4 * BDIM, BDIM);
    // 7) out = y + gate2 * (mlp @ w2 + b2)
    tf32gemm_kernel<EPI_RESGATE><<<dim3(BDIM / 128, ROWS / 128), 128, GEMM_SMEM>>>(
        mlp, w2t, b2, y, gate2, out, ROWS, BDIM, 4 * BDIM);
}